// round 10
// baseline (speedup 1.0000x reference)
#include <cuda_runtime.h>
#include <cuda_bf16.h>
#include <math.h>
#include <stdint.h>

#define D_MODEL 2048
#define NHEAD   16
#define HDIM    128
#define BATCH   2
#define SEQ     2048
#define MROWS   (BATCH*SEQ)   // 4096

// ---------------- device scratch (no runtime allocation) ----------------
__device__ __nv_bfloat16 g_qbh[(size_t)BATCH*NHEAD*SEQ*HDIM];  // roped+scaled Q hi/lo
__device__ __nv_bfloat16 g_qbl[(size_t)BATCH*NHEAD*SEQ*HDIM];
__device__ __nv_bfloat16 g_kbh[(size_t)BATCH*NHEAD*SEQ*HDIM];  // roped K hi/lo
__device__ __nv_bfloat16 g_kbl[(size_t)BATCH*NHEAD*SEQ*HDIM];
__device__ __nv_bfloat16 g_vbh[(size_t)BATCH*NHEAD*SEQ*HDIM];  // V hi/lo
__device__ __nv_bfloat16 g_vbl[(size_t)BATCH*NHEAD*SEQ*HDIM];

__device__ __nv_bfloat16 g_qh[(size_t)MROWS*D_MODEL];       // query hi/lo (GEMM A)
__device__ __nv_bfloat16 g_ql[(size_t)MROWS*D_MODEL];
__device__ __nv_bfloat16 g_wh[(size_t)3*D_MODEL*D_MODEL];   // W_qkv hi/lo
__device__ __nv_bfloat16 g_wl[(size_t)3*D_MODEL*D_MODEL];
__device__ __nv_bfloat16 g_oh[(size_t)D_MODEL*D_MODEL];     // W_out hi/lo
__device__ __nv_bfloat16 g_ol[(size_t)D_MODEL*D_MODEL];
__device__ __nv_bfloat16 g_ah[(size_t)MROWS*D_MODEL];       // attn-out hi/lo
__device__ __nv_bfloat16 g_al[(size_t)MROWS*D_MODEL];

__device__ float g_cos[(size_t)SEQ*64];                     // rope tables
__device__ float g_sin[(size_t)SEQ*64];

// ---------------- helpers ----------------
__device__ __forceinline__ uint32_t smem_u32(const void* p) {
    uint32_t a;
    asm("{ .reg .u64 t; cvta.to.shared.u64 t, %1; cvt.u32.u64 %0, t; }" : "=r"(a) : "l"(p));
    return a;
}
#define SWZ(o) ((o) ^ (((o) >> 3) & 0x70))

__device__ __forceinline__ void ldsm4(uint32_t addr, uint32_t* r) {
    asm volatile("ldmatrix.sync.aligned.m8n8.x4.shared.b16 {%0,%1,%2,%3}, [%4];"
                 : "=r"(r[0]), "=r"(r[1]), "=r"(r[2]), "=r"(r[3]) : "r"(addr));
}
__device__ __forceinline__ void ldsm4t(uint32_t addr, uint32_t* r) {
    asm volatile("ldmatrix.sync.aligned.m8n8.x4.trans.shared.b16 {%0,%1,%2,%3}, [%4];"
                 : "=r"(r[0]), "=r"(r[1]), "=r"(r[2]), "=r"(r[3]) : "r"(addr));
}
__device__ __forceinline__ void mma16816(float* c, const uint32_t* a, const uint32_t* b) {
    asm volatile(
        "mma.sync.aligned.m16n8k16.row.col.f32.bf16.bf16.f32 "
        "{%0,%1,%2,%3}, {%4,%5,%6,%7}, {%8,%9}, {%0,%1,%2,%3};"
        : "+f"(c[0]), "+f"(c[1]), "+f"(c[2]), "+f"(c[3])
        : "r"(a[0]), "r"(a[1]), "r"(a[2]), "r"(a[3]), "r"(b[0]), "r"(b[1]));
}
#define CP16(dst, src) \
    asm volatile("cp.async.cg.shared.global [%0], [%1], 16;" :: "r"(dst), "l"(src))
#define CP_COMMIT() asm volatile("cp.async.commit_group;" ::: "memory")
#define CP_WAIT0()  asm volatile("cp.async.wait_group 0;" ::: "memory")
#define CP_WAIT1()  asm volatile("cp.async.wait_group 1;" ::: "memory")

// split pair of fp32 into packed bf16x2 hi and lo (residual)
__device__ __forceinline__ void split2(float x, float y, uint32_t& hi, uint32_t& lo) {
    __nv_bfloat16 hx = __float2bfloat16(x), hy = __float2bfloat16(y);
    float rx = x - __bfloat162float(hx), ry = y - __bfloat162float(hy);
    __nv_bfloat16 lx = __float2bfloat16(rx), ly = __float2bfloat16(ry);
    hi = ((uint32_t)__bfloat16_as_ushort(hy) << 16) | __bfloat16_as_ushort(hx);
    lo = ((uint32_t)__bfloat16_as_ushort(ly) << 16) | __bfloat16_as_ushort(lx);
}

// ---------------------------------------------------------------------------
// fp32 -> bf16 hi/lo split
// ---------------------------------------------------------------------------
__global__ void split_kernel(const float* __restrict__ x,
                             __nv_bfloat16* __restrict__ hi,
                             __nv_bfloat16* __restrict__ lo, int n)
{
    int i = (blockIdx.x * 256 + threadIdx.x) * 4;
    if (i >= n) return;
    float4 v = *(const float4*)(x + i);
    uint32_t h0, l0, h1, l1;
    split2(v.x, v.y, h0, l0);
    split2(v.z, v.w, h1, l1);
    *(uint2*)(hi + i) = make_uint2(h0, h1);
    *(uint2*)(lo + i) = make_uint2(l0, l1);
}

// ---------------------------------------------------------------------------
// RoPE cos/sin table (double-precision range reduction, robust to fast-math)
// ---------------------------------------------------------------------------
__global__ void rope_table_kernel()
{
    int idx = blockIdx.x * 256 + threadIdx.x;       // SEQ*64 threads
    int l = idx >> 6, d = idx & 63;
    double invf = exp2(-(double)d * (13.287712379549449 / 64.0)); // 10000^(-d/64)
    double t    = fmod((double)l * invf, 6.283185307179586476925286766559);
    g_cos[idx] = cosf((float)t);
    g_sin[idx] = sinf((float)t);
}

// ---------------------------------------------------------------------------
// HMMA GEMM, 3-stage cp.async pipeline, K-chunks of 32 (packed hi|lo rows).
// Unchanged from round 9 (passing).
// ---------------------------------------------------------------------------
__device__ __forceinline__ void load_chunk_async(
    const __nv_bfloat16* __restrict__ a0, const __nv_bfloat16* __restrict__ a1,
    const __nv_bfloat16* __restrict__ b0, const __nv_bfloat16* __restrict__ b1,
    int K, int k0, uint32_t dst)
{
    const __nv_bfloat16* s[4] = {a0, a1, b0, b1};
    #pragma unroll
    for (int t = 0; t < 4; t++) {
        const __nv_bfloat16* p = s[t] + k0;
        const uint32_t d = dst + (t >> 1) * 16384;
        #pragma unroll
        for (int it = 0; it < 2; it++) {
            int i = threadIdx.x + it * 256;     // 0..511 (16B units per array)
            int r = i >> 2, c = i & 3;
            CP16(d + SWZ(r * 128 + (t & 1) * 64 + c * 16),
                 p + (size_t)r * K + c * 8);
        }
    }
}

template<int MODE>
__global__ __launch_bounds__(256, 2)
void tc_gemm(const __nv_bfloat16* __restrict__ Ah, const __nv_bfloat16* __restrict__ Al,
             const __nv_bfloat16* __restrict__ Bh, const __nv_bfloat16* __restrict__ Bl,
             const float* __restrict__ bias, float* __restrict__ C, int N, int K)
{
    extern __shared__ char smem[];
    char* smp = (char*)(((uintptr_t)smem + 1023) & ~(uintptr_t)1023);
    const uint32_t bufs = smem_u32(smp);

    const int tid  = threadIdx.x;
    const int lane = tid & 31;
    const int wid  = tid >> 5;
    const int wr   = wid >> 2;
    const int wc   = wid & 3;
    const int m0   = blockIdx.y << 7;
    const int n0   = blockIdx.x << 7;
    const int KCHUNKS = K >> 5;

    const __nv_bfloat16* Ahp = Ah + (size_t)m0 * K;
    const __nv_bfloat16* Alp = Al + (size_t)m0 * K;
    const __nv_bfloat16* Bhp = Bh + (size_t)n0 * K;
    const __nv_bfloat16* Blp = Bl + (size_t)n0 * K;

    float acc[4][4][4];
    #pragma unroll
    for (int i = 0; i < 4; i++)
        #pragma unroll
        for (int j = 0; j < 4; j++)
            #pragma unroll
            for (int r = 0; r < 4; r++) acc[i][j][r] = 0.f;

    const int      arow = lane & 15;
    const uint32_t adk  = (lane >> 4) << 4;
    const int      brow = (lane & 7) + ((lane >> 4) << 3);
    const uint32_t bdk  = ((lane >> 3) & 1) << 4;

    load_chunk_async(Ahp, Alp, Bhp, Blp, K, 0,  bufs);
    CP_COMMIT();
    load_chunk_async(Ahp, Alp, Bhp, Blp, K, 32, bufs + 32768);
    CP_COMMIT();
    CP_WAIT1();
    __syncthreads();

    for (int c = 0; c < KCHUNKS; c++) {
        if (c + 2 < KCHUNKS) {
            load_chunk_async(Ahp, Alp, Bhp, Blp, K, (c + 2) << 5,
                             bufs + ((c + 2) % 3) * 32768);
            CP_COMMIT();
        }

        const uint32_t bA = bufs + (c % 3) * 32768;
        const uint32_t bB = bA + 16384;

        #pragma unroll
        for (int ks = 0; ks < 2; ks++) {
            const uint32_t kbA = (uint32_t)ks * 32 + adk;
            const uint32_t kbB = (uint32_t)ks * 32 + bdk;

            uint32_t ah[4][4], bh[2][4], bl[2][4];
            #pragma unroll
            for (int mt = 0; mt < 4; mt++)
                ldsm4(bA + SWZ((uint32_t)(wr*64 + mt*16 + arow) * 128 + kbA), ah[mt]);
            #pragma unroll
            for (int np = 0; np < 2; np++) {
                const uint32_t rw = (uint32_t)(wc*32 + np*16 + brow) * 128;
                ldsm4(bB + SWZ(rw + kbB), bh[np]);
                ldsm4(bB + SWZ(rw + 64 + kbB), bl[np]);
            }
            #pragma unroll
            for (int mt = 0; mt < 4; mt++)
                #pragma unroll
                for (int nt = 0; nt < 4; nt++) {
                    mma16816(acc[mt][nt], ah[mt], &bh[nt >> 1][(nt & 1) * 2]);
                    mma16816(acc[mt][nt], ah[mt], &bl[nt >> 1][(nt & 1) * 2]);
                }
            uint32_t al[4][4];
            #pragma unroll
            for (int mt = 0; mt < 4; mt++)
                ldsm4(bA + SWZ((uint32_t)(wr*64 + mt*16 + arow) * 128 + 64 + kbA), al[mt]);
            #pragma unroll
            for (int mt = 0; mt < 4; mt++)
                #pragma unroll
                for (int nt = 0; nt < 4; nt++)
                    mma16816(acc[mt][nt], al[mt], &bh[nt >> 1][(nt & 1) * 2]);
        }

        if (c + 1 < KCHUNKS) {
            if (c + 2 < KCHUNKS) CP_WAIT1(); else CP_WAIT0();
            __syncthreads();
        }
    }

    if (MODE == 0) {
        #pragma unroll
        for (int mt = 0; mt < 4; mt++) {
            const int mrow = m0 + wr*64 + mt*16 + (lane >> 2);
            #pragma unroll
            for (int nt = 0; nt < 4; nt++) {
                const int cg = n0 + wc*32 + nt*8 + (lane & 3)*2;
                const float bx = bias[cg], by = bias[cg + 1];
                *(float2*)&C[(size_t)mrow * N + cg] =
                    make_float2(acc[mt][nt][0] + bx, acc[mt][nt][1] + by);
                *(float2*)&C[(size_t)(mrow + 8) * N + cg] =
                    make_float2(acc[mt][nt][2] + bx, acc[mt][nt][3] + by);
            }
        }
        return;
    }

    // ---------------- MODE 1 epilogue: stage -> rope/split -> scatter -------
    float* st = (float*)smp;                 // 128 x 132 fp32
    const int PITCH = 132;
    __syncthreads();
    #pragma unroll
    for (int mt = 0; mt < 4; mt++) {
        const int r0 = wr*64 + mt*16 + (lane >> 2);
        #pragma unroll
        for (int nt = 0; nt < 4; nt++) {
            const int cl = wc*32 + nt*8 + (lane & 3)*2;
            const float bx = bias[n0 + cl], by = bias[n0 + cl + 1];
            *(float2*)&st[r0*PITCH + cl] =
                make_float2(acc[mt][nt][0] + bx, acc[mt][nt][1] + by);
            *(float2*)&st[(r0 + 8)*PITCH + cl] =
                make_float2(acc[mt][nt][2] + bx, acc[mt][nt][3] + by);
        }
    }
    __syncthreads();

    const int which = n0 >> 11;              // 0=q 1=k 2=v
    const int h     = (n0 >> 7) & 15;
    const int row   = tid >> 1;
    const int half  = tid & 1;
    const int m     = m0 + row;
    const int bb    = m >> 11;
    const int l     = m & (SEQ - 1);
    const size_t obase = (((size_t)(bb*NHEAD + h))*SEQ + l)*HDIM;
    const float* srow = st + row * PITCH;

    if (which == 2) {
        const int d0 = half * 32;
        uint32_t h1[16], l1[16], h2[16], l2[16];
        #pragma unroll
        for (int j = 0; j < 16; j++) {
            split2(srow[d0 + 2*j],      srow[d0 + 2*j + 1],      h1[j], l1[j]);
            split2(srow[d0 + 64 + 2*j], srow[d0 + 64 + 2*j + 1], h2[j], l2[j]);
        }
        #pragma unroll
        for (int j = 0; j < 4; j++) {
            *(uint4*)&g_vbh[obase + d0 + j*8]      = ((uint4*)h1)[j];
            *(uint4*)&g_vbl[obase + d0 + j*8]      = ((uint4*)l1)[j];
            *(uint4*)&g_vbh[obase + d0 + 64 + j*8] = ((uint4*)h2)[j];
            *(uint4*)&g_vbl[obase + d0 + 64 + j*8] = ((uint4*)l2)[j];
        }
    } else {
        const float qs = (which == 0) ? 0.08838834764831845f : 1.0f;
        const int d0 = half * 32;
        const float* ct = g_cos + (size_t)l * 64;
        const float* stb = g_sin + (size_t)l * 64;
        uint32_t h1[16], l1[16], h2[16], l2[16];
        #pragma unroll
        for (int j = 0; j < 16; j++) {
            const int d = d0 + 2*j;
            float2 cc = *(const float2*)&ct[d];
            float2 ss = *(const float2*)&stb[d];
            float x1a = srow[d],      x1b = srow[d + 1];
            float x2a = srow[d + 64], x2b = srow[d + 65];
            float o1a = (x1a*cc.x - x2a*ss.x) * qs;
            float o1b = (x1b*cc.y - x2b*ss.y) * qs;
            float o2a = (x2a*cc.x + x1a*ss.x) * qs;
            float o2b = (x2b*cc.y + x1b*ss.y) * qs;
            split2(o1a, o1b, h1[j], l1[j]);
            split2(o2a, o2b, h2[j], l2[j]);
        }
        __nv_bfloat16* oh = (which == 0) ? g_qbh : g_kbh;
        __nv_bfloat16* ol = (which == 0) ? g_qbl : g_kbl;
        #pragma unroll
        for (int j = 0; j < 4; j++) {
            *(uint4*)&oh[obase + d0 + j*8]      = ((uint4*)h1)[j];
            *(uint4*)&ol[obase + d0 + j*8]      = ((uint4*)l1)[j];
            *(uint4*)&oh[obase + d0 + 64 + j*8] = ((uint4*)h2)[j];
            *(uint4*)&ol[obase + d0 + 64 + j*8] = ((uint4*)l2)[j];
        }
    }
}

// ---------------------------------------------------------------------------
// Attention helpers (BK = 32)
// ---------------------------------------------------------------------------
__device__ __forceinline__ void load_kv32(
    const __nv_bfloat16* __restrict__ kbh, const __nv_bfloat16* __restrict__ kbl,
    const __nv_bfloat16* __restrict__ vbh, const __nv_bfloat16* __restrict__ vbl,
    size_t row0, uint32_t dst, int tid)
{
    const __nv_bfloat16* arr[4] = {kbh, kbl, vbh, vbl};
    #pragma unroll
    for (int t = 0; t < 4; t++)
        #pragma unroll
        for (int it = 0; it < 2; it++) {
            int i = tid + it * 256;               // 0..511
            int row = i >> 4, u = i & 15;
            uint32_t d = dst + t*8192 + (u>>3)*4096 + SWZ(row*128 + (u&7)*16);
            CP16(d, arr[t] + (row0 + row) * HDIM + u * 8);
        }
}

// S (16x32 per warp) = Qh Kh + Qh Kl + Ql Kh, accumulated into s[16] (zeroed).
__device__ __forceinline__ void compute_S32(
    uint32_t QH, uint32_t QL, uint32_t KB, int wid, int lane, float* s)
{
    #pragma unroll
    for (int i = 0; i < 16; i++) s[i] = 0.f;
    const int      arow = wid*16 + (lane & 15);
    const uint32_t alo  = (uint32_t)((lane >> 4) << 4);
    const int      krow0 = (lane & 7) + ((lane >> 4) << 3);
    const uint32_t klo  = (uint32_t)(((lane >> 3) & 1) << 4);

    #pragma unroll
    for (int ks = 0; ks < 8; ks++) {
        const uint32_t aoff = (ks>>2)*16384 + SWZ(arow*128 + (ks&3)*32 + alo);
        uint32_t qa[4], qla[4];
        ldsm4(QH + aoff, qa);
        ldsm4(QL + aoff, qla);
        const uint32_t kcol = (uint32_t)((ks&3)*32) + klo;
        #pragma unroll
        for (int ntp = 0; ntp < 2; ntp++) {
            const uint32_t koff = (ks>>2)*4096 + SWZ((ntp*16 + krow0)*128 + kcol);
            uint32_t kb4[4], klb4[4];
            ldsm4(KB + koff, kb4);
            ldsm4(KB + 8192 + koff, klb4);
            mma16816(s + (2*ntp)*4,   qa,  &kb4[0]);
            mma16816(s + (2*ntp)*4,   qa,  &klb4[0]);
            mma16816(s + (2*ntp)*4,   qla, &kb4[0]);
            mma16816(s + (2*ntp+1)*4, qa,  &kb4[2]);
            mma16816(s + (2*ntp+1)*4, qa,  &klb4[2]);
            mma16816(s + (2*ntp+1)*4, qla, &kb4[2]);
        }
    }
}

// ---------------------------------------------------------------------------
// HMMA causal flash attention, BQ=128, BK=32, triple-buffered KV,
// S(kt+1) issued BEFORE softmax(kt) -> tensor pipe stays busy through softmax.
// ---------------------------------------------------------------------------
__global__ __launch_bounds__(256, 1)
void attn_kernel()
{
    extern __shared__ char sm[];
    const uint32_t base = (smem_u32(sm) + 1023) & ~1023u;
    const uint32_t QH = base;                 // 2 panels x 16KB
    const uint32_t QL = base + 32768;
    const uint32_t KV = base + 65536;         // 3 bufs x 32KB: Kh,+8K Kl,+16K Vh,+24K Vl

    const int tid  = threadIdx.x;
    const int lane = tid & 31;
    const int wid  = tid >> 5;
    const int qt   = (int)gridDim.x - 1 - (int)blockIdx.x;  // heavy tiles first
    const int h    = blockIdx.y;
    const int b    = blockIdx.z;
    const int bh   = b*NHEAD + h;
    const int q0   = qt << 7;
    const int nkv  = 4*(qt + 1);              // 32-wide KV blocks

    const size_t hoff = (size_t)bh * SEQ * HDIM;
    const __nv_bfloat16* qbh = g_qbh + hoff + (size_t)q0 * HDIM;
    const __nv_bfloat16* qbl = g_qbl + hoff + (size_t)q0 * HDIM;
    const __nv_bfloat16* kbh = g_kbh + hoff;
    const __nv_bfloat16* kbl = g_kbl + hoff;
    const __nv_bfloat16* vbh = g_vbh + hoff;
    const __nv_bfloat16* vbl = g_vbl + hoff;

    // ---- Q load ----
    #pragma unroll
    for (int it = 0; it < 8; it++) {
        int i = tid + it * 256;
        int row = i >> 4, u = i & 15;
        uint32_t off = (u >> 3) * 16384 + SWZ(row * 128 + (u & 7) * 16);
        CP16(QH + off, qbh + (size_t)row * HDIM + u * 8);
        CP16(QL + off, qbl + (size_t)row * HDIM + u * 8);
    }
    // ---- KV blocks 0,1 (nkv >= 4 always) ----
    load_kv32(kbh, kbl, vbh, vbl, 0, KV, tid);
    CP_COMMIT();
    load_kv32(kbh, kbl, vbh, vbl, 32, KV + 32768, tid);
    CP_COMMIT();
    CP_WAIT1();                 // Q + KV0 resident; KV1 in flight
    __syncthreads();

    float mr0 = -1e30f, mr1 = -1e30f, lr0 = 0.f, lr1 = 0.f;
    float o[16][4];
    #pragma unroll
    for (int t = 0; t < 16; t++)
        #pragma unroll
        for (int j = 0; j < 4; j++) o[t][j] = 0.f;

    const int rloc0 = wid*16 + (lane >> 2);
    const int rg0   = q0 + rloc0;
    const int vrow0 = (lane & 15);
    const uint32_t vcadd = (uint32_t)((lane >> 4) << 4);

    float scur[16], snext[16];
    compute_S32(QH, QL, KV, wid, lane, scur);        // S(0)

    for (int kt = 0; kt < nkv; kt++) {
        // ---- stage next: wait KV(kt+1), issue load KV(kt+2), issue S(kt+1)
        if (kt + 1 < nkv) {
            CP_WAIT0();
            __syncthreads();    // KV(kt+1) visible to all; all readers of buf
                                // (kt+2)%3 (PV kt-1 / S kt-1) are done
            if (kt + 2 < nkv) {
                load_kv32(kbh, kbl, vbh, vbl, (size_t)(kt + 2) * 32,
                          KV + ((kt + 2) % 3) * 32768, tid);
                CP_COMMIT();
            }
            compute_S32(QH, QL, KV + ((kt + 1) % 3) * 32768, wid, lane, snext);
        }

        // ---- softmax on scur (block kt) — overlaps tensor executing S(kt+1)
        if (kt >= 4*qt) {
            #pragma unroll
            for (int t = 0; t < 4; t++) {
                #pragma unroll
                for (int j = 0; j < 2; j++) {
                    const int n = kt*32 + t*8 + 2*(lane & 3) + j;
                    if (n > rg0)     scur[t*4 + j]     = -1e30f;
                    if (n > rg0 + 8) scur[t*4 + 2 + j] = -1e30f;
                }
            }
        }

        float rm0 = -1e30f, rm1 = -1e30f;
        #pragma unroll
        for (int t = 0; t < 4; t++) {
            rm0 = fmaxf(rm0, fmaxf(scur[t*4+0], scur[t*4+1]));
            rm1 = fmaxf(rm1, fmaxf(scur[t*4+2], scur[t*4+3]));
        }
        rm0 = fmaxf(rm0, __shfl_xor_sync(0xffffffffu, rm0, 1));
        rm0 = fmaxf(rm0, __shfl_xor_sync(0xffffffffu, rm0, 2));
        rm1 = fmaxf(rm1, __shfl_xor_sync(0xffffffffu, rm1, 1));
        rm1 = fmaxf(rm1, __shfl_xor_sync(0xffffffffu, rm1, 2));

        const float mn0 = fmaxf(mr0, rm0), mn1 = fmaxf(mr1, rm1);
        const float sf0 = __expf(mr0 - mn0), sf1 = __expf(mr1 - mn1);
        mr0 = mn0; mr1 = mn1;

        float rs0 = 0.f, rs1 = 0.f;
        #pragma unroll
        for (int t = 0; t < 4; t++) {
            scur[t*4+0] = __expf(scur[t*4+0] - mn0);
            scur[t*4+1] = __expf(scur[t*4+1] - mn0);
            scur[t*4+2] = __expf(scur[t*4+2] - mn1);
            scur[t*4+3] = __expf(scur[t*4+3] - mn1);
            rs0 += scur[t*4+0] + scur[t*4+1];
            rs1 += scur[t*4+2] + scur[t*4+3];
        }
        rs0 += __shfl_xor_sync(0xffffffffu, rs0, 1);
        rs0 += __shfl_xor_sync(0xffffffffu, rs0, 2);
        rs1 += __shfl_xor_sync(0xffffffffu, rs1, 1);
        rs1 += __shfl_xor_sync(0xffffffffu, rs1, 2);
        lr0 = lr0 * sf0 + rs0;
        lr1 = lr1 * sf1 + rs1;

        #pragma unroll
        for (int t = 0; t < 16; t++) {
            o[t][0] *= sf0; o[t][1] *= sf0;
            o[t][2] *= sf1; o[t][3] *= sf1;
        }

        // ---- P split into hi/lo A-fragments (2 k16 groups) ----
        uint32_t aph[2][4], apl[2][4];
        #pragma unroll
        for (int g = 0; g < 2; g++) {
            split2(scur[(2*g)*4+0],   scur[(2*g)*4+1],   aph[g][0], apl[g][0]);
            split2(scur[(2*g)*4+2],   scur[(2*g)*4+3],   aph[g][1], apl[g][1]);
            split2(scur[(2*g+1)*4+0], scur[(2*g+1)*4+1], aph[g][2], apl[g][2]);
            split2(scur[(2*g+1)*4+2], scur[(2*g+1)*4+3], aph[g][3], apl[g][3]);
        }

        // ---- O += P V  (V from buf kt%3) ----
        const uint32_t VB = KV + (kt % 3) * 32768 + 16384;
        #pragma unroll
        for (int dtp = 0; dtp < 8; dtp++) {
            const uint32_t vcol = (uint32_t)((dtp&3)*32) + vcadd;
            #pragma unroll
            for (int g = 0; g < 2; g++) {
                const uint32_t voff = (dtp>>2)*4096 + SWZ((g*16 + vrow0)*128 + vcol);
                uint32_t vb4[4], vlb4[4];
                ldsm4t(VB + voff, vb4);
                ldsm4t(VB + 8192 + voff, vlb4);
                mma16816(o[2*dtp],   aph[g], &vb4[0]);
                mma16816(o[2*dtp],   aph[g], &vlb4[0]);
                mma16816(o[2*dtp],   apl[g], &vb4[0]);
                mma16816(o[2*dtp+1], aph[g], &vb4[2]);
                mma16816(o[2*dtp+1], aph[g], &vlb4[2]);
                mma16816(o[2*dtp+1], apl[g], &vb4[2]);
            }
        }

        #pragma unroll
        for (int i = 0; i < 16; i++) scur[i] = snext[i];
    }

    // ---- epilogue ----
    const float inv0 = 1.f / lr0, inv1 = 1.f / lr1;
    const size_t row0 = ((size_t)(b*SEQ + rg0)) * D_MODEL + h*HDIM;
    const size_t row1 = row0 + 8 * D_MODEL;
    #pragma unroll
    for (int t = 0; t < 16; t++) {
        const int d = t*8 + 2*(lane & 3);
        uint32_t hi, lo;
        split2(o[t][0]*inv0, o[t][1]*inv0, hi, lo);
        *(uint32_t*)&g_ah[row0 + d] = hi;
        *(uint32_t*)&g_al[row0 + d] = lo;
        split2(o[t][2]*inv1, o[t][3]*inv1, hi, lo);
        *(uint32_t*)&g_ah[row1 + d] = hi;
        *(uint32_t*)&g_al[row1 + d] = lo;
    }
}

// ---------------------------------------------------------------------------
extern "C" void kernel_launch(void* const* d_in, const int* in_sizes, int n_in,
                              void* d_out, int out_size)
{
    const float* query = (const float*)d_in[0];
    const float* W_qkv = (const float*)d_in[1];
    const float* b_qkv = (const float*)d_in[2];
    const float* W_out = (const float*)d_in[3];
    const float* b_out = (const float*)d_in[4];
    float* out = (float*)d_out;

    void *p_qh, *p_ql, *p_wh, *p_wl, *p_oh, *p_ol, *p_ah, *p_al;
    cudaGetSymbolAddress(&p_qh, g_qh);  cudaGetSymbolAddress(&p_ql, g_ql);
    cudaGetSymbolAddress(&p_wh, g_wh);  cudaGetSymbolAddress(&p_wl, g_wl);
    cudaGetSymbolAddress(&p_oh, g_oh);  cudaGetSymbolAddress(&p_ol, g_ol);
    cudaGetSymbolAddress(&p_ah, g_ah);  cudaGetSymbolAddress(&p_al, g_al);

    const int GEMM_SMEM = 1024 + 3*32768;       // 3-stage K32 pipeline (2 CTAs/SM)
    cudaFuncSetAttribute(tc_gemm<0>, cudaFuncAttributeMaxDynamicSharedMemorySize, GEMM_SMEM);
    cudaFuncSetAttribute(tc_gemm<1>, cudaFuncAttributeMaxDynamicSharedMemorySize, GEMM_SMEM);
    const int ATTN_SMEM = 1024 + 65536 + 3*32768;   // Q + 3 KV bufs
    cudaFuncSetAttribute(attn_kernel, cudaFuncAttributeMaxDynamicSharedMemorySize, ATTN_SMEM);

    // 0) rope tables (must precede QKV epilogue)
    rope_table_kernel<<<(SEQ*64)/256, 256>>>();

    // 1) split inputs into bf16 hi/lo
    {
        int n;
        n = MROWS*D_MODEL;
        split_kernel<<<n/1024, 256>>>(query, (__nv_bfloat16*)p_qh, (__nv_bfloat16*)p_ql, n);
        n = 3*D_MODEL*D_MODEL;
        split_kernel<<<n/1024, 256>>>(W_qkv, (__nv_bfloat16*)p_wh, (__nv_bfloat16*)p_wl, n);
        n = D_MODEL*D_MODEL;
        split_kernel<<<n/1024, 256>>>(W_out, (__nv_bfloat16*)p_oh, (__nv_bfloat16*)p_ol, n);
    }

    // 2) QKV projection (HMMA) with fused rope/split epilogue
    tc_gemm<1><<<dim3(3*D_MODEL/128, MROWS/128), 256, GEMM_SMEM>>>(
        (const __nv_bfloat16*)p_qh, (const __nv_bfloat16*)p_ql,
        (const __nv_bfloat16*)p_wh, (const __nv_bfloat16*)p_wl,
        b_qkv, nullptr, 3*D_MODEL, D_MODEL);

    // 3) HMMA causal flash attention (S-prefetch pipelined) -> g_ah/g_al
    attn_kernel<<<dim3(SEQ/128, NHEAD, BATCH), 256, ATTN_SMEM>>>();

    // 4) Output projection (HMMA) -> d_out
    tc_gemm<0><<<dim3(D_MODEL/128, MROWS/128), 256, GEMM_SMEM>>>(
        (const __nv_bfloat16*)p_ah, (const __nv_bfloat16*)p_al,
        (const __nv_bfloat16*)p_oh, (const __nv_bfloat16*)p_ol,
        b_out, out, D_MODEL, D_MODEL);
}

// round 11
// speedup vs baseline: 1.0143x; 1.0143x over previous
#include <cuda_runtime.h>
#include <cuda_bf16.h>
#include <math.h>
#include <stdint.h>

#define D_MODEL 2048
#define NHEAD   16
#define HDIM    128
#define BATCH   2
#define SEQ     2048
#define MROWS   (BATCH*SEQ)   // 4096

// ---------------- device scratch (no runtime allocation) ----------------
__device__ __nv_bfloat16 g_qbh[(size_t)BATCH*NHEAD*SEQ*HDIM];  // roped+scaled Q hi/lo
__device__ __nv_bfloat16 g_qbl[(size_t)BATCH*NHEAD*SEQ*HDIM];
__device__ __nv_bfloat16 g_kbh[(size_t)BATCH*NHEAD*SEQ*HDIM];  // roped K hi/lo
__device__ __nv_bfloat16 g_kbl[(size_t)BATCH*NHEAD*SEQ*HDIM];
__device__ __nv_bfloat16 g_vbh[(size_t)BATCH*NHEAD*SEQ*HDIM];  // V hi/lo
__device__ __nv_bfloat16 g_vbl[(size_t)BATCH*NHEAD*SEQ*HDIM];

__device__ __nv_bfloat16 g_qh[(size_t)MROWS*D_MODEL];       // query hi/lo (GEMM A)
__device__ __nv_bfloat16 g_ql[(size_t)MROWS*D_MODEL];
__device__ __nv_bfloat16 g_wh[(size_t)3*D_MODEL*D_MODEL];   // W_qkv hi/lo
__device__ __nv_bfloat16 g_wl[(size_t)3*D_MODEL*D_MODEL];
__device__ __nv_bfloat16 g_oh[(size_t)D_MODEL*D_MODEL];     // W_out hi/lo
__device__ __nv_bfloat16 g_ol[(size_t)D_MODEL*D_MODEL];
__device__ __nv_bfloat16 g_ah[(size_t)MROWS*D_MODEL];       // attn-out hi/lo
__device__ __nv_bfloat16 g_al[(size_t)MROWS*D_MODEL];

__device__ float g_cos[(size_t)SEQ*64];                     // rope tables
__device__ float g_sin[(size_t)SEQ*64];

// ---------------- helpers ----------------
__device__ __forceinline__ uint32_t smem_u32(const void* p) {
    uint32_t a;
    asm("{ .reg .u64 t; cvta.to.shared.u64 t, %1; cvt.u32.u64 %0, t; }" : "=r"(a) : "l"(p));
    return a;
}
#define SWZ(o) ((o) ^ (((o) >> 3) & 0x70))

__device__ __forceinline__ void ldsm4(uint32_t addr, uint32_t* r) {
    asm volatile("ldmatrix.sync.aligned.m8n8.x4.shared.b16 {%0,%1,%2,%3}, [%4];"
                 : "=r"(r[0]), "=r"(r[1]), "=r"(r[2]), "=r"(r[3]) : "r"(addr));
}
__device__ __forceinline__ void ldsm4t(uint32_t addr, uint32_t* r) {
    asm volatile("ldmatrix.sync.aligned.m8n8.x4.trans.shared.b16 {%0,%1,%2,%3}, [%4];"
                 : "=r"(r[0]), "=r"(r[1]), "=r"(r[2]), "=r"(r[3]) : "r"(addr));
}
__device__ __forceinline__ void mma16816(float* c, const uint32_t* a, const uint32_t* b) {
    asm volatile(
        "mma.sync.aligned.m16n8k16.row.col.f32.bf16.bf16.f32 "
        "{%0,%1,%2,%3}, {%4,%5,%6,%7}, {%8,%9}, {%0,%1,%2,%3};"
        : "+f"(c[0]), "+f"(c[1]), "+f"(c[2]), "+f"(c[3])
        : "r"(a[0]), "r"(a[1]), "r"(a[2]), "r"(a[3]), "r"(b[0]), "r"(b[1]));
}
#define CP16(dst, src) \
    asm volatile("cp.async.cg.shared.global [%0], [%1], 16;" :: "r"(dst), "l"(src))
#define CP_COMMIT() asm volatile("cp.async.commit_group;" ::: "memory")
#define CP_WAIT0()  asm volatile("cp.async.wait_group 0;" ::: "memory")
#define CP_WAIT1()  asm volatile("cp.async.wait_group 1;" ::: "memory")

// split pair of fp32 into packed bf16x2 hi and lo (residual)
__device__ __forceinline__ void split2(float x, float y, uint32_t& hi, uint32_t& lo) {
    __nv_bfloat16 hx = __float2bfloat16(x), hy = __float2bfloat16(y);
    float rx = x - __bfloat162float(hx), ry = y - __bfloat162float(hy);
    __nv_bfloat16 lx = __float2bfloat16(rx), ly = __float2bfloat16(ry);
    hi = ((uint32_t)__bfloat16_as_ushort(hy) << 16) | __bfloat16_as_ushort(hx);
    lo = ((uint32_t)__bfloat16_as_ushort(ly) << 16) | __bfloat16_as_ushort(lx);
}

// ---------------------------------------------------------------------------
// fp32 -> bf16 hi/lo split
// ---------------------------------------------------------------------------
__global__ void split_kernel(const float* __restrict__ x,
                             __nv_bfloat16* __restrict__ hi,
                             __nv_bfloat16* __restrict__ lo, int n)
{
    int i = (blockIdx.x * 256 + threadIdx.x) * 4;
    if (i >= n) return;
    float4 v = *(const float4*)(x + i);
    uint32_t h0, l0, h1, l1;
    split2(v.x, v.y, h0, l0);
    split2(v.z, v.w, h1, l1);
    *(uint2*)(hi + i) = make_uint2(h0, h1);
    *(uint2*)(lo + i) = make_uint2(l0, l1);
}

// ---------------------------------------------------------------------------
// RoPE cos/sin table (double-precision range reduction, robust to fast-math)
// ---------------------------------------------------------------------------
__global__ void rope_table_kernel()
{
    int idx = blockIdx.x * 256 + threadIdx.x;       // SEQ*64 threads
    int l = idx >> 6, d = idx & 63;
    double invf = exp2(-(double)d * (13.287712379549449 / 64.0)); // 10000^(-d/64)
    double t    = fmod((double)l * invf, 6.283185307179586476925286766559);
    g_cos[idx] = cosf((float)t);
    g_sin[idx] = sinf((float)t);
}

// ---------------------------------------------------------------------------
// HMMA GEMM, 3-stage cp.async pipeline, K-chunks of 32 (packed hi|lo rows).
// Unchanged from round 9 (passing, 2 CTAs/SM).
// ---------------------------------------------------------------------------
__device__ __forceinline__ void load_chunk_async(
    const __nv_bfloat16* __restrict__ a0, const __nv_bfloat16* __restrict__ a1,
    const __nv_bfloat16* __restrict__ b0, const __nv_bfloat16* __restrict__ b1,
    int K, int k0, uint32_t dst)
{
    const __nv_bfloat16* s[4] = {a0, a1, b0, b1};
    #pragma unroll
    for (int t = 0; t < 4; t++) {
        const __nv_bfloat16* p = s[t] + k0;
        const uint32_t d = dst + (t >> 1) * 16384;
        #pragma unroll
        for (int it = 0; it < 2; it++) {
            int i = threadIdx.x + it * 256;     // 0..511 (16B units per array)
            int r = i >> 2, c = i & 3;
            CP16(d + SWZ(r * 128 + (t & 1) * 64 + c * 16),
                 p + (size_t)r * K + c * 8);
        }
    }
}

template<int MODE>
__global__ __launch_bounds__(256, 2)
void tc_gemm(const __nv_bfloat16* __restrict__ Ah, const __nv_bfloat16* __restrict__ Al,
             const __nv_bfloat16* __restrict__ Bh, const __nv_bfloat16* __restrict__ Bl,
             const float* __restrict__ bias, float* __restrict__ C, int N, int K)
{
    extern __shared__ char smem[];
    char* smp = (char*)(((uintptr_t)smem + 1023) & ~(uintptr_t)1023);
    const uint32_t bufs = smem_u32(smp);

    const int tid  = threadIdx.x;
    const int lane = tid & 31;
    const int wid  = tid >> 5;
    const int wr   = wid >> 2;
    const int wc   = wid & 3;
    const int m0   = blockIdx.y << 7;
    const int n0   = blockIdx.x << 7;
    const int KCHUNKS = K >> 5;

    const __nv_bfloat16* Ahp = Ah + (size_t)m0 * K;
    const __nv_bfloat16* Alp = Al + (size_t)m0 * K;
    const __nv_bfloat16* Bhp = Bh + (size_t)n0 * K;
    const __nv_bfloat16* Blp = Bl + (size_t)n0 * K;

    float acc[4][4][4];
    #pragma unroll
    for (int i = 0; i < 4; i++)
        #pragma unroll
        for (int j = 0; j < 4; j++)
            #pragma unroll
            for (int r = 0; r < 4; r++) acc[i][j][r] = 0.f;

    const int      arow = lane & 15;
    const uint32_t adk  = (lane >> 4) << 4;
    const int      brow = (lane & 7) + ((lane >> 4) << 3);
    const uint32_t bdk  = ((lane >> 3) & 1) << 4;

    load_chunk_async(Ahp, Alp, Bhp, Blp, K, 0,  bufs);
    CP_COMMIT();
    load_chunk_async(Ahp, Alp, Bhp, Blp, K, 32, bufs + 32768);
    CP_COMMIT();
    CP_WAIT1();
    __syncthreads();

    for (int c = 0; c < KCHUNKS; c++) {
        if (c + 2 < KCHUNKS) {
            load_chunk_async(Ahp, Alp, Bhp, Blp, K, (c + 2) << 5,
                             bufs + ((c + 2) % 3) * 32768);
            CP_COMMIT();
        }

        const uint32_t bA = bufs + (c % 3) * 32768;
        const uint32_t bB = bA + 16384;

        #pragma unroll
        for (int ks = 0; ks < 2; ks++) {
            const uint32_t kbA = (uint32_t)ks * 32 + adk;
            const uint32_t kbB = (uint32_t)ks * 32 + bdk;

            uint32_t ah[4][4], bh[2][4], bl[2][4];
            #pragma unroll
            for (int mt = 0; mt < 4; mt++)
                ldsm4(bA + SWZ((uint32_t)(wr*64 + mt*16 + arow) * 128 + kbA), ah[mt]);
            #pragma unroll
            for (int np = 0; np < 2; np++) {
                const uint32_t rw = (uint32_t)(wc*32 + np*16 + brow) * 128;
                ldsm4(bB + SWZ(rw + kbB), bh[np]);
                ldsm4(bB + SWZ(rw + 64 + kbB), bl[np]);
            }
            #pragma unroll
            for (int mt = 0; mt < 4; mt++)
                #pragma unroll
                for (int nt = 0; nt < 4; nt++) {
                    mma16816(acc[mt][nt], ah[mt], &bh[nt >> 1][(nt & 1) * 2]);
                    mma16816(acc[mt][nt], ah[mt], &bl[nt >> 1][(nt & 1) * 2]);
                }
            uint32_t al[4][4];
            #pragma unroll
            for (int mt = 0; mt < 4; mt++)
                ldsm4(bA + SWZ((uint32_t)(wr*64 + mt*16 + arow) * 128 + 64 + kbA), al[mt]);
            #pragma unroll
            for (int mt = 0; mt < 4; mt++)
                #pragma unroll
                for (int nt = 0; nt < 4; nt++)
                    mma16816(acc[mt][nt], al[mt], &bh[nt >> 1][(nt & 1) * 2]);
        }

        if (c + 1 < KCHUNKS) {
            if (c + 2 < KCHUNKS) CP_WAIT1(); else CP_WAIT0();
            __syncthreads();
        }
    }

    if (MODE == 0) {
        #pragma unroll
        for (int mt = 0; mt < 4; mt++) {
            const int mrow = m0 + wr*64 + mt*16 + (lane >> 2);
            #pragma unroll
            for (int nt = 0; nt < 4; nt++) {
                const int cg = n0 + wc*32 + nt*8 + (lane & 3)*2;
                const float bx = bias[cg], by = bias[cg + 1];
                *(float2*)&C[(size_t)mrow * N + cg] =
                    make_float2(acc[mt][nt][0] + bx, acc[mt][nt][1] + by);
                *(float2*)&C[(size_t)(mrow + 8) * N + cg] =
                    make_float2(acc[mt][nt][2] + bx, acc[mt][nt][3] + by);
            }
        }
        return;
    }

    // ---------------- MODE 1 epilogue: stage -> rope/split -> scatter -------
    float* st = (float*)smp;                 // 128 x 132 fp32
    const int PITCH = 132;
    __syncthreads();
    #pragma unroll
    for (int mt = 0; mt < 4; mt++) {
        const int r0 = wr*64 + mt*16 + (lane >> 2);
        #pragma unroll
        for (int nt = 0; nt < 4; nt++) {
            const int cl = wc*32 + nt*8 + (lane & 3)*2;
            const float bx = bias[n0 + cl], by = bias[n0 + cl + 1];
            *(float2*)&st[r0*PITCH + cl] =
                make_float2(acc[mt][nt][0] + bx, acc[mt][nt][1] + by);
            *(float2*)&st[(r0 + 8)*PITCH + cl] =
                make_float2(acc[mt][nt][2] + bx, acc[mt][nt][3] + by);
        }
    }
    __syncthreads();

    const int which = n0 >> 11;              // 0=q 1=k 2=v
    const int h     = (n0 >> 7) & 15;
    const int row   = tid >> 1;
    const int half  = tid & 1;
    const int m     = m0 + row;
    const int bb    = m >> 11;
    const int l     = m & (SEQ - 1);
    const size_t obase = (((size_t)(bb*NHEAD + h))*SEQ + l)*HDIM;
    const float* srow = st + row * PITCH;

    if (which == 2) {
        const int d0 = half * 32;
        uint32_t h1[16], l1[16], h2[16], l2[16];
        #pragma unroll
        for (int j = 0; j < 16; j++) {
            split2(srow[d0 + 2*j],      srow[d0 + 2*j + 1],      h1[j], l1[j]);
            split2(srow[d0 + 64 + 2*j], srow[d0 + 64 + 2*j + 1], h2[j], l2[j]);
        }
        #pragma unroll
        for (int j = 0; j < 4; j++) {
            *(uint4*)&g_vbh[obase + d0 + j*8]      = ((uint4*)h1)[j];
            *(uint4*)&g_vbl[obase + d0 + j*8]      = ((uint4*)l1)[j];
            *(uint4*)&g_vbh[obase + d0 + 64 + j*8] = ((uint4*)h2)[j];
            *(uint4*)&g_vbl[obase + d0 + 64 + j*8] = ((uint4*)l2)[j];
        }
    } else {
        const float qs = (which == 0) ? 0.08838834764831845f : 1.0f;
        const int d0 = half * 32;
        const float* ct = g_cos + (size_t)l * 64;
        const float* stb = g_sin + (size_t)l * 64;
        uint32_t h1[16], l1[16], h2[16], l2[16];
        #pragma unroll
        for (int j = 0; j < 16; j++) {
            const int d = d0 + 2*j;
            float2 cc = *(const float2*)&ct[d];
            float2 ss = *(const float2*)&stb[d];
            float x1a = srow[d],      x1b = srow[d + 1];
            float x2a = srow[d + 64], x2b = srow[d + 65];
            float o1a = (x1a*cc.x - x2a*ss.x) * qs;
            float o1b = (x1b*cc.y - x2b*ss.y) * qs;
            float o2a = (x2a*cc.x + x1a*ss.x) * qs;
            float o2b = (x2b*cc.y + x1b*ss.y) * qs;
            split2(o1a, o1b, h1[j], l1[j]);
            split2(o2a, o2b, h2[j], l2[j]);
        }
        __nv_bfloat16* oh = (which == 0) ? g_qbh : g_kbh;
        __nv_bfloat16* ol = (which == 0) ? g_qbl : g_kbl;
        #pragma unroll
        for (int j = 0; j < 4; j++) {
            *(uint4*)&oh[obase + d0 + j*8]      = ((uint4*)h1)[j];
            *(uint4*)&ol[obase + d0 + j*8]      = ((uint4*)l1)[j];
            *(uint4*)&oh[obase + d0 + 64 + j*8] = ((uint4*)h2)[j];
            *(uint4*)&ol[obase + d0 + 64 + j*8] = ((uint4*)l2)[j];
        }
    }
}

// ---------------------------------------------------------------------------
// Attention helpers (BK = 64)
// ---------------------------------------------------------------------------
// Load K (hi+lo) 64 rows into dst (Kh at +0, Kl at +16384)
__device__ __forceinline__ void load_k64(
    const __nv_bfloat16* __restrict__ kbh, const __nv_bfloat16* __restrict__ kbl,
    size_t row0, uint32_t dst, int tid)
{
    const __nv_bfloat16* arr[2] = {kbh, kbl};
    #pragma unroll
    for (int t = 0; t < 2; t++)
        #pragma unroll
        for (int it = 0; it < 4; it++) {
            int i = tid + it * 256;               // 0..1023
            int row = i >> 4, u = i & 15;
            uint32_t d = dst + t*16384 + (u>>3)*8192 + SWZ(row*128 + (u&7)*16);
            CP16(d, arr[t] + (row0 + row) * HDIM + u * 8);
        }
}
__device__ __forceinline__ void load_v64(
    const __nv_bfloat16* __restrict__ vbh, const __nv_bfloat16* __restrict__ vbl,
    size_t row0, uint32_t dst, int tid)
{
    const __nv_bfloat16* arr[2] = {vbh, vbl};
    #pragma unroll
    for (int t = 0; t < 2; t++)
        #pragma unroll
        for (int it = 0; it < 4; it++) {
            int i = tid + it * 256;
            int row = i >> 4, u = i & 15;
            uint32_t d = dst + t*16384 + (u>>3)*8192 + SWZ(row*128 + (u&7)*16);
            CP16(d, arr[t] + (row0 + row) * HDIM + u * 8);
        }
}

// S (16x64 per warp) = Qh Kh + Qh Kl + Ql Kh into s[32] (zeroed here).
__device__ __forceinline__ void compute_S64(
    uint32_t QH, uint32_t QL, uint32_t KB, int wid, int lane, float* s)
{
    #pragma unroll
    for (int i = 0; i < 32; i++) s[i] = 0.f;
    const int      arow  = wid*16 + (lane & 15);
    const uint32_t alo   = (uint32_t)((lane >> 4) << 4);
    const int      krow0 = (lane & 7) + ((lane >> 4) << 3);
    const uint32_t klo   = (uint32_t)(((lane >> 3) & 1) << 4);

    #pragma unroll
    for (int ks = 0; ks < 8; ks++) {
        const uint32_t aoff = (ks>>2)*16384 + SWZ(arow*128 + (ks&3)*32 + alo);
        uint32_t qa[4], qla[4];
        ldsm4(QH + aoff, qa);
        ldsm4(QL + aoff, qla);
        const uint32_t kcol = (uint32_t)((ks&3)*32) + klo;
        #pragma unroll
        for (int ntp = 0; ntp < 4; ntp++) {
            const uint32_t koff = (ks>>2)*8192 + SWZ((ntp*16 + krow0)*128 + kcol);
            uint32_t kb4[4], klb4[4];
            ldsm4(KB + koff, kb4);
            ldsm4(KB + 16384 + koff, klb4);
            mma16816(s + (2*ntp)*4,   qa,  &kb4[0]);
            mma16816(s + (2*ntp)*4,   qa,  &klb4[0]);
            mma16816(s + (2*ntp)*4,   qla, &kb4[0]);
            mma16816(s + (2*ntp+1)*4, qa,  &kb4[2]);
            mma16816(s + (2*ntp+1)*4, qa,  &klb4[2]);
            mma16816(s + (2*ntp+1)*4, qla, &kb4[2]);
        }
    }
}

// ---------------------------------------------------------------------------
// HMMA causal flash attention. BQ=128, BK=64.
// K double-buffered, V triple-buffered; S(kt+1) issued BEFORE softmax(kt) so
// the tensor pipe stays busy through softmax. ONE barrier per KV block.
// ---------------------------------------------------------------------------
__global__ __launch_bounds__(256, 1)
void attn_kernel()
{
    extern __shared__ char sm[];
    const uint32_t base = (smem_u32(sm) + 1023) & ~1023u;
    const uint32_t QH  = base;                // 2 panels x 16KB
    const uint32_t QL  = base + 32768;
    const uint32_t KB0 = base + 65536;        // K buf b: +b*32768 (Kh, +16K Kl)
    const uint32_t VB0 = base + 131072;       // V buf b: +b*32768 (Vh, +16K Vl)

    const int tid  = threadIdx.x;
    const int lane = tid & 31;
    const int wid  = tid >> 5;
    const int qt   = (int)gridDim.x - 1 - (int)blockIdx.x;  // heavy tiles first
    const int h    = blockIdx.y;
    const int b    = blockIdx.z;
    const int bh   = b*NHEAD + h;
    const int q0   = qt << 7;
    const int nkv  = 2*qt + 2;

    const size_t hoff = (size_t)bh * SEQ * HDIM;
    const __nv_bfloat16* qbh = g_qbh + hoff + (size_t)q0 * HDIM;
    const __nv_bfloat16* qbl = g_qbl + hoff + (size_t)q0 * HDIM;
    const __nv_bfloat16* kbh = g_kbh + hoff;
    const __nv_bfloat16* kbl = g_kbl + hoff;
    const __nv_bfloat16* vbh = g_vbh + hoff;
    const __nv_bfloat16* vbl = g_vbl + hoff;

    // ---- Q load + KV blocks 0,1 (nkv >= 2 always) ----
    #pragma unroll
    for (int it = 0; it < 8; it++) {
        int i = tid + it * 256;
        int row = i >> 4, u = i & 15;
        uint32_t off = (u >> 3) * 16384 + SWZ(row * 128 + (u & 7) * 16);
        CP16(QH + off, qbh + (size_t)row * HDIM + u * 8);
        CP16(QL + off, qbl + (size_t)row * HDIM + u * 8);
    }
    load_k64(kbh, kbl, 0, KB0, tid);
    load_v64(vbh, vbl, 0, VB0, tid);
    CP_COMMIT();                               // group: Q + KV0
    load_k64(kbh, kbl, 64, KB0 + 32768, tid);
    load_v64(vbh, vbl, 64, VB0 + 32768, tid);
    CP_COMMIT();                               // group: KV1
    CP_WAIT1();                                // Q + KV0 resident
    __syncthreads();

    float mr0 = -1e30f, mr1 = -1e30f, lr0 = 0.f, lr1 = 0.f;
    float o[16][4];
    #pragma unroll
    for (int t = 0; t < 16; t++)
        #pragma unroll
        for (int j = 0; j < 4; j++) o[t][j] = 0.f;

    const int rloc0 = wid*16 + (lane >> 2);
    const int rg0   = q0 + rloc0;
    const int vrow0 = (lane & 15);
    const uint32_t vcadd = (uint32_t)((lane >> 4) << 4);

    float scur[32], snext[32];
    compute_S64(QH, QL, KB0, wid, lane, scur);      // S(0) from K buf 0

    for (int kt = 0; kt < nkv; kt++) {
        if (kt + 1 < nkv) {
            CP_WAIT0();
            __syncthreads();   // KV(kt+1) visible; all warps done with iter kt-1
            if (kt + 2 < nkv) {
                // K(kt+2) -> buf kt%2 : K(kt) dead (S(kt) computed last iter).
                // V(kt+2) -> buf (kt+2)%3 : V(kt-1) dead (PV(kt-1) done,
                // barrier-protected).
                load_k64(kbh, kbl, (size_t)(kt + 2) * 64,
                         KB0 + ((kt + 2) & 1) * 32768, tid);
                load_v64(vbh, vbl, (size_t)(kt + 2) * 64,
                         VB0 + ((kt + 2) % 3) * 32768, tid);
                CP_COMMIT();
            }
            // queue S(kt+1) HMMAs; softmax below overlaps their execution
            compute_S64(QH, QL, KB0 + ((kt + 1) & 1) * 32768, wid, lane, snext);
        }

        // ---- softmax on scur (block kt) ----
        if (kt >= 2*qt) {
            #pragma unroll
            for (int t = 0; t < 8; t++) {
                #pragma unroll
                for (int j = 0; j < 2; j++) {
                    const int n = kt*64 + t*8 + 2*(lane & 3) + j;
                    if (n > rg0)     scur[t*4 + j]     = -1e30f;
                    if (n > rg0 + 8) scur[t*4 + 2 + j] = -1e30f;
                }
            }
        }

        float rm0 = -1e30f, rm1 = -1e30f;
        #pragma unroll
        for (int t = 0; t < 8; t++) {
            rm0 = fmaxf(rm0, fmaxf(scur[t*4+0], scur[t*4+1]));
            rm1 = fmaxf(rm1, fmaxf(scur[t*4+2], scur[t*4+3]));
        }
        rm0 = fmaxf(rm0, __shfl_xor_sync(0xffffffffu, rm0, 1));
        rm0 = fmaxf(rm0, __shfl_xor_sync(0xffffffffu, rm0, 2));
        rm1 = fmaxf(rm1, __shfl_xor_sync(0xffffffffu, rm1, 1));
        rm1 = fmaxf(rm1, __shfl_xor_sync(0xffffffffu, rm1, 2));

        const float mn0 = fmaxf(mr0, rm0), mn1 = fmaxf(mr1, rm1);
        const float sf0 = __expf(mr0 - mn0), sf1 = __expf(mr1 - mn1);
        mr0 = mn0; mr1 = mn1;

        float rs0 = 0.f, rs1 = 0.f;
        #pragma unroll
        for (int t = 0; t < 8; t++) {
            scur[t*4+0] = __expf(scur[t*4+0] - mn0);
            scur[t*4+1] = __expf(scur[t*4+1] - mn0);
            scur[t*4+2] = __expf(scur[t*4+2] - mn1);
            scur[t*4+3] = __expf(scur[t*4+3] - mn1);
            rs0 += scur[t*4+0] + scur[t*4+1];
            rs1 += scur[t*4+2] + scur[t*4+3];
        }
        rs0 += __shfl_xor_sync(0xffffffffu, rs0, 1);
        rs0 += __shfl_xor_sync(0xffffffffu, rs0, 2);
        rs1 += __shfl_xor_sync(0xffffffffu, rs1, 1);
        rs1 += __shfl_xor_sync(0xffffffffu, rs1, 2);
        lr0 = lr0 * sf0 + rs0;
        lr1 = lr1 * sf1 + rs1;

        #pragma unroll
        for (int t = 0; t < 16; t++) {
            o[t][0] *= sf0; o[t][1] *= sf0;
            o[t][2] *= sf1; o[t][3] *= sf1;
        }

        // ---- P split into hi/lo A-fragments (4 k16 groups) ----
        uint32_t aph[4][4], apl[4][4];
        #pragma unroll
        for (int g = 0; g < 4; g++) {
            split2(scur[(2*g)*4+0],   scur[(2*g)*4+1],   aph[g][0], apl[g][0]);
            split2(scur[(2*g)*4+2],   scur[(2*g)*4+3],   aph[g][1], apl[g][1]);
            split2(scur[(2*g+1)*4+0], scur[(2*g+1)*4+1], aph[g][2], apl[g][2]);
            split2(scur[(2*g+1)*4+2], scur[(2*g+1)*4+3], aph[g][3], apl[g][3]);
        }

        // ---- O += P V   (V from buf kt%3) ----
        const uint32_t VB = VB0 + (kt % 3) * 32768;
        #pragma unroll
        for (int dtp = 0; dtp < 8; dtp++) {
            const uint32_t vcol = (uint32_t)((dtp&3)*32) + vcadd;
            #pragma unroll
            for (int g = 0; g < 4; g++) {
                const uint32_t voff = (dtp>>2)*8192 + SWZ((g*16 + vrow0)*128 + vcol);
                uint32_t vb4[4], vlb4[4];
                ldsm4t(VB + voff, vb4);
                ldsm4t(VB + 16384 + voff, vlb4);
                mma16816(o[2*dtp],   aph[g], &vb4[0]);
                mma16816(o[2*dtp],   aph[g], &vlb4[0]);
                mma16816(o[2*dtp],   apl[g], &vb4[0]);
                mma16816(o[2*dtp+1], aph[g], &vb4[2]);
                mma16816(o[2*dtp+1], aph[g], &vlb4[2]);
                mma16816(o[2*dtp+1], apl[g], &vb4[2]);
            }
        }

        #pragma unroll
        for (int i = 0; i < 32; i++) scur[i] = snext[i];
    }

    // ---- epilogue ----
    const float inv0 = 1.f / lr0, inv1 = 1.f / lr1;
    const size_t row0 = ((size_t)(b*SEQ + rg0)) * D_MODEL + h*HDIM;
    const size_t row1 = row0 + 8 * D_MODEL;
    #pragma unroll
    for (int t = 0; t < 16; t++) {
        const int d = t*8 + 2*(lane & 3);
        uint32_t hi, lo;
        split2(o[t][0]*inv0, o[t][1]*inv0, hi, lo);
        *(uint32_t*)&g_ah[row0 + d] = hi;
        *(uint32_t*)&g_al[row0 + d] = lo;
        split2(o[t][2]*inv1, o[t][3]*inv1, hi, lo);
        *(uint32_t*)&g_ah[row1 + d] = hi;
        *(uint32_t*)&g_al[row1 + d] = lo;
    }
}

// ---------------------------------------------------------------------------
extern "C" void kernel_launch(void* const* d_in, const int* in_sizes, int n_in,
                              void* d_out, int out_size)
{
    const float* query = (const float*)d_in[0];
    const float* W_qkv = (const float*)d_in[1];
    const float* b_qkv = (const float*)d_in[2];
    const float* W_out = (const float*)d_in[3];
    const float* b_out = (const float*)d_in[4];
    float* out = (float*)d_out;

    void *p_qh, *p_ql, *p_wh, *p_wl, *p_oh, *p_ol, *p_ah, *p_al;
    cudaGetSymbolAddress(&p_qh, g_qh);  cudaGetSymbolAddress(&p_ql, g_ql);
    cudaGetSymbolAddress(&p_wh, g_wh);  cudaGetSymbolAddress(&p_wl, g_wl);
    cudaGetSymbolAddress(&p_oh, g_oh);  cudaGetSymbolAddress(&p_ol, g_ol);
    cudaGetSymbolAddress(&p_ah, g_ah);  cudaGetSymbolAddress(&p_al, g_al);

    const int GEMM_SMEM = 1024 + 3*32768;       // 3-stage K32 pipeline (2 CTAs/SM)
    cudaFuncSetAttribute(tc_gemm<0>, cudaFuncAttributeMaxDynamicSharedMemorySize, GEMM_SMEM);
    cudaFuncSetAttribute(tc_gemm<1>, cudaFuncAttributeMaxDynamicSharedMemorySize, GEMM_SMEM);
    // Q 64KB + K 2x32KB + V 3x32KB = 224KB (+1KB align)
    const int ATTN_SMEM = 1024 + 65536 + 2*32768 + 3*32768;
    cudaFuncSetAttribute(attn_kernel, cudaFuncAttributeMaxDynamicSharedMemorySize, ATTN_SMEM);

    // 0) rope tables (must precede QKV epilogue)
    rope_table_kernel<<<(SEQ*64)/256, 256>>>();

    // 1) split inputs into bf16 hi/lo
    {
        int n;
        n = MROWS*D_MODEL;
        split_kernel<<<n/1024, 256>>>(query, (__nv_bfloat16*)p_qh, (__nv_bfloat16*)p_ql, n);
        n = 3*D_MODEL*D_MODEL;
        split_kernel<<<n/1024, 256>>>(W_qkv, (__nv_bfloat16*)p_wh, (__nv_bfloat16*)p_wl, n);
        n = D_MODEL*D_MODEL;
        split_kernel<<<n/1024, 256>>>(W_out, (__nv_bfloat16*)p_oh, (__nv_bfloat16*)p_ol, n);
    }

    // 2) QKV projection (HMMA) with fused rope/split epilogue
    tc_gemm<1><<<dim3(3*D_MODEL/128, MROWS/128), 256, GEMM_SMEM>>>(
        (const __nv_bfloat16*)p_qh, (const __nv_bfloat16*)p_ql,
        (const __nv_bfloat16*)p_wh, (const __nv_bfloat16*)p_wl,
        b_qkv, nullptr, 3*D_MODEL, D_MODEL);

    // 3) HMMA causal flash attention (S-prefetch, BK=64) -> g_ah/g_al
    attn_kernel<<<dim3(SEQ/128, NHEAD, BATCH), 256, ATTN_SMEM>>>();

    // 4) Output projection (HMMA) -> d_out
    tc_gemm<0><<<dim3(D_MODEL/128, MROWS/128), 256, GEMM_SMEM>>>(
        (const __nv_bfloat16*)p_ah, (const __nv_bfloat16*)p_al,
        (const __nv_bfloat16*)p_oh, (const __nv_bfloat16*)p_ol,
        b_out, out, D_MODEL, D_MODEL);
}

// round 12
// speedup vs baseline: 1.4202x; 1.4001x over previous
#include <cuda_runtime.h>
#include <cuda_fp16.h>
#include <math.h>
#include <stdint.h>

#define D_MODEL 2048
#define NHEAD   16
#define HDIM    128
#define BATCH   2
#define SEQ     2048
#define MROWS   (BATCH*SEQ)   // 4096

// ---------------- device scratch (no runtime allocation) ----------------
__device__ __half g_qbh[(size_t)BATCH*NHEAD*SEQ*HDIM];  // roped+scaled Q hi/lo (fp16)
__device__ __half g_qbl[(size_t)BATCH*NHEAD*SEQ*HDIM];
__device__ __half g_kb [(size_t)BATCH*NHEAD*SEQ*HDIM];  // roped K (single fp16)
__device__ __half g_vb [(size_t)BATCH*NHEAD*SEQ*HDIM];  // V (single fp16)

__device__ __half g_qh[(size_t)MROWS*D_MODEL];          // query hi/lo (GEMM A)
__device__ __half g_ql[(size_t)MROWS*D_MODEL];
__device__ __half g_w [(size_t)3*D_MODEL*D_MODEL];      // W_qkv (single fp16)
__device__ __half g_o [(size_t)D_MODEL*D_MODEL];        // W_out (single fp16)
__device__ __half g_ah[(size_t)MROWS*D_MODEL];          // attn-out hi/lo
__device__ __half g_al[(size_t)MROWS*D_MODEL];

__device__ float g_cos[(size_t)SEQ*64];                 // rope tables
__device__ float g_sin[(size_t)SEQ*64];

// ---------------- helpers ----------------
__device__ __forceinline__ uint32_t smem_u32(const void* p) {
    uint32_t a;
    asm("{ .reg .u64 t; cvta.to.shared.u64 t, %1; cvt.u32.u64 %0, t; }" : "=r"(a) : "l"(p));
    return a;
}
#define SWZ(o) ((o) ^ (((o) >> 3) & 0x70))

__device__ __forceinline__ void ldsm4(uint32_t addr, uint32_t* r) {
    asm volatile("ldmatrix.sync.aligned.m8n8.x4.shared.b16 {%0,%1,%2,%3}, [%4];"
                 : "=r"(r[0]), "=r"(r[1]), "=r"(r[2]), "=r"(r[3]) : "r"(addr));
}
__device__ __forceinline__ void ldsm4t(uint32_t addr, uint32_t* r) {
    asm volatile("ldmatrix.sync.aligned.m8n8.x4.trans.shared.b16 {%0,%1,%2,%3}, [%4];"
                 : "=r"(r[0]), "=r"(r[1]), "=r"(r[2]), "=r"(r[3]) : "r"(addr));
}
__device__ __forceinline__ void mma16816(float* c, const uint32_t* a, const uint32_t* b) {
    asm volatile(
        "mma.sync.aligned.m16n8k16.row.col.f32.f16.f16.f32 "
        "{%0,%1,%2,%3}, {%4,%5,%6,%7}, {%8,%9}, {%0,%1,%2,%3};"
        : "+f"(c[0]), "+f"(c[1]), "+f"(c[2]), "+f"(c[3])
        : "r"(a[0]), "r"(a[1]), "r"(a[2]), "r"(a[3]), "r"(b[0]), "r"(b[1]));
}
#define CP16(dst, src) \
    asm volatile("cp.async.cg.shared.global [%0], [%1], 16;" :: "r"(dst), "l"(src))
#define CP_COMMIT() asm volatile("cp.async.commit_group;" ::: "memory")
#define CP_WAIT0()  asm volatile("cp.async.wait_group 0;" ::: "memory")
#define CP_WAIT1()  asm volatile("cp.async.wait_group 1;" ::: "memory")

// split pair of fp32 into packed fp16x2 hi and lo (residual)
__device__ __forceinline__ void split2h(float x, float y, uint32_t& hi, uint32_t& lo) {
    __half hx = __float2half_rn(x), hy = __float2half_rn(y);
    float rx = x - __half2float(hx), ry = y - __half2float(hy);
    __half lx = __float2half_rn(rx), ly = __float2half_rn(ry);
    hi = ((uint32_t)__half_as_ushort(hy) << 16) | __half_as_ushort(hx);
    lo = ((uint32_t)__half_as_ushort(ly) << 16) | __half_as_ushort(lx);
}
__device__ __forceinline__ uint32_t pack2h(float x, float y) {
    __half hx = __float2half_rn(x), hy = __float2half_rn(y);
    return ((uint32_t)__half_as_ushort(hy) << 16) | __half_as_ushort(hx);
}

// ---------------------------------------------------------------------------
// fp32 -> fp16 hi/lo split, and fp32 -> fp16 single convert
// ---------------------------------------------------------------------------
__global__ void splith_kernel(const float* __restrict__ x,
                              __half* __restrict__ hi,
                              __half* __restrict__ lo, int n)
{
    int i = (blockIdx.x * 256 + threadIdx.x) * 4;
    if (i >= n) return;
    float4 v = *(const float4*)(x + i);
    uint32_t h0, l0, h1, l1;
    split2h(v.x, v.y, h0, l0);
    split2h(v.z, v.w, h1, l1);
    *(uint2*)(hi + i) = make_uint2(h0, h1);
    *(uint2*)(lo + i) = make_uint2(l0, l1);
}
__global__ void cvth_kernel(const float* __restrict__ x,
                            __half* __restrict__ y, int n)
{
    int i = (blockIdx.x * 256 + threadIdx.x) * 4;
    if (i >= n) return;
    float4 v = *(const float4*)(x + i);
    *(uint2*)(y + i) = make_uint2(pack2h(v.x, v.y), pack2h(v.z, v.w));
}

// ---------------------------------------------------------------------------
// RoPE cos/sin table (double-precision range reduction, robust to fast-math)
// ---------------------------------------------------------------------------
__global__ void rope_table_kernel()
{
    int idx = blockIdx.x * 256 + threadIdx.x;       // SEQ*64 threads
    int l = idx >> 6, d = idx & 63;
    double invf = exp2(-(double)d * (13.287712379549449 / 64.0)); // 10000^(-d/64)
    double t    = fmod((double)l * invf, 6.283185307179586476925286766559);
    g_cos[idx] = cosf((float)t);
    g_sin[idx] = sinf((float)t);
}

// ---------------------------------------------------------------------------
// HMMA GEMM (fp16, 2 products): C = (Ah+Al)*B^T + bias, fp32 accum.
// CTA 128x128, 8 warps, K-chunks of 32, 3-stage cp.async, 2 CTAs/SM.
// Chunk layout (24KB): A 16KB (128 rows x [hi 64B | lo 64B], SW128);
//   B 8KB (64 phys rows x 128B: N rows 0-63 left half, 64-127 right half).
// MODE 0: write C fp32 row-major.
// MODE 1: QKV epilogue with fused RoPE: q -> fp16 hi/lo (scaled 1/sqrt(128));
//         k -> roped single fp16; v -> single fp16. All [B,H,L,128].
// ---------------------------------------------------------------------------
__device__ __forceinline__ void load_chunk_async(
    const __half* __restrict__ a0, const __half* __restrict__ a1,
    const __half* __restrict__ b, int K, int k0, uint32_t dst)
{
    const __half* s[2] = {a0, a1};
    #pragma unroll
    for (int t = 0; t < 2; t++) {
        const __half* p = s[t] + k0;
        #pragma unroll
        for (int it = 0; it < 2; it++) {
            int i = threadIdx.x + it * 256;     // 0..511
            int r = i >> 2, c = i & 3;
            CP16(dst + SWZ(r * 128 + t * 64 + c * 16), p + (size_t)r * K + c * 8);
        }
    }
    const __half* pb = b + k0;
    #pragma unroll
    for (int it = 0; it < 2; it++) {
        int i = threadIdx.x + it * 256;         // 0..511
        int r = i >> 2, c = i & 3;              // r = N row 0..127
        CP16(dst + 16384 + SWZ((r & 63) * 128 + ((r >> 6) << 6) + c * 16),
             pb + (size_t)r * K + c * 8);
    }
}

template<int MODE>
__global__ __launch_bounds__(256, 2)
void tc_gemm(const __half* __restrict__ Ah, const __half* __restrict__ Al,
             const __half* __restrict__ B,
             const float* __restrict__ bias, float* __restrict__ C, int N, int K)
{
    extern __shared__ char smem[];
    char* smp = (char*)(((uintptr_t)smem + 1023) & ~(uintptr_t)1023);
    const uint32_t bufs = smem_u32(smp);

    const int tid  = threadIdx.x;
    const int lane = tid & 31;
    const int wid  = tid >> 5;
    const int wr   = wid >> 2;
    const int wc   = wid & 3;
    const int m0   = blockIdx.y << 7;
    const int n0   = blockIdx.x << 7;
    const int KCHUNKS = K >> 5;

    const __half* Ahp = Ah + (size_t)m0 * K;
    const __half* Alp = Al + (size_t)m0 * K;
    const __half* Bp  = B  + (size_t)n0 * K;

    float acc[4][4][4];
    #pragma unroll
    for (int i = 0; i < 4; i++)
        #pragma unroll
        for (int j = 0; j < 4; j++)
            #pragma unroll
            for (int r = 0; r < 4; r++) acc[i][j][r] = 0.f;

    const int      arow = lane & 15;
    const uint32_t adk  = (lane >> 4) << 4;
    const int      brow = (lane & 7) + ((lane >> 4) << 3);
    const uint32_t bdk  = ((lane >> 3) & 1) << 4;

    load_chunk_async(Ahp, Alp, Bp, K, 0,  bufs);
    CP_COMMIT();
    load_chunk_async(Ahp, Alp, Bp, K, 32, bufs + 24576);
    CP_COMMIT();
    CP_WAIT1();
    __syncthreads();

    for (int c = 0; c < KCHUNKS; c++) {
        if (c + 2 < KCHUNKS) {
            load_chunk_async(Ahp, Alp, Bp, K, (c + 2) << 5,
                             bufs + ((c + 2) % 3) * 24576);
            CP_COMMIT();
        }

        const uint32_t bA = bufs + (c % 3) * 24576;
        const uint32_t bB = bA + 16384;

        #pragma unroll
        for (int ks = 0; ks < 2; ks++) {
            const uint32_t kbA = (uint32_t)ks * 32 + adk;
            const uint32_t kbB = (uint32_t)ks * 32 + bdk;

            uint32_t ah[4][4], al[4][4], bx[2][4];
            #pragma unroll
            for (int mt = 0; mt < 4; mt++) {
                const uint32_t rw = (uint32_t)(wr*64 + mt*16 + arow) * 128;
                ldsm4(bA + SWZ(rw + kbA), ah[mt]);
                ldsm4(bA + SWZ(rw + 64 + kbA), al[mt]);
            }
            #pragma unroll
            for (int np = 0; np < 2; np++) {
                const int rw = wc*32 + np*16 + brow;
                ldsm4(bB + SWZ((uint32_t)(rw & 63) * 128 + (uint32_t)((rw >> 6) << 6) + kbB),
                      bx[np]);
            }
            #pragma unroll
            for (int mt = 0; mt < 4; mt++)
                #pragma unroll
                for (int nt = 0; nt < 4; nt++) {
                    const uint32_t* b2 = &bx[nt >> 1][(nt & 1) * 2];
                    mma16816(acc[mt][nt], ah[mt], b2);
                    mma16816(acc[mt][nt], al[mt], b2);
                }
        }

        if (c + 1 < KCHUNKS) {
            if (c + 2 < KCHUNKS) CP_WAIT1(); else CP_WAIT0();
            __syncthreads();
        }
    }

    if (MODE == 0) {
        #pragma unroll
        for (int mt = 0; mt < 4; mt++) {
            const int mrow = m0 + wr*64 + mt*16 + (lane >> 2);
            #pragma unroll
            for (int nt = 0; nt < 4; nt++) {
                const int cg = n0 + wc*32 + nt*8 + (lane & 3)*2;
                const float bx2 = bias[cg], by = bias[cg + 1];
                *(float2*)&C[(size_t)mrow * N + cg] =
                    make_float2(acc[mt][nt][0] + bx2, acc[mt][nt][1] + by);
                *(float2*)&C[(size_t)(mrow + 8) * N + cg] =
                    make_float2(acc[mt][nt][2] + bx2, acc[mt][nt][3] + by);
            }
        }
        return;
    }

    // ---------------- MODE 1 epilogue: stage -> rope/convert -> scatter -----
    float* st = (float*)smp;                 // 128 x 132 fp32 (67.6KB <= 72KB)
    const int PITCH = 132;
    __syncthreads();
    #pragma unroll
    for (int mt = 0; mt < 4; mt++) {
        const int r0 = wr*64 + mt*16 + (lane >> 2);
        #pragma unroll
        for (int nt = 0; nt < 4; nt++) {
            const int cl = wc*32 + nt*8 + (lane & 3)*2;
            const float bx2 = bias[n0 + cl], by = bias[n0 + cl + 1];
            *(float2*)&st[r0*PITCH + cl] =
                make_float2(acc[mt][nt][0] + bx2, acc[mt][nt][1] + by);
            *(float2*)&st[(r0 + 8)*PITCH + cl] =
                make_float2(acc[mt][nt][2] + bx2, acc[mt][nt][3] + by);
        }
    }
    __syncthreads();

    const int which = n0 >> 11;              // 0=q 1=k 2=v
    const int h     = (n0 >> 7) & 15;
    const int row   = tid >> 1;
    const int half  = tid & 1;
    const int m     = m0 + row;
    const int bb    = m >> 11;
    const int l     = m & (SEQ - 1);
    const size_t obase = (((size_t)(bb*NHEAD + h))*SEQ + l)*HDIM;
    const float* srow = st + row * PITCH;
    const int d0 = half * 32;                // covers [d0,d0+32) and [d0+64,d0+96)

    if (which == 2) {
        uint32_t h1[16], h2[16];
        #pragma unroll
        for (int j = 0; j < 16; j++) {
            h1[j] = pack2h(srow[d0 + 2*j],      srow[d0 + 2*j + 1]);
            h2[j] = pack2h(srow[d0 + 64 + 2*j], srow[d0 + 64 + 2*j + 1]);
        }
        #pragma unroll
        for (int j = 0; j < 4; j++) {
            *(uint4*)&g_vb[obase + d0 + j*8]      = ((uint4*)h1)[j];
            *(uint4*)&g_vb[obase + d0 + 64 + j*8] = ((uint4*)h2)[j];
        }
    } else {
        const float qs = (which == 0) ? 0.08838834764831845f : 1.0f;
        const float* ct  = g_cos + (size_t)l * 64;
        const float* stb = g_sin + (size_t)l * 64;
        if (which == 0) {
            uint32_t h1[16], l1[16], h2[16], l2[16];
            #pragma unroll
            for (int j = 0; j < 16; j++) {
                const int d = d0 + 2*j;
                float2 cc = *(const float2*)&ct[d];
                float2 ss = *(const float2*)&stb[d];
                float x1a = srow[d],      x1b = srow[d + 1];
                float x2a = srow[d + 64], x2b = srow[d + 65];
                split2h((x1a*cc.x - x2a*ss.x)*qs, (x1b*cc.y - x2b*ss.y)*qs, h1[j], l1[j]);
                split2h((x2a*cc.x + x1a*ss.x)*qs, (x2b*cc.y + x1b*ss.y)*qs, h2[j], l2[j]);
            }
            #pragma unroll
            for (int j = 0; j < 4; j++) {
                *(uint4*)&g_qbh[obase + d0 + j*8]      = ((uint4*)h1)[j];
                *(uint4*)&g_qbl[obase + d0 + j*8]      = ((uint4*)l1)[j];
                *(uint4*)&g_qbh[obase + d0 + 64 + j*8] = ((uint4*)h2)[j];
                *(uint4*)&g_qbl[obase + d0 + 64 + j*8] = ((uint4*)l2)[j];
            }
        } else {
            uint32_t h1[16], h2[16];
            #pragma unroll
            for (int j = 0; j < 16; j++) {
                const int d = d0 + 2*j;
                float2 cc = *(const float2*)&ct[d];
                float2 ss = *(const float2*)&stb[d];
                float x1a = srow[d],      x1b = srow[d + 1];
                float x2a = srow[d + 64], x2b = srow[d + 65];
                h1[j] = pack2h(x1a*cc.x - x2a*ss.x, x1b*cc.y - x2b*ss.y);
                h2[j] = pack2h(x2a*cc.x + x1a*ss.x, x2b*cc.y + x1b*ss.y);
            }
            #pragma unroll
            for (int j = 0; j < 4; j++) {
                *(uint4*)&g_kb[obase + d0 + j*8]      = ((uint4*)h1)[j];
                *(uint4*)&g_kb[obase + d0 + 64 + j*8] = ((uint4*)h2)[j];
            }
        }
    }
}

// ---------------------------------------------------------------------------
// HMMA causal flash attention (fp16, 2 products). BQ=128, BK=64, 8 warps.
// Q split hi/lo; K,V single fp16. Double-buffered KV (32KB per buffer:
// K 2x8KB panels at +0, V 2x8KB panels at +16384). Round-9 schedule.
// ---------------------------------------------------------------------------
__global__ __launch_bounds__(256, 1)
void attn_kernel()
{
    extern __shared__ char sm[];
    const uint32_t base = (smem_u32(sm) + 1023) & ~1023u;
    const uint32_t QH = base;                 // 2 panels x 16KB
    const uint32_t QL = base + 32768;
    const uint32_t KV = base + 65536;         // buf b at +b*32768

    const int tid  = threadIdx.x;
    const int lane = tid & 31;
    const int wid  = tid >> 5;
    const int qt   = (int)gridDim.x - 1 - (int)blockIdx.x;  // heavy tiles first
    const int h    = blockIdx.y;
    const int b    = blockIdx.z;
    const int bh   = b*NHEAD + h;
    const int q0   = qt << 7;
    const int nkv  = 2*qt + 2;

    const size_t hoff = (size_t)bh * SEQ * HDIM;
    const __half* qbh = g_qbh + hoff + (size_t)q0 * HDIM;
    const __half* qbl = g_qbl + hoff + (size_t)q0 * HDIM;
    const __half* kb  = g_kb + hoff;
    const __half* vb  = g_vb + hoff;

    // ---- Q load ----
    #pragma unroll
    for (int it = 0; it < 8; it++) {
        int i = tid + it * 256;
        int row = i >> 4, u = i & 15;
        uint32_t off = (u >> 3) * 16384 + SWZ(row * 128 + (u & 7) * 16);
        CP16(QH + off, qbh + (size_t)row * HDIM + u * 8);
        CP16(QL + off, qbl + (size_t)row * HDIM + u * 8);
    }
    // ---- KV block 0 ----
    {
        const __half* arr[2] = {kb, vb};
        #pragma unroll
        for (int t = 0; t < 2; t++)
            #pragma unroll
            for (int it = 0; it < 4; it++) {
                int i = tid + it * 256;
                int row = i >> 4, u = i & 15;
                uint32_t d = KV + t*16384 + (u>>3)*8192 + SWZ(row*128 + (u&7)*16);
                CP16(d, arr[t] + (size_t)row * HDIM + u * 8);
            }
    }
    CP_COMMIT();
    CP_WAIT0();
    __syncthreads();

    float mr0 = -1e30f, mr1 = -1e30f, lr0 = 0.f, lr1 = 0.f;
    float o[16][4];
    #pragma unroll
    for (int t = 0; t < 16; t++)
        #pragma unroll
        for (int j = 0; j < 4; j++) o[t][j] = 0.f;

    const int rloc0 = wid*16 + (lane >> 2);
    const int rg0   = q0 + rloc0;

    for (int kt = 0; kt < nkv; kt++) {
        const uint32_t KB = KV + (kt & 1) * 32768;
        const uint32_t VB = KB + 16384;

        if (kt + 1 < nkv) {
            const __half* arr[2] = {kb, vb};
            const size_t s0 = (size_t)(kt + 1) * 64 * HDIM;
            const uint32_t nb = KV + ((kt + 1) & 1) * 32768;
            #pragma unroll
            for (int t = 0; t < 2; t++)
                #pragma unroll
                for (int it = 0; it < 4; it++) {
                    int i = tid + it * 256;
                    int row = i >> 4, u = i & 15;
                    uint32_t d = nb + t*16384 + (u>>3)*8192 + SWZ(row*128 + (u&7)*16);
                    CP16(d, arr[t] + s0 + (size_t)row * HDIM + u * 8);
                }
            CP_COMMIT();
        }

        // ---- S = (Qh+Ql) K^T ----
        float s[8][4];
        #pragma unroll
        for (int t = 0; t < 8; t++)
            #pragma unroll
            for (int j = 0; j < 4; j++) s[t][j] = 0.f;

        #pragma unroll
        for (int ks = 0; ks < 8; ks++) {
            const int arow = wid*16 + (lane & 15);
            const uint32_t aoff = (ks>>2)*16384
                + SWZ(arow*128 + (ks&3)*32 + ((lane>>4)<<4));
            uint32_t qa[4], qla[4];
            ldsm4(QH + aoff, qa);
            ldsm4(QL + aoff, qla);

            const int krow0 = (lane & 7) + ((lane >> 4) << 3);
            const uint32_t kcol = (uint32_t)((ks&3)*32 + (((lane>>3)&1)<<4));
            #pragma unroll
            for (int ntp = 0; ntp < 4; ntp++) {
                const uint32_t koff = (ks>>2)*8192 + SWZ((ntp*16 + krow0)*128 + kcol);
                uint32_t kb4[4];
                ldsm4(KB + koff, kb4);
                mma16816(s[2*ntp],   qa,  &kb4[0]);
                mma16816(s[2*ntp],   qla, &kb4[0]);
                mma16816(s[2*ntp+1], qa,  &kb4[2]);
                mma16816(s[2*ntp+1], qla, &kb4[2]);
            }
        }

        if (kt >= 2*qt) {
            #pragma unroll
            for (int t = 0; t < 8; t++) {
                #pragma unroll
                for (int j = 0; j < 2; j++) {
                    const int n = kt*64 + t*8 + 2*(lane & 3) + j;
                    if (n > rg0)     s[t][j]   = -1e30f;
                    if (n > rg0 + 8) s[t][2+j] = -1e30f;
                }
            }
        }

        float rm0 = -1e30f, rm1 = -1e30f;
        #pragma unroll
        for (int t = 0; t < 8; t++) {
            rm0 = fmaxf(rm0, fmaxf(s[t][0], s[t][1]));
            rm1 = fmaxf(rm1, fmaxf(s[t][2], s[t][3]));
        }
        rm0 = fmaxf(rm0, __shfl_xor_sync(0xffffffffu, rm0, 1));
        rm0 = fmaxf(rm0, __shfl_xor_sync(0xffffffffu, rm0, 2));
        rm1 = fmaxf(rm1, __shfl_xor_sync(0xffffffffu, rm1, 1));
        rm1 = fmaxf(rm1, __shfl_xor_sync(0xffffffffu, rm1, 2));

        const float mn0 = fmaxf(mr0, rm0), mn1 = fmaxf(mr1, rm1);
        const float sf0 = __expf(mr0 - mn0), sf1 = __expf(mr1 - mn1);
        mr0 = mn0; mr1 = mn1;

        float rs0 = 0.f, rs1 = 0.f;
        #pragma unroll
        for (int t = 0; t < 8; t++) {
            s[t][0] = __expf(s[t][0] - mn0);
            s[t][1] = __expf(s[t][1] - mn0);
            s[t][2] = __expf(s[t][2] - mn1);
            s[t][3] = __expf(s[t][3] - mn1);
            rs0 += s[t][0] + s[t][1];
            rs1 += s[t][2] + s[t][3];
        }
        rs0 += __shfl_xor_sync(0xffffffffu, rs0, 1);
        rs0 += __shfl_xor_sync(0xffffffffu, rs0, 2);
        rs1 += __shfl_xor_sync(0xffffffffu, rs1, 1);
        rs1 += __shfl_xor_sync(0xffffffffu, rs1, 2);
        lr0 = lr0 * sf0 + rs0;
        lr1 = lr1 * sf1 + rs1;

        #pragma unroll
        for (int t = 0; t < 16; t++) {
            o[t][0] *= sf0; o[t][1] *= sf0;
            o[t][2] *= sf1; o[t][3] *= sf1;
        }

        // ---- P split (fp16 hi/lo) into A-fragments ----
        uint32_t aph[4][4], apl[4][4];
        #pragma unroll
        for (int g = 0; g < 4; g++) {
            split2h(s[2*g][0],   s[2*g][1],   aph[g][0], apl[g][0]);
            split2h(s[2*g][2],   s[2*g][3],   aph[g][1], apl[g][1]);
            split2h(s[2*g+1][0], s[2*g+1][1], aph[g][2], apl[g][2]);
            split2h(s[2*g+1][2], s[2*g+1][3], aph[g][3], apl[g][3]);
        }

        // ---- O += (Ph+Pl) V ----
        const int vrow0 = (lane & 15);
        const uint32_t vcadd = (uint32_t)((lane >> 4) << 4);
        #pragma unroll
        for (int dtp = 0; dtp < 8; dtp++) {
            const uint32_t vcol = (uint32_t)((dtp&3)*32) + vcadd;
            #pragma unroll
            for (int g = 0; g < 4; g++) {
                const uint32_t voff = (dtp>>2)*8192 + SWZ((g*16 + vrow0)*128 + vcol);
                uint32_t vb4[4];
                ldsm4t(VB + voff, vb4);
                mma16816(o[2*dtp],   aph[g], &vb4[0]);
                mma16816(o[2*dtp],   apl[g], &vb4[0]);
                mma16816(o[2*dtp+1], aph[g], &vb4[2]);
                mma16816(o[2*dtp+1], apl[g], &vb4[2]);
            }
        }

        if (kt + 1 < nkv) {
            CP_WAIT0();
            __syncthreads();
        }
    }

    // ---- epilogue: normalize, split fp16 hi/lo, write [B, L, H*128] ----
    const float inv0 = 1.f / lr0, inv1 = 1.f / lr1;
    const size_t row0 = ((size_t)(b*SEQ + rg0)) * D_MODEL + h*HDIM;
    const size_t row1 = row0 + 8 * D_MODEL;
    #pragma unroll
    for (int t = 0; t < 16; t++) {
        const int d = t*8 + 2*(lane & 3);
        uint32_t hi, lo;
        split2h(o[t][0]*inv0, o[t][1]*inv0, hi, lo);
        *(uint32_t*)&g_ah[row0 + d] = hi;
        *(uint32_t*)&g_al[row0 + d] = lo;
        split2h(o[t][2]*inv1, o[t][3]*inv1, hi, lo);
        *(uint32_t*)&g_ah[row1 + d] = hi;
        *(uint32_t*)&g_al[row1 + d] = lo;
    }
}

// ---------------------------------------------------------------------------
extern "C" void kernel_launch(void* const* d_in, const int* in_sizes, int n_in,
                              void* d_out, int out_size)
{
    const float* query = (const float*)d_in[0];
    const float* W_qkv = (const float*)d_in[1];
    const float* b_qkv = (const float*)d_in[2];
    const float* W_out = (const float*)d_in[3];
    const float* b_out = (const float*)d_in[4];
    float* out = (float*)d_out;

    void *p_qh, *p_ql, *p_w, *p_o, *p_ah, *p_al;
    cudaGetSymbolAddress(&p_qh, g_qh);  cudaGetSymbolAddress(&p_ql, g_ql);
    cudaGetSymbolAddress(&p_w, g_w);    cudaGetSymbolAddress(&p_o, g_o);
    cudaGetSymbolAddress(&p_ah, g_ah);  cudaGetSymbolAddress(&p_al, g_al);

    const int GEMM_SMEM = 1024 + 3*24576;       // 3-stage K32 pipeline (2 CTAs/SM)
    cudaFuncSetAttribute(tc_gemm<0>, cudaFuncAttributeMaxDynamicSharedMemorySize, GEMM_SMEM);
    cudaFuncSetAttribute(tc_gemm<1>, cudaFuncAttributeMaxDynamicSharedMemorySize, GEMM_SMEM);
    const int ATTN_SMEM = 1024 + 65536 + 2*32768;   // Q 64KB + 2 KV bufs
    cudaFuncSetAttribute(attn_kernel, cudaFuncAttributeMaxDynamicSharedMemorySize, ATTN_SMEM);

    // 0) rope tables (must precede QKV epilogue)
    rope_table_kernel<<<(SEQ*64)/256, 256>>>();

    // 1) prepare fp16 operands
    {
        int n;
        n = MROWS*D_MODEL;
        splith_kernel<<<n/1024, 256>>>(query, (__half*)p_qh, (__half*)p_ql, n);
        n = 3*D_MODEL*D_MODEL;
        cvth_kernel<<<n/1024, 256>>>(W_qkv, (__half*)p_w, n);
        n = D_MODEL*D_MODEL;
        cvth_kernel<<<n/1024, 256>>>(W_out, (__half*)p_o, n);
    }

    // 2) QKV projection (fp16 HMMA, 2 products) with fused rope epilogue
    tc_gemm<1><<<dim3(3*D_MODEL/128, MROWS/128), 256, GEMM_SMEM>>>(
        (const __half*)p_qh, (const __half*)p_ql, (const __half*)p_w,
        b_qkv, nullptr, 3*D_MODEL, D_MODEL);

    // 3) causal flash attention -> g_ah/g_al
    attn_kernel<<<dim3(SEQ/128, NHEAD, BATCH), 256, ATTN_SMEM>>>();

    // 4) Output projection -> d_out
    tc_gemm<0><<<dim3(D_MODEL/128, MROWS/128), 256, GEMM_SMEM>>>(
        (const __half*)p_ah, (const __half*)p_al, (const __half*)p_o,
        b_out, out, D_MODEL, D_MODEL);
}

// round 13
// speedup vs baseline: 1.4627x; 1.0299x over previous
#include <cuda_runtime.h>
#include <cuda_fp16.h>
#include <math.h>
#include <stdint.h>

#define D_MODEL 2048
#define NHEAD   16
#define HDIM    128
#define BATCH   2
#define SEQ     2048
#define MROWS   (BATCH*SEQ)   // 4096

// ---------------- device scratch (no runtime allocation) ----------------
__device__ __half g_qbh[(size_t)BATCH*NHEAD*SEQ*HDIM];  // roped+scaled Q hi/lo (fp16)
__device__ __half g_qbl[(size_t)BATCH*NHEAD*SEQ*HDIM];
__device__ __half g_kb [(size_t)BATCH*NHEAD*SEQ*HDIM];  // roped K (single fp16)
__device__ __half g_vb [(size_t)BATCH*NHEAD*SEQ*HDIM];  // V (single fp16)

__device__ __half g_qh[(size_t)MROWS*D_MODEL];          // query hi/lo (GEMM A)
__device__ __half g_ql[(size_t)MROWS*D_MODEL];
__device__ __half g_w [(size_t)3*D_MODEL*D_MODEL];      // W_qkv (single fp16)
__device__ __half g_o [(size_t)D_MODEL*D_MODEL];        // W_out (single fp16)
__device__ __half g_ah[(size_t)MROWS*D_MODEL];          // attn-out hi/lo
__device__ __half g_al[(size_t)MROWS*D_MODEL];

__device__ float g_cos[(size_t)SEQ*64];                 // rope tables
__device__ float g_sin[(size_t)SEQ*64];

// ---------------- helpers ----------------
__device__ __forceinline__ uint32_t smem_u32(const void* p) {
    uint32_t a;
    asm("{ .reg .u64 t; cvta.to.shared.u64 t, %1; cvt.u32.u64 %0, t; }" : "=r"(a) : "l"(p));
    return a;
}
#define SWZ(o) ((o) ^ (((o) >> 3) & 0x70))

__device__ __forceinline__ void ldsm4(uint32_t addr, uint32_t* r) {
    asm volatile("ldmatrix.sync.aligned.m8n8.x4.shared.b16 {%0,%1,%2,%3}, [%4];"
                 : "=r"(r[0]), "=r"(r[1]), "=r"(r[2]), "=r"(r[3]) : "r"(addr));
}
__device__ __forceinline__ void ldsm4t(uint32_t addr, uint32_t* r) {
    asm volatile("ldmatrix.sync.aligned.m8n8.x4.trans.shared.b16 {%0,%1,%2,%3}, [%4];"
                 : "=r"(r[0]), "=r"(r[1]), "=r"(r[2]), "=r"(r[3]) : "r"(addr));
}
__device__ __forceinline__ void mma16816(float* c, const uint32_t* a, const uint32_t* b) {
    asm volatile(
        "mma.sync.aligned.m16n8k16.row.col.f32.f16.f16.f32 "
        "{%0,%1,%2,%3}, {%4,%5,%6,%7}, {%8,%9}, {%0,%1,%2,%3};"
        : "+f"(c[0]), "+f"(c[1]), "+f"(c[2]), "+f"(c[3])
        : "r"(a[0]), "r"(a[1]), "r"(a[2]), "r"(a[3]), "r"(b[0]), "r"(b[1]));
}
#define CP16(dst, src) \
    asm volatile("cp.async.cg.shared.global [%0], [%1], 16;" :: "r"(dst), "l"(src))
#define CP_COMMIT() asm volatile("cp.async.commit_group;" ::: "memory")
#define CP_WAIT0()  asm volatile("cp.async.wait_group 0;" ::: "memory")
#define CP_WAIT1()  asm volatile("cp.async.wait_group 1;" ::: "memory")

// split pair of fp32 into packed fp16x2 hi and lo (residual)
__device__ __forceinline__ void split2h(float x, float y, uint32_t& hi, uint32_t& lo) {
    __half hx = __float2half_rn(x), hy = __float2half_rn(y);
    float rx = x - __half2float(hx), ry = y - __half2float(hy);
    __half lx = __float2half_rn(rx), ly = __float2half_rn(ry);
    hi = ((uint32_t)__half_as_ushort(hy) << 16) | __half_as_ushort(hx);
    lo = ((uint32_t)__half_as_ushort(ly) << 16) | __half_as_ushort(lx);
}
__device__ __forceinline__ uint32_t pack2h(float x, float y) {
    __half hx = __float2half_rn(x), hy = __float2half_rn(y);
    return ((uint32_t)__half_as_ushort(hy) << 16) | __half_as_ushort(hx);
}

// ---------------------------------------------------------------------------
// fp32 -> fp16 hi/lo split, and fp32 -> fp16 single convert
// ---------------------------------------------------------------------------
__global__ void splith_kernel(const float* __restrict__ x,
                              __half* __restrict__ hi,
                              __half* __restrict__ lo, int n)
{
    int i = (blockIdx.x * 256 + threadIdx.x) * 4;
    if (i >= n) return;
    float4 v = *(const float4*)(x + i);
    uint32_t h0, l0, h1, l1;
    split2h(v.x, v.y, h0, l0);
    split2h(v.z, v.w, h1, l1);
    *(uint2*)(hi + i) = make_uint2(h0, h1);
    *(uint2*)(lo + i) = make_uint2(l0, l1);
}
__global__ void cvth_kernel(const float* __restrict__ x,
                            __half* __restrict__ y, int n)
{
    int i = (blockIdx.x * 256 + threadIdx.x) * 4;
    if (i >= n) return;
    float4 v = *(const float4*)(x + i);
    *(uint2*)(y + i) = make_uint2(pack2h(v.x, v.y), pack2h(v.z, v.w));
}

// ---------------------------------------------------------------------------
// RoPE cos/sin table (double-precision range reduction, robust to fast-math)
// ---------------------------------------------------------------------------
__global__ void rope_table_kernel()
{
    int idx = blockIdx.x * 256 + threadIdx.x;       // SEQ*64 threads
    int l = idx >> 6, d = idx & 63;
    double invf = exp2(-(double)d * (13.287712379549449 / 64.0)); // 10000^(-d/64)
    double t    = fmod((double)l * invf, 6.283185307179586476925286766559);
    g_cos[idx] = cosf((float)t);
    g_sin[idx] = sinf((float)t);
}

// ---------------------------------------------------------------------------
// HMMA GEMM (fp16, 2 products): C = (Ah+Al)*B^T + bias, fp32 accum.
// Unchanged from round 12 (passing, 2 CTAs/SM).
// ---------------------------------------------------------------------------
__device__ __forceinline__ void load_chunk_async(
    const __half* __restrict__ a0, const __half* __restrict__ a1,
    const __half* __restrict__ b, int K, int k0, uint32_t dst)
{
    const __half* s[2] = {a0, a1};
    #pragma unroll
    for (int t = 0; t < 2; t++) {
        const __half* p = s[t] + k0;
        #pragma unroll
        for (int it = 0; it < 2; it++) {
            int i = threadIdx.x + it * 256;     // 0..511
            int r = i >> 2, c = i & 3;
            CP16(dst + SWZ(r * 128 + t * 64 + c * 16), p + (size_t)r * K + c * 8);
        }
    }
    const __half* pb = b + k0;
    #pragma unroll
    for (int it = 0; it < 2; it++) {
        int i = threadIdx.x + it * 256;         // 0..511
        int r = i >> 2, c = i & 3;              // r = N row 0..127
        CP16(dst + 16384 + SWZ((r & 63) * 128 + ((r >> 6) << 6) + c * 16),
             pb + (size_t)r * K + c * 8);
    }
}

template<int MODE>
__global__ __launch_bounds__(256, 2)
void tc_gemm(const __half* __restrict__ Ah, const __half* __restrict__ Al,
             const __half* __restrict__ B,
             const float* __restrict__ bias, float* __restrict__ C, int N, int K)
{
    extern __shared__ char smem[];
    char* smp = (char*)(((uintptr_t)smem + 1023) & ~(uintptr_t)1023);
    const uint32_t bufs = smem_u32(smp);

    const int tid  = threadIdx.x;
    const int lane = tid & 31;
    const int wid  = tid >> 5;
    const int wr   = wid >> 2;
    const int wc   = wid & 3;
    const int m0   = blockIdx.y << 7;
    const int n0   = blockIdx.x << 7;
    const int KCHUNKS = K >> 5;

    const __half* Ahp = Ah + (size_t)m0 * K;
    const __half* Alp = Al + (size_t)m0 * K;
    const __half* Bp  = B  + (size_t)n0 * K;

    float acc[4][4][4];
    #pragma unroll
    for (int i = 0; i < 4; i++)
        #pragma unroll
        for (int j = 0; j < 4; j++)
            #pragma unroll
            for (int r = 0; r < 4; r++) acc[i][j][r] = 0.f;

    const int      arow = lane & 15;
    const uint32_t adk  = (lane >> 4) << 4;
    const int      brow = (lane & 7) + ((lane >> 4) << 3);
    const uint32_t bdk  = ((lane >> 3) & 1) << 4;

    load_chunk_async(Ahp, Alp, Bp, K, 0,  bufs);
    CP_COMMIT();
    load_chunk_async(Ahp, Alp, Bp, K, 32, bufs + 24576);
    CP_COMMIT();
    CP_WAIT1();
    __syncthreads();

    for (int c = 0; c < KCHUNKS; c++) {
        if (c + 2 < KCHUNKS) {
            load_chunk_async(Ahp, Alp, Bp, K, (c + 2) << 5,
                             bufs + ((c + 2) % 3) * 24576);
            CP_COMMIT();
        }

        const uint32_t bA = bufs + (c % 3) * 24576;
        const uint32_t bB = bA + 16384;

        #pragma unroll
        for (int ks = 0; ks < 2; ks++) {
            const uint32_t kbA = (uint32_t)ks * 32 + adk;
            const uint32_t kbB = (uint32_t)ks * 32 + bdk;

            uint32_t ah[4][4], al[4][4], bx[2][4];
            #pragma unroll
            for (int mt = 0; mt < 4; mt++) {
                const uint32_t rw = (uint32_t)(wr*64 + mt*16 + arow) * 128;
                ldsm4(bA + SWZ(rw + kbA), ah[mt]);
                ldsm4(bA + SWZ(rw + 64 + kbA), al[mt]);
            }
            #pragma unroll
            for (int np = 0; np < 2; np++) {
                const int rw = wc*32 + np*16 + brow;
                ldsm4(bB + SWZ((uint32_t)(rw & 63) * 128 + (uint32_t)((rw >> 6) << 6) + kbB),
                      bx[np]);
            }
            #pragma unroll
            for (int mt = 0; mt < 4; mt++)
                #pragma unroll
                for (int nt = 0; nt < 4; nt++) {
                    const uint32_t* b2 = &bx[nt >> 1][(nt & 1) * 2];
                    mma16816(acc[mt][nt], ah[mt], b2);
                    mma16816(acc[mt][nt], al[mt], b2);
                }
        }

        if (c + 1 < KCHUNKS) {
            if (c + 2 < KCHUNKS) CP_WAIT1(); else CP_WAIT0();
            __syncthreads();
        }
    }

    if (MODE == 0) {
        #pragma unroll
        for (int mt = 0; mt < 4; mt++) {
            const int mrow = m0 + wr*64 + mt*16 + (lane >> 2);
            #pragma unroll
            for (int nt = 0; nt < 4; nt++) {
                const int cg = n0 + wc*32 + nt*8 + (lane & 3)*2;
                const float bx2 = bias[cg], by = bias[cg + 1];
                *(float2*)&C[(size_t)mrow * N + cg] =
                    make_float2(acc[mt][nt][0] + bx2, acc[mt][nt][1] + by);
                *(float2*)&C[(size_t)(mrow + 8) * N + cg] =
                    make_float2(acc[mt][nt][2] + bx2, acc[mt][nt][3] + by);
            }
        }
        return;
    }

    // ---------------- MODE 1 epilogue: stage -> rope/convert -> scatter -----
    float* st = (float*)smp;                 // 128 x 132 fp32
    const int PITCH = 132;
    __syncthreads();
    #pragma unroll
    for (int mt = 0; mt < 4; mt++) {
        const int r0 = wr*64 + mt*16 + (lane >> 2);
        #pragma unroll
        for (int nt = 0; nt < 4; nt++) {
            const int cl = wc*32 + nt*8 + (lane & 3)*2;
            const float bx2 = bias[n0 + cl], by = bias[n0 + cl + 1];
            *(float2*)&st[r0*PITCH + cl] =
                make_float2(acc[mt][nt][0] + bx2, acc[mt][nt][1] + by);
            *(float2*)&st[(r0 + 8)*PITCH + cl] =
                make_float2(acc[mt][nt][2] + bx2, acc[mt][nt][3] + by);
        }
    }
    __syncthreads();

    const int which = n0 >> 11;              // 0=q 1=k 2=v
    const int h     = (n0 >> 7) & 15;
    const int row   = tid >> 1;
    const int half  = tid & 1;
    const int m     = m0 + row;
    const int bb    = m >> 11;
    const int l     = m & (SEQ - 1);
    const size_t obase = (((size_t)(bb*NHEAD + h))*SEQ + l)*HDIM;
    const float* srow = st + row * PITCH;
    const int d0 = half * 32;

    if (which == 2) {
        uint32_t h1[16], h2[16];
        #pragma unroll
        for (int j = 0; j < 16; j++) {
            h1[j] = pack2h(srow[d0 + 2*j],      srow[d0 + 2*j + 1]);
            h2[j] = pack2h(srow[d0 + 64 + 2*j], srow[d0 + 64 + 2*j + 1]);
        }
        #pragma unroll
        for (int j = 0; j < 4; j++) {
            *(uint4*)&g_vb[obase + d0 + j*8]      = ((uint4*)h1)[j];
            *(uint4*)&g_vb[obase + d0 + 64 + j*8] = ((uint4*)h2)[j];
        }
    } else {
        const float qs = (which == 0) ? 0.08838834764831845f : 1.0f;
        const float* ct  = g_cos + (size_t)l * 64;
        const float* stb = g_sin + (size_t)l * 64;
        if (which == 0) {
            uint32_t h1[16], l1[16], h2[16], l2[16];
            #pragma unroll
            for (int j = 0; j < 16; j++) {
                const int d = d0 + 2*j;
                float2 cc = *(const float2*)&ct[d];
                float2 ss = *(const float2*)&stb[d];
                float x1a = srow[d],      x1b = srow[d + 1];
                float x2a = srow[d + 64], x2b = srow[d + 65];
                split2h((x1a*cc.x - x2a*ss.x)*qs, (x1b*cc.y - x2b*ss.y)*qs, h1[j], l1[j]);
                split2h((x2a*cc.x + x1a*ss.x)*qs, (x2b*cc.y + x1b*ss.y)*qs, h2[j], l2[j]);
            }
            #pragma unroll
            for (int j = 0; j < 4; j++) {
                *(uint4*)&g_qbh[obase + d0 + j*8]      = ((uint4*)h1)[j];
                *(uint4*)&g_qbl[obase + d0 + j*8]      = ((uint4*)l1)[j];
                *(uint4*)&g_qbh[obase + d0 + 64 + j*8] = ((uint4*)h2)[j];
                *(uint4*)&g_qbl[obase + d0 + 64 + j*8] = ((uint4*)l2)[j];
            }
        } else {
            uint32_t h1[16], h2[16];
            #pragma unroll
            for (int j = 0; j < 16; j++) {
                const int d = d0 + 2*j;
                float2 cc = *(const float2*)&ct[d];
                float2 ss = *(const float2*)&stb[d];
                float x1a = srow[d],      x1b = srow[d + 1];
                float x2a = srow[d + 64], x2b = srow[d + 65];
                h1[j] = pack2h(x1a*cc.x - x2a*ss.x, x1b*cc.y - x2b*ss.y);
                h2[j] = pack2h(x2a*cc.x + x1a*ss.x, x2b*cc.y + x1b*ss.y);
            }
            #pragma unroll
            for (int j = 0; j < 4; j++) {
                *(uint4*)&g_kb[obase + d0 + j*8]      = ((uint4*)h1)[j];
                *(uint4*)&g_kb[obase + d0 + 64 + j*8] = ((uint4*)h2)[j];
            }
        }
    }
}

// ---------------------------------------------------------------------------
// HMMA causal flash attention (fp16, 2 products).
// BQ=64, 4 warps (16 q-rows each), 2 CTAs/SM -> cross-CTA overlap hides
// softmax. Q hi/lo 32KB + double-buffered KV 2x32KB = 97KB smem.
// ---------------------------------------------------------------------------
__global__ __launch_bounds__(128, 2)
void attn_kernel()
{
    extern __shared__ char sm[];
    const uint32_t base = (smem_u32(sm) + 1023) & ~1023u;
    const uint32_t QH = base;                 // 2 panels x 8KB (dims 0-63, 64-127)
    const uint32_t QL = base + 16384;
    const uint32_t KV = base + 32768;         // buf b at +b*32768 (K 16KB, V 16KB)

    const int tid  = threadIdx.x;
    const int lane = tid & 31;
    const int wid  = tid >> 5;                // 0..3
    const int qt   = (int)gridDim.x - 1 - (int)blockIdx.x;  // heavy tiles first
    const int h    = blockIdx.y;
    const int b    = blockIdx.z;
    const int bh   = b*NHEAD + h;
    const int q0   = qt << 6;
    const int nkv  = qt + 1;

    const size_t hoff = (size_t)bh * SEQ * HDIM;
    const __half* qbh = g_qbh + hoff + (size_t)q0 * HDIM;
    const __half* qbl = g_qbl + hoff + (size_t)q0 * HDIM;
    const __half* kb  = g_kb + hoff;
    const __half* vb  = g_vb + hoff;

    // ---- Q load (64 rows x 16 units per array) ----
    #pragma unroll
    for (int it = 0; it < 8; it++) {
        int i = tid + it * 128;               // 0..1023
        int row = i >> 4, u = i & 15;
        uint32_t off = (u >> 3) * 8192 + SWZ(row * 128 + (u & 7) * 16);
        CP16(QH + off, qbh + (size_t)row * HDIM + u * 8);
        CP16(QL + off, qbl + (size_t)row * HDIM + u * 8);
    }
    // ---- KV block 0 ----
    {
        const __half* arr[2] = {kb, vb};
        #pragma unroll
        for (int t = 0; t < 2; t++)
            #pragma unroll
            for (int it = 0; it < 8; it++) {
                int i = tid + it * 128;       // 0..1023
                int row = i >> 4, u = i & 15;
                uint32_t d = KV + t*16384 + (u>>3)*8192 + SWZ(row*128 + (u&7)*16);
                CP16(d, arr[t] + (size_t)row * HDIM + u * 8);
            }
    }
    CP_COMMIT();
    CP_WAIT0();
    __syncthreads();

    float mr0 = -1e30f, mr1 = -1e30f, lr0 = 0.f, lr1 = 0.f;
    float o[16][4];
    #pragma unroll
    for (int t = 0; t < 16; t++)
        #pragma unroll
        for (int j = 0; j < 4; j++) o[t][j] = 0.f;

    const int rloc0 = wid*16 + (lane >> 2);   // 0..63
    const int rg0   = q0 + rloc0;

    for (int kt = 0; kt < nkv; kt++) {
        const uint32_t KB = KV + (kt & 1) * 32768;
        const uint32_t VB = KB + 16384;

        if (kt + 1 < nkv) {
            const __half* arr[2] = {kb, vb};
            const size_t s0 = (size_t)(kt + 1) * 64 * HDIM;
            const uint32_t nb = KV + ((kt + 1) & 1) * 32768;
            #pragma unroll
            for (int t = 0; t < 2; t++)
                #pragma unroll
                for (int it = 0; it < 8; it++) {
                    int i = tid + it * 128;
                    int row = i >> 4, u = i & 15;
                    uint32_t d = nb + t*16384 + (u>>3)*8192 + SWZ(row*128 + (u&7)*16);
                    CP16(d, arr[t] + s0 + (size_t)row * HDIM + u * 8);
                }
            CP_COMMIT();
        }

        // ---- S = (Qh+Ql) K^T ----
        float s[8][4];
        #pragma unroll
        for (int t = 0; t < 8; t++)
            #pragma unroll
            for (int j = 0; j < 4; j++) s[t][j] = 0.f;

        #pragma unroll
        for (int ks = 0; ks < 8; ks++) {
            const int arow = wid*16 + (lane & 15);
            const uint32_t aoff = (ks>>2)*8192
                + SWZ(arow*128 + (ks&3)*32 + ((lane>>4)<<4));
            uint32_t qa[4], qla[4];
            ldsm4(QH + aoff, qa);
            ldsm4(QL + aoff, qla);

            const int krow0 = (lane & 7) + ((lane >> 4) << 3);
            const uint32_t kcol = (uint32_t)((ks&3)*32 + (((lane>>3)&1)<<4));
            #pragma unroll
            for (int ntp = 0; ntp < 4; ntp++) {
                const uint32_t koff = (ks>>2)*8192 + SWZ((ntp*16 + krow0)*128 + kcol);
                uint32_t kb4[4];
                ldsm4(KB + koff, kb4);
                mma16816(s[2*ntp],   qa,  &kb4[0]);
                mma16816(s[2*ntp],   qla, &kb4[0]);
                mma16816(s[2*ntp+1], qa,  &kb4[2]);
                mma16816(s[2*ntp+1], qla, &kb4[2]);
            }
        }

        // ---- causal mask (diagonal block only) ----
        if (kt >= qt) {
            #pragma unroll
            for (int t = 0; t < 8; t++) {
                #pragma unroll
                for (int j = 0; j < 2; j++) {
                    const int n = kt*64 + t*8 + 2*(lane & 3) + j;
                    if (n > rg0)     s[t][j]   = -1e30f;
                    if (n > rg0 + 8) s[t][2+j] = -1e30f;
                }
            }
        }

        float rm0 = -1e30f, rm1 = -1e30f;
        #pragma unroll
        for (int t = 0; t < 8; t++) {
            rm0 = fmaxf(rm0, fmaxf(s[t][0], s[t][1]));
            rm1 = fmaxf(rm1, fmaxf(s[t][2], s[t][3]));
        }
        rm0 = fmaxf(rm0, __shfl_xor_sync(0xffffffffu, rm0, 1));
        rm0 = fmaxf(rm0, __shfl_xor_sync(0xffffffffu, rm0, 2));
        rm1 = fmaxf(rm1, __shfl_xor_sync(0xffffffffu, rm1, 1));
        rm1 = fmaxf(rm1, __shfl_xor_sync(0xffffffffu, rm1, 2));

        const float mn0 = fmaxf(mr0, rm0), mn1 = fmaxf(mr1, rm1);
        const float sf0 = __expf(mr0 - mn0), sf1 = __expf(mr1 - mn1);
        mr0 = mn0; mr1 = mn1;

        float rs0 = 0.f, rs1 = 0.f;
        #pragma unroll
        for (int t = 0; t < 8; t++) {
            s[t][0] = __expf(s[t][0] - mn0);
            s[t][1] = __expf(s[t][1] - mn0);
            s[t][2] = __expf(s[t][2] - mn1);
            s[t][3] = __expf(s[t][3] - mn1);
            rs0 += s[t][0] + s[t][1];
            rs1 += s[t][2] + s[t][3];
        }
        rs0 += __shfl_xor_sync(0xffffffffu, rs0, 1);
        rs0 += __shfl_xor_sync(0xffffffffu, rs0, 2);
        rs1 += __shfl_xor_sync(0xffffffffu, rs1, 1);
        rs1 += __shfl_xor_sync(0xffffffffu, rs1, 2);
        lr0 = lr0 * sf0 + rs0;
        lr1 = lr1 * sf1 + rs1;

        #pragma unroll
        for (int t = 0; t < 16; t++) {
            o[t][0] *= sf0; o[t][1] *= sf0;
            o[t][2] *= sf1; o[t][3] *= sf1;
        }

        // ---- P split (fp16 hi/lo) into A-fragments ----
        uint32_t aph[4][4], apl[4][4];
        #pragma unroll
        for (int g = 0; g < 4; g++) {
            split2h(s[2*g][0],   s[2*g][1],   aph[g][0], apl[g][0]);
            split2h(s[2*g][2],   s[2*g][3],   aph[g][1], apl[g][1]);
            split2h(s[2*g+1][0], s[2*g+1][1], aph[g][2], apl[g][2]);
            split2h(s[2*g+1][2], s[2*g+1][3], aph[g][3], apl[g][3]);
        }

        // ---- O += (Ph+Pl) V ----
        const int vrow0 = (lane & 15);
        const uint32_t vcadd = (uint32_t)((lane >> 4) << 4);
        #pragma unroll
        for (int dtp = 0; dtp < 8; dtp++) {
            const uint32_t vcol = (uint32_t)((dtp&3)*32) + vcadd;
            #pragma unroll
            for (int g = 0; g < 4; g++) {
                const uint32_t voff = (dtp>>2)*8192 + SWZ((g*16 + vrow0)*128 + vcol);
                uint32_t vb4[4];
                ldsm4t(VB + voff, vb4);
                mma16816(o[2*dtp],   aph[g], &vb4[0]);
                mma16816(o[2*dtp],   apl[g], &vb4[0]);
                mma16816(o[2*dtp+1], aph[g], &vb4[2]);
                mma16816(o[2*dtp+1], apl[g], &vb4[2]);
            }
        }

        if (kt + 1 < nkv) {
            CP_WAIT0();
            __syncthreads();
        }
    }

    // ---- epilogue: normalize, split fp16 hi/lo, write [B, L, H*128] ----
    const float inv0 = 1.f / lr0, inv1 = 1.f / lr1;
    const size_t row0 = ((size_t)(b*SEQ + rg0)) * D_MODEL + h*HDIM;
    const size_t row1 = row0 + 8 * D_MODEL;
    #pragma unroll
    for (int t = 0; t < 16; t++) {
        const int d = t*8 + 2*(lane & 3);
        uint32_t hi, lo;
        split2h(o[t][0]*inv0, o[t][1]*inv0, hi, lo);
        *(uint32_t*)&g_ah[row0 + d] = hi;
        *(uint32_t*)&g_al[row0 + d] = lo;
        split2h(o[t][2]*inv1, o[t][3]*inv1, hi, lo);
        *(uint32_t*)&g_ah[row1 + d] = hi;
        *(uint32_t*)&g_al[row1 + d] = lo;
    }
}

// ---------------------------------------------------------------------------
extern "C" void kernel_launch(void* const* d_in, const int* in_sizes, int n_in,
                              void* d_out, int out_size)
{
    const float* query = (const float*)d_in[0];
    const float* W_qkv = (const float*)d_in[1];
    const float* b_qkv = (const float*)d_in[2];
    const float* W_out = (const float*)d_in[3];
    const float* b_out = (const float*)d_in[4];
    float* out = (float*)d_out;

    void *p_qh, *p_ql, *p_w, *p_o, *p_ah, *p_al;
    cudaGetSymbolAddress(&p_qh, g_qh);  cudaGetSymbolAddress(&p_ql, g_ql);
    cudaGetSymbolAddress(&p_w, g_w);    cudaGetSymbolAddress(&p_o, g_o);
    cudaGetSymbolAddress(&p_ah, g_ah);  cudaGetSymbolAddress(&p_al, g_al);

    const int GEMM_SMEM = 1024 + 3*24576;       // 3-stage K32 pipeline (2 CTAs/SM)
    cudaFuncSetAttribute(tc_gemm<0>, cudaFuncAttributeMaxDynamicSharedMemorySize, GEMM_SMEM);
    cudaFuncSetAttribute(tc_gemm<1>, cudaFuncAttributeMaxDynamicSharedMemorySize, GEMM_SMEM);
    const int ATTN_SMEM = 1024 + 32768 + 2*32768;   // Q 32KB + 2 KV bufs (2 CTAs/SM)
    cudaFuncSetAttribute(attn_kernel, cudaFuncAttributeMaxDynamicSharedMemorySize, ATTN_SMEM);

    // 0) rope tables (must precede QKV epilogue)
    rope_table_kernel<<<(SEQ*64)/256, 256>>>();

    // 1) prepare fp16 operands
    {
        int n;
        n = MROWS*D_MODEL;
        splith_kernel<<<n/1024, 256>>>(query, (__half*)p_qh, (__half*)p_ql, n);
        n = 3*D_MODEL*D_MODEL;
        cvth_kernel<<<n/1024, 256>>>(W_qkv, (__half*)p_w, n);
        n = D_MODEL*D_MODEL;
        cvth_kernel<<<n/1024, 256>>>(W_out, (__half*)p_o, n);
    }

    // 2) QKV projection (fp16 HMMA, 2 products) with fused rope epilogue
    tc_gemm<1><<<dim3(3*D_MODEL/128, MROWS/128), 256, GEMM_SMEM>>>(
        (const __half*)p_qh, (const __half*)p_ql, (const __half*)p_w,
        b_qkv, nullptr, 3*D_MODEL, D_MODEL);

    // 3) causal flash attention (BQ=64, 2 CTAs/SM) -> g_ah/g_al
    attn_kernel<<<dim3(SEQ/64, NHEAD, BATCH), 128, ATTN_SMEM>>>();

    // 4) Output projection -> d_out
    tc_gemm<0><<<dim3(D_MODEL/128, MROWS/128), 256, GEMM_SMEM>>>(
        (const __half*)p_ah, (const __half*)p_al, (const __half*)p_o,
        b_out, out, D_MODEL, D_MODEL);
}

// round 14
// speedup vs baseline: 1.5192x; 1.0387x over previous
#include <cuda_runtime.h>
#include <cuda_fp16.h>
#include <math.h>
#include <stdint.h>

#define D_MODEL 2048
#define NHEAD   16
#define HDIM    128
#define BATCH   2
#define SEQ     2048
#define MROWS   (BATCH*SEQ)   // 4096

// ---------------- device scratch (no runtime allocation) ----------------
__device__ __half g_qbh[(size_t)BATCH*NHEAD*SEQ*HDIM];  // roped+scaled Q hi/lo (fp16)
__device__ __half g_qbl[(size_t)BATCH*NHEAD*SEQ*HDIM];
__device__ __half g_kb [(size_t)BATCH*NHEAD*SEQ*HDIM];  // roped K (single fp16)
__device__ __half g_vb [(size_t)BATCH*NHEAD*SEQ*HDIM];  // V (single fp16)

__device__ __half g_qh[(size_t)MROWS*D_MODEL];          // query hi/lo (GEMM A)
__device__ __half g_ql[(size_t)MROWS*D_MODEL];
__device__ __half g_w [(size_t)3*D_MODEL*D_MODEL];      // W_qkv (single fp16)
__device__ __half g_o [(size_t)D_MODEL*D_MODEL];        // W_out (single fp16)
__device__ __half g_ah[(size_t)MROWS*D_MODEL];          // attn-out hi/lo
__device__ __half g_al[(size_t)MROWS*D_MODEL];

__device__ float g_cos[(size_t)SEQ*64];                 // rope tables
__device__ float g_sin[(size_t)SEQ*64];

// ---------------- helpers ----------------
__device__ __forceinline__ uint32_t smem_u32(const void* p) {
    uint32_t a;
    asm("{ .reg .u64 t; cvta.to.shared.u64 t, %1; cvt.u32.u64 %0, t; }" : "=r"(a) : "l"(p));
    return a;
}
#define SWZ(o) ((o) ^ (((o) >> 3) & 0x70))

__device__ __forceinline__ void ldsm4(uint32_t addr, uint32_t* r) {
    asm volatile("ldmatrix.sync.aligned.m8n8.x4.shared.b16 {%0,%1,%2,%3}, [%4];"
                 : "=r"(r[0]), "=r"(r[1]), "=r"(r[2]), "=r"(r[3]) : "r"(addr));
}
__device__ __forceinline__ void ldsm4t(uint32_t addr, uint32_t* r) {
    asm volatile("ldmatrix.sync.aligned.m8n8.x4.trans.shared.b16 {%0,%1,%2,%3}, [%4];"
                 : "=r"(r[0]), "=r"(r[1]), "=r"(r[2]), "=r"(r[3]) : "r"(addr));
}
__device__ __forceinline__ void mma16816(float* c, const uint32_t* a, const uint32_t* b) {
    asm volatile(
        "mma.sync.aligned.m16n8k16.row.col.f32.f16.f16.f32 "
        "{%0,%1,%2,%3}, {%4,%5,%6,%7}, {%8,%9}, {%0,%1,%2,%3};"
        : "+f"(c[0]), "+f"(c[1]), "+f"(c[2]), "+f"(c[3])
        : "r"(a[0]), "r"(a[1]), "r"(a[2]), "r"(a[3]), "r"(b[0]), "r"(b[1]));
}
#define CP16(dst, src) \
    asm volatile("cp.async.cg.shared.global [%0], [%1], 16;" :: "r"(dst), "l"(src))
#define CP_COMMIT() asm volatile("cp.async.commit_group;" ::: "memory")
#define CP_WAIT0()  asm volatile("cp.async.wait_group 0;" ::: "memory")
#define CP_WAIT1()  asm volatile("cp.async.wait_group 1;" ::: "memory")

// split pair of fp32 into packed fp16x2 hi and lo (residual)
__device__ __forceinline__ void split2h(float x, float y, uint32_t& hi, uint32_t& lo) {
    __half hx = __float2half_rn(x), hy = __float2half_rn(y);
    float rx = x - __half2float(hx), ry = y - __half2float(hy);
    __half lx = __float2half_rn(rx), ly = __float2half_rn(ry);
    hi = ((uint32_t)__half_as_ushort(hy) << 16) | __half_as_ushort(hx);
    lo = ((uint32_t)__half_as_ushort(ly) << 16) | __half_as_ushort(lx);
}
__device__ __forceinline__ uint32_t pack2h(float x, float y) {
    __half hx = __float2half_rn(x), hy = __float2half_rn(y);
    return ((uint32_t)__half_as_ushort(hy) << 16) | __half_as_ushort(hx);
}

// ---------------------------------------------------------------------------
// fp32 -> fp16 hi/lo split, and fp32 -> fp16 single convert
// ---------------------------------------------------------------------------
__global__ void splith_kernel(const float* __restrict__ x,
                              __half* __restrict__ hi,
                              __half* __restrict__ lo, int n)
{
    int i = (blockIdx.x * 256 + threadIdx.x) * 4;
    if (i >= n) return;
    float4 v = *(const float4*)(x + i);
    uint32_t h0, l0, h1, l1;
    split2h(v.x, v.y, h0, l0);
    split2h(v.z, v.w, h1, l1);
    *(uint2*)(hi + i) = make_uint2(h0, h1);
    *(uint2*)(lo + i) = make_uint2(l0, l1);
}
__global__ void cvth_kernel(const float* __restrict__ x,
                            __half* __restrict__ y, int n)
{
    int i = (blockIdx.x * 256 + threadIdx.x) * 4;
    if (i >= n) return;
    float4 v = *(const float4*)(x + i);
    *(uint2*)(y + i) = make_uint2(pack2h(v.x, v.y), pack2h(v.z, v.w));
}

// ---------------------------------------------------------------------------
// RoPE cos/sin table (double-precision range reduction, robust to fast-math)
// ---------------------------------------------------------------------------
__global__ void rope_table_kernel()
{
    int idx = blockIdx.x * 256 + threadIdx.x;       // SEQ*64 threads
    int l = idx >> 6, d = idx & 63;
    double invf = exp2(-(double)d * (13.287712379549449 / 64.0)); // 10000^(-d/64)
    double t    = fmod((double)l * invf, 6.283185307179586476925286766559);
    g_cos[idx] = cosf((float)t);
    g_sin[idx] = sinf((float)t);
}

// ---------------------------------------------------------------------------
// HMMA GEMM (fp16, 2 products): C = (Ah+Al)*B^T + bias, fp32 accum.
// Unchanged from round 12/13 (passing, 2 CTAs/SM).
// ---------------------------------------------------------------------------
__device__ __forceinline__ void load_chunk_async(
    const __half* __restrict__ a0, const __half* __restrict__ a1,
    const __half* __restrict__ b, int K, int k0, uint32_t dst)
{
    const __half* s[2] = {a0, a1};
    #pragma unroll
    for (int t = 0; t < 2; t++) {
        const __half* p = s[t] + k0;
        #pragma unroll
        for (int it = 0; it < 2; it++) {
            int i = threadIdx.x + it * 256;     // 0..511
            int r = i >> 2, c = i & 3;
            CP16(dst + SWZ(r * 128 + t * 64 + c * 16), p + (size_t)r * K + c * 8);
        }
    }
    const __half* pb = b + k0;
    #pragma unroll
    for (int it = 0; it < 2; it++) {
        int i = threadIdx.x + it * 256;         // 0..511
        int r = i >> 2, c = i & 3;              // r = N row 0..127
        CP16(dst + 16384 + SWZ((r & 63) * 128 + ((r >> 6) << 6) + c * 16),
             pb + (size_t)r * K + c * 8);
    }
}

template<int MODE>
__global__ __launch_bounds__(256, 2)
void tc_gemm(const __half* __restrict__ Ah, const __half* __restrict__ Al,
             const __half* __restrict__ B,
             const float* __restrict__ bias, float* __restrict__ C, int N, int K)
{
    extern __shared__ char smem[];
    char* smp = (char*)(((uintptr_t)smem + 1023) & ~(uintptr_t)1023);
    const uint32_t bufs = smem_u32(smp);

    const int tid  = threadIdx.x;
    const int lane = tid & 31;
    const int wid  = tid >> 5;
    const int wr   = wid >> 2;
    const int wc   = wid & 3;
    const int m0   = blockIdx.y << 7;
    const int n0   = blockIdx.x << 7;
    const int KCHUNKS = K >> 5;

    const __half* Ahp = Ah + (size_t)m0 * K;
    const __half* Alp = Al + (size_t)m0 * K;
    const __half* Bp  = B  + (size_t)n0 * K;

    float acc[4][4][4];
    #pragma unroll
    for (int i = 0; i < 4; i++)
        #pragma unroll
        for (int j = 0; j < 4; j++)
            #pragma unroll
            for (int r = 0; r < 4; r++) acc[i][j][r] = 0.f;

    const int      arow = lane & 15;
    const uint32_t adk  = (lane >> 4) << 4;
    const int      brow = (lane & 7) + ((lane >> 4) << 3);
    const uint32_t bdk  = ((lane >> 3) & 1) << 4;

    load_chunk_async(Ahp, Alp, Bp, K, 0,  bufs);
    CP_COMMIT();
    load_chunk_async(Ahp, Alp, Bp, K, 32, bufs + 24576);
    CP_COMMIT();
    CP_WAIT1();
    __syncthreads();

    for (int c = 0; c < KCHUNKS; c++) {
        if (c + 2 < KCHUNKS) {
            load_chunk_async(Ahp, Alp, Bp, K, (c + 2) << 5,
                             bufs + ((c + 2) % 3) * 24576);
            CP_COMMIT();
        }

        const uint32_t bA = bufs + (c % 3) * 24576;
        const uint32_t bB = bA + 16384;

        #pragma unroll
        for (int ks = 0; ks < 2; ks++) {
            const uint32_t kbA = (uint32_t)ks * 32 + adk;
            const uint32_t kbB = (uint32_t)ks * 32 + bdk;

            uint32_t ah[4][4], al[4][4], bx[2][4];
            #pragma unroll
            for (int mt = 0; mt < 4; mt++) {
                const uint32_t rw = (uint32_t)(wr*64 + mt*16 + arow) * 128;
                ldsm4(bA + SWZ(rw + kbA), ah[mt]);
                ldsm4(bA + SWZ(rw + 64 + kbA), al[mt]);
            }
            #pragma unroll
            for (int np = 0; np < 2; np++) {
                const int rw = wc*32 + np*16 + brow;
                ldsm4(bB + SWZ((uint32_t)(rw & 63) * 128 + (uint32_t)((rw >> 6) << 6) + kbB),
                      bx[np]);
            }
            #pragma unroll
            for (int mt = 0; mt < 4; mt++)
                #pragma unroll
                for (int nt = 0; nt < 4; nt++) {
                    const uint32_t* b2 = &bx[nt >> 1][(nt & 1) * 2];
                    mma16816(acc[mt][nt], ah[mt], b2);
                    mma16816(acc[mt][nt], al[mt], b2);
                }
        }

        if (c + 1 < KCHUNKS) {
            if (c + 2 < KCHUNKS) CP_WAIT1(); else CP_WAIT0();
            __syncthreads();
        }
    }

    if (MODE == 0) {
        #pragma unroll
        for (int mt = 0; mt < 4; mt++) {
            const int mrow = m0 + wr*64 + mt*16 + (lane >> 2);
            #pragma unroll
            for (int nt = 0; nt < 4; nt++) {
                const int cg = n0 + wc*32 + nt*8 + (lane & 3)*2;
                const float bx2 = bias[cg], by = bias[cg + 1];
                *(float2*)&C[(size_t)mrow * N + cg] =
                    make_float2(acc[mt][nt][0] + bx2, acc[mt][nt][1] + by);
                *(float2*)&C[(size_t)(mrow + 8) * N + cg] =
                    make_float2(acc[mt][nt][2] + bx2, acc[mt][nt][3] + by);
            }
        }
        return;
    }

    // ---------------- MODE 1 epilogue: stage -> rope/convert -> scatter -----
    float* st = (float*)smp;                 // 128 x 132 fp32
    const int PITCH = 132;
    __syncthreads();
    #pragma unroll
    for (int mt = 0; mt < 4; mt++) {
        const int r0 = wr*64 + mt*16 + (lane >> 2);
        #pragma unroll
        for (int nt = 0; nt < 4; nt++) {
            const int cl = wc*32 + nt*8 + (lane & 3)*2;
            const float bx2 = bias[n0 + cl], by = bias[n0 + cl + 1];
            *(float2*)&st[r0*PITCH + cl] =
                make_float2(acc[mt][nt][0] + bx2, acc[mt][nt][1] + by);
            *(float2*)&st[(r0 + 8)*PITCH + cl] =
                make_float2(acc[mt][nt][2] + bx2, acc[mt][nt][3] + by);
        }
    }
    __syncthreads();

    const int which = n0 >> 11;              // 0=q 1=k 2=v
    const int h     = (n0 >> 7) & 15;
    const int row   = tid >> 1;
    const int half  = tid & 1;
    const int m     = m0 + row;
    const int bb    = m >> 11;
    const int l     = m & (SEQ - 1);
    const size_t obase = (((size_t)(bb*NHEAD + h))*SEQ + l)*HDIM;
    const float* srow = st + row * PITCH;
    const int d0 = half * 32;

    if (which == 2) {
        uint32_t h1[16], h2[16];
        #pragma unroll
        for (int j = 0; j < 16; j++) {
            h1[j] = pack2h(srow[d0 + 2*j],      srow[d0 + 2*j + 1]);
            h2[j] = pack2h(srow[d0 + 64 + 2*j], srow[d0 + 64 + 2*j + 1]);
        }
        #pragma unroll
        for (int j = 0; j < 4; j++) {
            *(uint4*)&g_vb[obase + d0 + j*8]      = ((uint4*)h1)[j];
            *(uint4*)&g_vb[obase + d0 + 64 + j*8] = ((uint4*)h2)[j];
        }
    } else {
        const float qs = (which == 0) ? 0.08838834764831845f : 1.0f;
        const float* ct  = g_cos + (size_t)l * 64;
        const float* stb = g_sin + (size_t)l * 64;
        if (which == 0) {
            uint32_t h1[16], l1[16], h2[16], l2[16];
            #pragma unroll
            for (int j = 0; j < 16; j++) {
                const int d = d0 + 2*j;
                float2 cc = *(const float2*)&ct[d];
                float2 ss = *(const float2*)&stb[d];
                float x1a = srow[d],      x1b = srow[d + 1];
                float x2a = srow[d + 64], x2b = srow[d + 65];
                split2h((x1a*cc.x - x2a*ss.x)*qs, (x1b*cc.y - x2b*ss.y)*qs, h1[j], l1[j]);
                split2h((x2a*cc.x + x1a*ss.x)*qs, (x2b*cc.y + x1b*ss.y)*qs, h2[j], l2[j]);
            }
            #pragma unroll
            for (int j = 0; j < 4; j++) {
                *(uint4*)&g_qbh[obase + d0 + j*8]      = ((uint4*)h1)[j];
                *(uint4*)&g_qbl[obase + d0 + j*8]      = ((uint4*)l1)[j];
                *(uint4*)&g_qbh[obase + d0 + 64 + j*8] = ((uint4*)h2)[j];
                *(uint4*)&g_qbl[obase + d0 + 64 + j*8] = ((uint4*)l2)[j];
            }
        } else {
            uint32_t h1[16], h2[16];
            #pragma unroll
            for (int j = 0; j < 16; j++) {
                const int d = d0 + 2*j;
                float2 cc = *(const float2*)&ct[d];
                float2 ss = *(const float2*)&stb[d];
                float x1a = srow[d],      x1b = srow[d + 1];
                float x2a = srow[d + 64], x2b = srow[d + 65];
                h1[j] = pack2h(x1a*cc.x - x2a*ss.x, x1b*cc.y - x2b*ss.y);
                h2[j] = pack2h(x2a*cc.x + x1a*ss.x, x2b*cc.y + x1b*ss.y);
            }
            #pragma unroll
            for (int j = 0; j < 4; j++) {
                *(uint4*)&g_kb[obase + d0 + j*8]      = ((uint4*)h1)[j];
                *(uint4*)&g_kb[obase + d0 + 64 + j*8] = ((uint4*)h2)[j];
            }
        }
    }
}

// ---------------------------------------------------------------------------
// HMMA causal flash attention (fp16).
// S = (Qh+Ql) K^T (2 products — accuracy-critical: logit error is amplified
// by exp). PV = P V with SINGLE fp16 P (P in [0,1]: rounding error is a
// direct 2^-11 relative error on probabilities, safe).
// BQ=64, 4 warps, 2 CTAs/SM. Q hi/lo 32KB + double-buffered KV 2x32KB.
// ---------------------------------------------------------------------------
__global__ __launch_bounds__(128, 2)
void attn_kernel()
{
    extern __shared__ char sm[];
    const uint32_t base = (smem_u32(sm) + 1023) & ~1023u;
    const uint32_t QH = base;                 // 2 panels x 8KB (dims 0-63, 64-127)
    const uint32_t QL = base + 16384;
    const uint32_t KV = base + 32768;         // buf b at +b*32768 (K 16KB, V 16KB)

    const int tid  = threadIdx.x;
    const int lane = tid & 31;
    const int wid  = tid >> 5;                // 0..3
    const int qt   = (int)gridDim.x - 1 - (int)blockIdx.x;  // heavy tiles first
    const int h    = blockIdx.y;
    const int b    = blockIdx.z;
    const int bh   = b*NHEAD + h;
    const int q0   = qt << 6;
    const int nkv  = qt + 1;

    const size_t hoff = (size_t)bh * SEQ * HDIM;
    const __half* qbh = g_qbh + hoff + (size_t)q0 * HDIM;
    const __half* qbl = g_qbl + hoff + (size_t)q0 * HDIM;
    const __half* kb  = g_kb + hoff;
    const __half* vb  = g_vb + hoff;

    // ---- Q load (64 rows x 16 units per array) ----
    #pragma unroll
    for (int it = 0; it < 8; it++) {
        int i = tid + it * 128;               // 0..1023
        int row = i >> 4, u = i & 15;
        uint32_t off = (u >> 3) * 8192 + SWZ(row * 128 + (u & 7) * 16);
        CP16(QH + off, qbh + (size_t)row * HDIM + u * 8);
        CP16(QL + off, qbl + (size_t)row * HDIM + u * 8);
    }
    // ---- KV block 0 ----
    {
        const __half* arr[2] = {kb, vb};
        #pragma unroll
        for (int t = 0; t < 2; t++)
            #pragma unroll
            for (int it = 0; it < 8; it++) {
                int i = tid + it * 128;       // 0..1023
                int row = i >> 4, u = i & 15;
                uint32_t d = KV + t*16384 + (u>>3)*8192 + SWZ(row*128 + (u&7)*16);
                CP16(d, arr[t] + (size_t)row * HDIM + u * 8);
            }
    }
    CP_COMMIT();
    CP_WAIT0();
    __syncthreads();

    float mr0 = -1e30f, mr1 = -1e30f, lr0 = 0.f, lr1 = 0.f;
    float o[16][4];
    #pragma unroll
    for (int t = 0; t < 16; t++)
        #pragma unroll
        for (int j = 0; j < 4; j++) o[t][j] = 0.f;

    const int rloc0 = wid*16 + (lane >> 2);   // 0..63
    const int rg0   = q0 + rloc0;

    for (int kt = 0; kt < nkv; kt++) {
        const uint32_t KB = KV + (kt & 1) * 32768;
        const uint32_t VB = KB + 16384;

        if (kt + 1 < nkv) {
            const __half* arr[2] = {kb, vb};
            const size_t s0 = (size_t)(kt + 1) * 64 * HDIM;
            const uint32_t nb = KV + ((kt + 1) & 1) * 32768;
            #pragma unroll
            for (int t = 0; t < 2; t++)
                #pragma unroll
                for (int it = 0; it < 8; it++) {
                    int i = tid + it * 128;
                    int row = i >> 4, u = i & 15;
                    uint32_t d = nb + t*16384 + (u>>3)*8192 + SWZ(row*128 + (u&7)*16);
                    CP16(d, arr[t] + s0 + (size_t)row * HDIM + u * 8);
                }
            CP_COMMIT();
        }

        // ---- S = (Qh+Ql) K^T ----
        float s[8][4];
        #pragma unroll
        for (int t = 0; t < 8; t++)
            #pragma unroll
            for (int j = 0; j < 4; j++) s[t][j] = 0.f;

        #pragma unroll
        for (int ks = 0; ks < 8; ks++) {
            const int arow = wid*16 + (lane & 15);
            const uint32_t aoff = (ks>>2)*8192
                + SWZ(arow*128 + (ks&3)*32 + ((lane>>4)<<4));
            uint32_t qa[4], qla[4];
            ldsm4(QH + aoff, qa);
            ldsm4(QL + aoff, qla);

            const int krow0 = (lane & 7) + ((lane >> 4) << 3);
            const uint32_t kcol = (uint32_t)((ks&3)*32 + (((lane>>3)&1)<<4));
            #pragma unroll
            for (int ntp = 0; ntp < 4; ntp++) {
                const uint32_t koff = (ks>>2)*8192 + SWZ((ntp*16 + krow0)*128 + kcol);
                uint32_t kb4[4];
                ldsm4(KB + koff, kb4);
                mma16816(s[2*ntp],   qa,  &kb4[0]);
                mma16816(s[2*ntp],   qla, &kb4[0]);
                mma16816(s[2*ntp+1], qa,  &kb4[2]);
                mma16816(s[2*ntp+1], qla, &kb4[2]);
            }
        }

        // ---- causal mask (diagonal block only) ----
        if (kt >= qt) {
            #pragma unroll
            for (int t = 0; t < 8; t++) {
                #pragma unroll
                for (int j = 0; j < 2; j++) {
                    const int n = kt*64 + t*8 + 2*(lane & 3) + j;
                    if (n > rg0)     s[t][j]   = -1e30f;
                    if (n > rg0 + 8) s[t][2+j] = -1e30f;
                }
            }
        }

        float rm0 = -1e30f, rm1 = -1e30f;
        #pragma unroll
        for (int t = 0; t < 8; t++) {
            rm0 = fmaxf(rm0, fmaxf(s[t][0], s[t][1]));
            rm1 = fmaxf(rm1, fmaxf(s[t][2], s[t][3]));
        }
        rm0 = fmaxf(rm0, __shfl_xor_sync(0xffffffffu, rm0, 1));
        rm0 = fmaxf(rm0, __shfl_xor_sync(0xffffffffu, rm0, 2));
        rm1 = fmaxf(rm1, __shfl_xor_sync(0xffffffffu, rm1, 1));
        rm1 = fmaxf(rm1, __shfl_xor_sync(0xffffffffu, rm1, 2));

        const float mn0 = fmaxf(mr0, rm0), mn1 = fmaxf(mr1, rm1);
        const float sf0 = __expf(mr0 - mn0), sf1 = __expf(mr1 - mn1);
        mr0 = mn0; mr1 = mn1;

        float rs0 = 0.f, rs1 = 0.f;
        #pragma unroll
        for (int t = 0; t < 8; t++) {
            s[t][0] = __expf(s[t][0] - mn0);
            s[t][1] = __expf(s[t][1] - mn0);
            s[t][2] = __expf(s[t][2] - mn1);
            s[t][3] = __expf(s[t][3] - mn1);
            rs0 += s[t][0] + s[t][1];
            rs1 += s[t][2] + s[t][3];
        }
        rs0 += __shfl_xor_sync(0xffffffffu, rs0, 1);
        rs0 += __shfl_xor_sync(0xffffffffu, rs0, 2);
        rs1 += __shfl_xor_sync(0xffffffffu, rs1, 1);
        rs1 += __shfl_xor_sync(0xffffffffu, rs1, 2);
        lr0 = lr0 * sf0 + rs0;
        lr1 = lr1 * sf1 + rs1;

        #pragma unroll
        for (int t = 0; t < 16; t++) {
            o[t][0] *= sf0; o[t][1] *= sf0;
            o[t][2] *= sf1; o[t][3] *= sf1;
        }

        // ---- P packed single fp16 into A-fragments ----
        uint32_t aph[4][4];
        #pragma unroll
        for (int g = 0; g < 4; g++) {
            aph[g][0] = pack2h(s[2*g][0],   s[2*g][1]);
            aph[g][1] = pack2h(s[2*g][2],   s[2*g][3]);
            aph[g][2] = pack2h(s[2*g+1][0], s[2*g+1][1]);
            aph[g][3] = pack2h(s[2*g+1][2], s[2*g+1][3]);
        }

        // ---- O += P V (single product) ----
        const int vrow0 = (lane & 15);
        const uint32_t vcadd = (uint32_t)((lane >> 4) << 4);
        #pragma unroll
        for (int dtp = 0; dtp < 8; dtp++) {
            const uint32_t vcol = (uint32_t)((dtp&3)*32) + vcadd;
            #pragma unroll
            for (int g = 0; g < 4; g++) {
                const uint32_t voff = (dtp>>2)*8192 + SWZ((g*16 + vrow0)*128 + vcol);
                uint32_t vb4[4];
                ldsm4t(VB + voff, vb4);
                mma16816(o[2*dtp],   aph[g], &vb4[0]);
                mma16816(o[2*dtp+1], aph[g], &vb4[2]);
            }
        }

        if (kt + 1 < nkv) {
            CP_WAIT0();
            __syncthreads();
        }
    }

    // ---- epilogue: normalize, split fp16 hi/lo, write [B, L, H*128] ----
    const float inv0 = 1.f / lr0, inv1 = 1.f / lr1;
    const size_t row0 = ((size_t)(b*SEQ + rg0)) * D_MODEL + h*HDIM;
    const size_t row1 = row0 + 8 * D_MODEL;
    #pragma unroll
    for (int t = 0; t < 16; t++) {
        const int d = t*8 + 2*(lane & 3);
        uint32_t hi, lo;
        split2h(o[t][0]*inv0, o[t][1]*inv0, hi, lo);
        *(uint32_t*)&g_ah[row0 + d] = hi;
        *(uint32_t*)&g_al[row0 + d] = lo;
        split2h(o[t][2]*inv1, o[t][3]*inv1, hi, lo);
        *(uint32_t*)&g_ah[row1 + d] = hi;
        *(uint32_t*)&g_al[row1 + d] = lo;
    }
}

// ---------------------------------------------------------------------------
extern "C" void kernel_launch(void* const* d_in, const int* in_sizes, int n_in,
                              void* d_out, int out_size)
{
    const float* query = (const float*)d_in[0];
    const float* W_qkv = (const float*)d_in[1];
    const float* b_qkv = (const float*)d_in[2];
    const float* W_out = (const float*)d_in[3];
    const float* b_out = (const float*)d_in[4];
    float* out = (float*)d_out;

    void *p_qh, *p_ql, *p_w, *p_o, *p_ah, *p_al;
    cudaGetSymbolAddress(&p_qh, g_qh);  cudaGetSymbolAddress(&p_ql, g_ql);
    cudaGetSymbolAddress(&p_w, g_w);    cudaGetSymbolAddress(&p_o, g_o);
    cudaGetSymbolAddress(&p_ah, g_ah);  cudaGetSymbolAddress(&p_al, g_al);

    const int GEMM_SMEM = 1024 + 3*24576;       // 3-stage K32 pipeline (2 CTAs/SM)
    cudaFuncSetAttribute(tc_gemm<0>, cudaFuncAttributeMaxDynamicSharedMemorySize, GEMM_SMEM);
    cudaFuncSetAttribute(tc_gemm<1>, cudaFuncAttributeMaxDynamicSharedMemorySize, GEMM_SMEM);
    const int ATTN_SMEM = 1024 + 32768 + 2*32768;   // Q 32KB + 2 KV bufs (2 CTAs/SM)
    cudaFuncSetAttribute(attn_kernel, cudaFuncAttributeMaxDynamicSharedMemorySize, ATTN_SMEM);

    // 0) rope tables (must precede QKV epilogue)
    rope_table_kernel<<<(SEQ*64)/256, 256>>>();

    // 1) prepare fp16 operands
    {
        int n;
        n = MROWS*D_MODEL;
        splith_kernel<<<n/1024, 256>>>(query, (__half*)p_qh, (__half*)p_ql, n);
        n = 3*D_MODEL*D_MODEL;
        cvth_kernel<<<n/1024, 256>>>(W_qkv, (__half*)p_w, n);
        n = D_MODEL*D_MODEL;
        cvth_kernel<<<n/1024, 256>>>(W_out, (__half*)p_o, n);
    }

    // 2) QKV projection (fp16 HMMA, 2 products) with fused rope epilogue
    tc_gemm<1><<<dim3(3*D_MODEL/128, MROWS/128), 256, GEMM_SMEM>>>(
        (const __half*)p_qh, (const __half*)p_ql, (const __half*)p_w,
        b_qkv, nullptr, 3*D_MODEL, D_MODEL);

    // 3) causal flash attention (BQ=64, 2 CTAs/SM, single-P PV) -> g_ah/g_al
    attn_kernel<<<dim3(SEQ/64, NHEAD, BATCH), 128, ATTN_SMEM>>>();

    // 4) Output projection -> d_out
    tc_gemm<0><<<dim3(D_MODEL/128, MROWS/128), 256, GEMM_SMEM>>>(
        (const __half*)p_ah, (const __half*)p_al, (const __half*)p_o,
        b_out, out, D_MODEL, D_MODEL);
}

// round 15
// speedup vs baseline: 1.9265x; 1.2681x over previous
#include <cuda_runtime.h>
#include <cuda_fp16.h>
#include <math.h>
#include <stdint.h>

#define D_MODEL 2048
#define NHEAD   16
#define HDIM    128
#define BATCH   2
#define SEQ     2048
#define MROWS   (BATCH*SEQ)   // 4096

// ---------------- device scratch (no runtime allocation) ----------------
__device__ __half g_qbh[(size_t)BATCH*NHEAD*SEQ*HDIM];  // roped+scaled Q hi/lo (fp16)
__device__ __half g_qbl[(size_t)BATCH*NHEAD*SEQ*HDIM];
__device__ __half g_kb [(size_t)BATCH*NHEAD*SEQ*HDIM];  // roped K (single fp16)
__device__ __half g_vb [(size_t)BATCH*NHEAD*SEQ*HDIM];  // V (single fp16)

__device__ __half g_qh[(size_t)MROWS*D_MODEL];          // query hi/lo (GEMM A)
__device__ __half g_ql[(size_t)MROWS*D_MODEL];
__device__ __half g_w [(size_t)3*D_MODEL*D_MODEL];      // W_qkv (single fp16)
__device__ __half g_o [(size_t)D_MODEL*D_MODEL];        // W_out (single fp16)
__device__ __half g_ah[(size_t)MROWS*D_MODEL];          // attn-out (single fp16)

__device__ float g_cos[(size_t)SEQ*64];                 // rope tables
__device__ float g_sin[(size_t)SEQ*64];

// ---------------- helpers ----------------
__device__ __forceinline__ uint32_t smem_u32(const void* p) {
    uint32_t a;
    asm("{ .reg .u64 t; cvta.to.shared.u64 t, %1; cvt.u32.u64 %0, t; }" : "=r"(a) : "l"(p));
    return a;
}
#define SWZ(o) ((o) ^ (((o) >> 3) & 0x70))

__device__ __forceinline__ void ldsm4(uint32_t addr, uint32_t* r) {
    asm volatile("ldmatrix.sync.aligned.m8n8.x4.shared.b16 {%0,%1,%2,%3}, [%4];"
                 : "=r"(r[0]), "=r"(r[1]), "=r"(r[2]), "=r"(r[3]) : "r"(addr));
}
__device__ __forceinline__ void ldsm4t(uint32_t addr, uint32_t* r) {
    asm volatile("ldmatrix.sync.aligned.m8n8.x4.trans.shared.b16 {%0,%1,%2,%3}, [%4];"
                 : "=r"(r[0]), "=r"(r[1]), "=r"(r[2]), "=r"(r[3]) : "r"(addr));
}
__device__ __forceinline__ void mma16816(float* c, const uint32_t* a, const uint32_t* b) {
    asm volatile(
        "mma.sync.aligned.m16n8k16.row.col.f32.f16.f16.f32 "
        "{%0,%1,%2,%3}, {%4,%5,%6,%7}, {%8,%9}, {%0,%1,%2,%3};"
        : "+f"(c[0]), "+f"(c[1]), "+f"(c[2]), "+f"(c[3])
        : "r"(a[0]), "r"(a[1]), "r"(a[2]), "r"(a[3]), "r"(b[0]), "r"(b[1]));
}
#define CP16(dst, src) \
    asm volatile("cp.async.cg.shared.global [%0], [%1], 16;" :: "r"(dst), "l"(src))
#define CP_COMMIT() asm volatile("cp.async.commit_group;" ::: "memory")
#define CP_WAIT0()  asm volatile("cp.async.wait_group 0;" ::: "memory")
#define CP_WAIT1()  asm volatile("cp.async.wait_group 1;" ::: "memory")

// split pair of fp32 into packed fp16x2 hi and lo (residual)
__device__ __forceinline__ void split2h(float x, float y, uint32_t& hi, uint32_t& lo) {
    __half hx = __float2half_rn(x), hy = __float2half_rn(y);
    float rx = x - __half2float(hx), ry = y - __half2float(hy);
    __half lx = __float2half_rn(rx), ly = __float2half_rn(ry);
    hi = ((uint32_t)__half_as_ushort(hy) << 16) | __half_as_ushort(hx);
    lo = ((uint32_t)__half_as_ushort(ly) << 16) | __half_as_ushort(lx);
}
__device__ __forceinline__ uint32_t pack2h(float x, float y) {
    __half hx = __float2half_rn(x), hy = __float2half_rn(y);
    return ((uint32_t)__half_as_ushort(hy) << 16) | __half_as_ushort(hx);
}

// ---------------------------------------------------------------------------
// fp32 -> fp16 hi/lo split, and fp32 -> fp16 single convert
// ---------------------------------------------------------------------------
__global__ void splith_kernel(const float* __restrict__ x,
                              __half* __restrict__ hi,
                              __half* __restrict__ lo, int n)
{
    int i = (blockIdx.x * 256 + threadIdx.x) * 4;
    if (i >= n) return;
    float4 v = *(const float4*)(x + i);
    uint32_t h0, l0, h1, l1;
    split2h(v.x, v.y, h0, l0);
    split2h(v.z, v.w, h1, l1);
    *(uint2*)(hi + i) = make_uint2(h0, h1);
    *(uint2*)(lo + i) = make_uint2(l0, l1);
}
__global__ void cvth_kernel(const float* __restrict__ x,
                            __half* __restrict__ y, int n)
{
    int i = (blockIdx.x * 256 + threadIdx.x) * 4;
    if (i >= n) return;
    float4 v = *(const float4*)(x + i);
    *(uint2*)(y + i) = make_uint2(pack2h(v.x, v.y), pack2h(v.z, v.w));
}

// ---------------------------------------------------------------------------
// RoPE cos/sin table (double-precision range reduction, robust to fast-math)
// ---------------------------------------------------------------------------
__global__ void rope_table_kernel()
{
    int idx = blockIdx.x * 256 + threadIdx.x;       // SEQ*64 threads
    int l = idx >> 6, d = idx & 63;
    double invf = exp2(-(double)d * (13.287712379549449 / 64.0)); // 10000^(-d/64)
    double t    = fmod((double)l * invf, 6.283185307179586476925286766559);
    g_cos[idx] = cosf((float)t);
    g_sin[idx] = sinf((float)t);
}

// ---------------------------------------------------------------------------
// HMMA GEMM (fp16): C = (Ah [+ Al]) * B^T + bias, fp32 accum.
// `dual` (block-uniform) selects 1 vs 2 A-side products:
//   MODE 0 (out-proj): single product (A = attn output, linear -> safe).
//   MODE 1 (QKV): dual for q,k columns (feed exp), single for v columns.
// CTA 128x128, 8 warps, K-chunks of 32, 3-stage cp.async, 2 CTAs/SM.
// ---------------------------------------------------------------------------
__device__ __forceinline__ void load_chunk_async(
    const __half* __restrict__ a0, const __half* __restrict__ a1,
    const __half* __restrict__ b, int K, int k0, uint32_t dst, bool dual)
{
    const __half* p = a0 + k0;
    #pragma unroll
    for (int it = 0; it < 2; it++) {
        int i = threadIdx.x + it * 256;         // 0..511
        int r = i >> 2, c = i & 3;
        CP16(dst + SWZ(r * 128 + c * 16), p + (size_t)r * K + c * 8);
    }
    if (dual) {
        p = a1 + k0;
        #pragma unroll
        for (int it = 0; it < 2; it++) {
            int i = threadIdx.x + it * 256;
            int r = i >> 2, c = i & 3;
            CP16(dst + SWZ(r * 128 + 64 + c * 16), p + (size_t)r * K + c * 8);
        }
    }
    const __half* pb = b + k0;
    #pragma unroll
    for (int it = 0; it < 2; it++) {
        int i = threadIdx.x + it * 256;         // 0..511
        int r = i >> 2, c = i & 3;              // r = N row 0..127
        CP16(dst + 16384 + SWZ((r & 63) * 128 + ((r >> 6) << 6) + c * 16),
             pb + (size_t)r * K + c * 8);
    }
}

template<int MODE>
__global__ __launch_bounds__(256, 2)
void tc_gemm(const __half* __restrict__ Ah, const __half* __restrict__ Al,
             const __half* __restrict__ B,
             const float* __restrict__ bias, float* __restrict__ C, int N, int K)
{
    extern __shared__ char smem[];
    char* smp = (char*)(((uintptr_t)smem + 1023) & ~(uintptr_t)1023);
    const uint32_t bufs = smem_u32(smp);

    const int tid  = threadIdx.x;
    const int lane = tid & 31;
    const int wid  = tid >> 5;
    const int wr   = wid >> 2;
    const int wc   = wid & 3;
    const int m0   = blockIdx.y << 7;
    const int n0   = blockIdx.x << 7;
    const int KCHUNKS = K >> 5;
    const bool dual = (MODE == 1) ? ((n0 >> 11) != 2) : false;

    const __half* Ahp = Ah + (size_t)m0 * K;
    const __half* Alp = Al + (size_t)m0 * K;
    const __half* Bp  = B  + (size_t)n0 * K;

    float acc[4][4][4];
    #pragma unroll
    for (int i = 0; i < 4; i++)
        #pragma unroll
        for (int j = 0; j < 4; j++)
            #pragma unroll
            for (int r = 0; r < 4; r++) acc[i][j][r] = 0.f;

    const int      arow = lane & 15;
    const uint32_t adk  = (lane >> 4) << 4;
    const int      brow = (lane & 7) + ((lane >> 4) << 3);
    const uint32_t bdk  = ((lane >> 3) & 1) << 4;

    load_chunk_async(Ahp, Alp, Bp, K, 0,  bufs, dual);
    CP_COMMIT();
    load_chunk_async(Ahp, Alp, Bp, K, 32, bufs + 24576, dual);
    CP_COMMIT();
    CP_WAIT1();
    __syncthreads();

    for (int c = 0; c < KCHUNKS; c++) {
        if (c + 2 < KCHUNKS) {
            load_chunk_async(Ahp, Alp, Bp, K, (c + 2) << 5,
                             bufs + ((c + 2) % 3) * 24576, dual);
            CP_COMMIT();
        }

        const uint32_t bA = bufs + (c % 3) * 24576;
        const uint32_t bB = bA + 16384;

        #pragma unroll
        for (int ks = 0; ks < 2; ks++) {
            const uint32_t kbA = (uint32_t)ks * 32 + adk;
            const uint32_t kbB = (uint32_t)ks * 32 + bdk;

            uint32_t ah[4][4], bx[2][4];
            #pragma unroll
            for (int mt = 0; mt < 4; mt++)
                ldsm4(bA + SWZ((uint32_t)(wr*64 + mt*16 + arow) * 128 + kbA), ah[mt]);
            #pragma unroll
            for (int np = 0; np < 2; np++) {
                const int rw = wc*32 + np*16 + brow;
                ldsm4(bB + SWZ((uint32_t)(rw & 63) * 128 + (uint32_t)((rw >> 6) << 6) + kbB),
                      bx[np]);
            }
            #pragma unroll
            for (int mt = 0; mt < 4; mt++)
                #pragma unroll
                for (int nt = 0; nt < 4; nt++)
                    mma16816(acc[mt][nt], ah[mt], &bx[nt >> 1][(nt & 1) * 2]);

            if (dual) {
                uint32_t al[4][4];
                #pragma unroll
                for (int mt = 0; mt < 4; mt++)
                    ldsm4(bA + SWZ((uint32_t)(wr*64 + mt*16 + arow) * 128 + 64 + kbA),
                          al[mt]);
                #pragma unroll
                for (int mt = 0; mt < 4; mt++)
                    #pragma unroll
                    for (int nt = 0; nt < 4; nt++)
                        mma16816(acc[mt][nt], al[mt], &bx[nt >> 1][(nt & 1) * 2]);
            }
        }

        if (c + 1 < KCHUNKS) {
            if (c + 2 < KCHUNKS) CP_WAIT1(); else CP_WAIT0();
            __syncthreads();
        }
    }

    if (MODE == 0) {
        #pragma unroll
        for (int mt = 0; mt < 4; mt++) {
            const int mrow = m0 + wr*64 + mt*16 + (lane >> 2);
            #pragma unroll
            for (int nt = 0; nt < 4; nt++) {
                const int cg = n0 + wc*32 + nt*8 + (lane & 3)*2;
                const float bx2 = bias[cg], by = bias[cg + 1];
                *(float2*)&C[(size_t)mrow * N + cg] =
                    make_float2(acc[mt][nt][0] + bx2, acc[mt][nt][1] + by);
                *(float2*)&C[(size_t)(mrow + 8) * N + cg] =
                    make_float2(acc[mt][nt][2] + bx2, acc[mt][nt][3] + by);
            }
        }
        return;
    }

    // ---------------- MODE 1 epilogue: stage -> rope/convert -> scatter -----
    float* st = (float*)smp;                 // 128 x 132 fp32
    const int PITCH = 132;
    __syncthreads();
    #pragma unroll
    for (int mt = 0; mt < 4; mt++) {
        const int r0 = wr*64 + mt*16 + (lane >> 2);
        #pragma unroll
        for (int nt = 0; nt < 4; nt++) {
            const int cl = wc*32 + nt*8 + (lane & 3)*2;
            const float bx2 = bias[n0 + cl], by = bias[n0 + cl + 1];
            *(float2*)&st[r0*PITCH + cl] =
                make_float2(acc[mt][nt][0] + bx2, acc[mt][nt][1] + by);
            *(float2*)&st[(r0 + 8)*PITCH + cl] =
                make_float2(acc[mt][nt][2] + bx2, acc[mt][nt][3] + by);
        }
    }
    __syncthreads();

    const int which = n0 >> 11;              // 0=q 1=k 2=v
    const int h     = (n0 >> 7) & 15;
    const int row   = tid >> 1;
    const int half  = tid & 1;
    const int m     = m0 + row;
    const int bb    = m >> 11;
    const int l     = m & (SEQ - 1);
    const size_t obase = (((size_t)(bb*NHEAD + h))*SEQ + l)*HDIM;
    const float* srow = st + row * PITCH;
    const int d0 = half * 32;

    if (which == 2) {
        uint32_t h1[16], h2[16];
        #pragma unroll
        for (int j = 0; j < 16; j++) {
            h1[j] = pack2h(srow[d0 + 2*j],      srow[d0 + 2*j + 1]);
            h2[j] = pack2h(srow[d0 + 64 + 2*j], srow[d0 + 64 + 2*j + 1]);
        }
        #pragma unroll
        for (int j = 0; j < 4; j++) {
            *(uint4*)&g_vb[obase + d0 + j*8]      = ((uint4*)h1)[j];
            *(uint4*)&g_vb[obase + d0 + 64 + j*8] = ((uint4*)h2)[j];
        }
    } else {
        const float qs = (which == 0) ? 0.08838834764831845f : 1.0f;
        const float* ct  = g_cos + (size_t)l * 64;
        const float* stb = g_sin + (size_t)l * 64;
        if (which == 0) {
            uint32_t h1[16], l1[16], h2[16], l2[16];
            #pragma unroll
            for (int j = 0; j < 16; j++) {
                const int d = d0 + 2*j;
                float2 cc = *(const float2*)&ct[d];
                float2 ss = *(const float2*)&stb[d];
                float x1a = srow[d],      x1b = srow[d + 1];
                float x2a = srow[d + 64], x2b = srow[d + 65];
                split2h((x1a*cc.x - x2a*ss.x)*qs, (x1b*cc.y - x2b*ss.y)*qs, h1[j], l1[j]);
                split2h((x2a*cc.x + x1a*ss.x)*qs, (x2b*cc.y + x1b*ss.y)*qs, h2[j], l2[j]);
            }
            #pragma unroll
            for (int j = 0; j < 4; j++) {
                *(uint4*)&g_qbh[obase + d0 + j*8]      = ((uint4*)h1)[j];
                *(uint4*)&g_qbl[obase + d0 + j*8]      = ((uint4*)l1)[j];
                *(uint4*)&g_qbh[obase + d0 + 64 + j*8] = ((uint4*)h2)[j];
                *(uint4*)&g_qbl[obase + d0 + 64 + j*8] = ((uint4*)l2)[j];
            }
        } else {
            uint32_t h1[16], h2[16];
            #pragma unroll
            for (int j = 0; j < 16; j++) {
                const int d = d0 + 2*j;
                float2 cc = *(const float2*)&ct[d];
                float2 ss = *(const float2*)&stb[d];
                float x1a = srow[d],      x1b = srow[d + 1];
                float x2a = srow[d + 64], x2b = srow[d + 65];
                h1[j] = pack2h(x1a*cc.x - x2a*ss.x, x1b*cc.y - x2b*ss.y);
                h2[j] = pack2h(x2a*cc.x + x1a*ss.x, x2b*cc.y + x1b*ss.y);
            }
            #pragma unroll
            for (int j = 0; j < 4; j++) {
                *(uint4*)&g_kb[obase + d0 + j*8]      = ((uint4*)h1)[j];
                *(uint4*)&g_kb[obase + d0 + 64 + j*8] = ((uint4*)h2)[j];
            }
        }
    }
}

// ---------------------------------------------------------------------------
// HMMA causal flash attention (fp16).
// S = (Qh+Ql) K^T (dual: logits feed exp). PV = P V (single fp16 P).
// Output O stored single fp16 (enters out-proj linearly).
// BQ=64, 4 warps, 2 CTAs/SM. Q hi/lo 32KB + double-buffered KV 2x32KB.
// ---------------------------------------------------------------------------
__global__ __launch_bounds__(128, 2)
void attn_kernel()
{
    extern __shared__ char sm[];
    const uint32_t base = (smem_u32(sm) + 1023) & ~1023u;
    const uint32_t QH = base;                 // 2 panels x 8KB (dims 0-63, 64-127)
    const uint32_t QL = base + 16384;
    const uint32_t KV = base + 32768;         // buf b at +b*32768 (K 16KB, V 16KB)

    const int tid  = threadIdx.x;
    const int lane = tid & 31;
    const int wid  = tid >> 5;                // 0..3
    const int qt   = (int)gridDim.x - 1 - (int)blockIdx.x;  // heavy tiles first
    const int h    = blockIdx.y;
    const int b    = blockIdx.z;
    const int bh   = b*NHEAD + h;
    const int q0   = qt << 6;
    const int nkv  = qt + 1;

    const size_t hoff = (size_t)bh * SEQ * HDIM;
    const __half* qbh = g_qbh + hoff + (size_t)q0 * HDIM;
    const __half* qbl = g_qbl + hoff + (size_t)q0 * HDIM;
    const __half* kb  = g_kb + hoff;
    const __half* vb  = g_vb + hoff;

    // ---- Q load (64 rows x 16 units per array) ----
    #pragma unroll
    for (int it = 0; it < 8; it++) {
        int i = tid + it * 128;               // 0..1023
        int row = i >> 4, u = i & 15;
        uint32_t off = (u >> 3) * 8192 + SWZ(row * 128 + (u & 7) * 16);
        CP16(QH + off, qbh + (size_t)row * HDIM + u * 8);
        CP16(QL + off, qbl + (size_t)row * HDIM + u * 8);
    }
    // ---- KV block 0 ----
    {
        const __half* arr[2] = {kb, vb};
        #pragma unroll
        for (int t = 0; t < 2; t++)
            #pragma unroll
            for (int it = 0; it < 8; it++) {
                int i = tid + it * 128;       // 0..1023
                int row = i >> 4, u = i & 15;
                uint32_t d = KV + t*16384 + (u>>3)*8192 + SWZ(row*128 + (u&7)*16);
                CP16(d, arr[t] + (size_t)row * HDIM + u * 8);
            }
    }
    CP_COMMIT();
    CP_WAIT0();
    __syncthreads();

    float mr0 = -1e30f, mr1 = -1e30f, lr0 = 0.f, lr1 = 0.f;
    float o[16][4];
    #pragma unroll
    for (int t = 0; t < 16; t++)
        #pragma unroll
        for (int j = 0; j < 4; j++) o[t][j] = 0.f;

    const int rloc0 = wid*16 + (lane >> 2);   // 0..63
    const int rg0   = q0 + rloc0;

    for (int kt = 0; kt < nkv; kt++) {
        const uint32_t KB = KV + (kt & 1) * 32768;
        const uint32_t VB = KB + 16384;

        if (kt + 1 < nkv) {
            const __half* arr[2] = {kb, vb};
            const size_t s0 = (size_t)(kt + 1) * 64 * HDIM;
            const uint32_t nb = KV + ((kt + 1) & 1) * 32768;
            #pragma unroll
            for (int t = 0; t < 2; t++)
                #pragma unroll
                for (int it = 0; it < 8; it++) {
                    int i = tid + it * 128;
                    int row = i >> 4, u = i & 15;
                    uint32_t d = nb + t*16384 + (u>>3)*8192 + SWZ(row*128 + (u&7)*16);
                    CP16(d, arr[t] + s0 + (size_t)row * HDIM + u * 8);
                }
            CP_COMMIT();
        }

        // ---- S = (Qh+Ql) K^T ----
        float s[8][4];
        #pragma unroll
        for (int t = 0; t < 8; t++)
            #pragma unroll
            for (int j = 0; j < 4; j++) s[t][j] = 0.f;

        #pragma unroll
        for (int ks = 0; ks < 8; ks++) {
            const int arow = wid*16 + (lane & 15);
            const uint32_t aoff = (ks>>2)*8192
                + SWZ(arow*128 + (ks&3)*32 + ((lane>>4)<<4));
            uint32_t qa[4], qla[4];
            ldsm4(QH + aoff, qa);
            ldsm4(QL + aoff, qla);

            const int krow0 = (lane & 7) + ((lane >> 4) << 3);
            const uint32_t kcol = (uint32_t)((ks&3)*32 + (((lane>>3)&1)<<4));
            #pragma unroll
            for (int ntp = 0; ntp < 4; ntp++) {
                const uint32_t koff = (ks>>2)*8192 + SWZ((ntp*16 + krow0)*128 + kcol);
                uint32_t kb4[4];
                ldsm4(KB + koff, kb4);
                mma16816(s[2*ntp],   qa,  &kb4[0]);
                mma16816(s[2*ntp],   qla, &kb4[0]);
                mma16816(s[2*ntp+1], qa,  &kb4[2]);
                mma16816(s[2*ntp+1], qla, &kb4[2]);
            }
        }

        // ---- causal mask (diagonal block only) ----
        if (kt >= qt) {
            #pragma unroll
            for (int t = 0; t < 8; t++) {
                #pragma unroll
                for (int j = 0; j < 2; j++) {
                    const int n = kt*64 + t*8 + 2*(lane & 3) + j;
                    if (n > rg0)     s[t][j]   = -1e30f;
                    if (n > rg0 + 8) s[t][2+j] = -1e30f;
                }
            }
        }

        float rm0 = -1e30f, rm1 = -1e30f;
        #pragma unroll
        for (int t = 0; t < 8; t++) {
            rm0 = fmaxf(rm0, fmaxf(s[t][0], s[t][1]));
            rm1 = fmaxf(rm1, fmaxf(s[t][2], s[t][3]));
        }
        rm0 = fmaxf(rm0, __shfl_xor_sync(0xffffffffu, rm0, 1));
        rm0 = fmaxf(rm0, __shfl_xor_sync(0xffffffffu, rm0, 2));
        rm1 = fmaxf(rm1, __shfl_xor_sync(0xffffffffu, rm1, 1));
        rm1 = fmaxf(rm1, __shfl_xor_sync(0xffffffffu, rm1, 2));

        const float mn0 = fmaxf(mr0, rm0), mn1 = fmaxf(mr1, rm1);
        const float sf0 = __expf(mr0 - mn0), sf1 = __expf(mr1 - mn1);
        mr0 = mn0; mr1 = mn1;

        float rs0 = 0.f, rs1 = 0.f;
        #pragma unroll
        for (int t = 0; t < 8; t++) {
            s[t][0] = __expf(s[t][0] - mn0);
            s[t][1] = __expf(s[t][1] - mn0);
            s[t][2] = __expf(s[t][2] - mn1);
            s[t][3] = __expf(s[t][3] - mn1);
            rs0 += s[t][0] + s[t][1];
            rs1 += s[t][2] + s[t][3];
        }
        rs0 += __shfl_xor_sync(0xffffffffu, rs0, 1);
        rs0 += __shfl_xor_sync(0xffffffffu, rs0, 2);
        rs1 += __shfl_xor_sync(0xffffffffu, rs1, 1);
        rs1 += __shfl_xor_sync(0xffffffffu, rs1, 2);
        lr0 = lr0 * sf0 + rs0;
        lr1 = lr1 * sf1 + rs1;

        #pragma unroll
        for (int t = 0; t < 16; t++) {
            o[t][0] *= sf0; o[t][1] *= sf0;
            o[t][2] *= sf1; o[t][3] *= sf1;
        }

        // ---- P packed single fp16 into A-fragments ----
        uint32_t aph[4][4];
        #pragma unroll
        for (int g = 0; g < 4; g++) {
            aph[g][0] = pack2h(s[2*g][0],   s[2*g][1]);
            aph[g][1] = pack2h(s[2*g][2],   s[2*g][3]);
            aph[g][2] = pack2h(s[2*g+1][0], s[2*g+1][1]);
            aph[g][3] = pack2h(s[2*g+1][2], s[2*g+1][3]);
        }

        // ---- O += P V (single product) ----
        const int vrow0 = (lane & 15);
        const uint32_t vcadd = (uint32_t)((lane >> 4) << 4);
        #pragma unroll
        for (int dtp = 0; dtp < 8; dtp++) {
            const uint32_t vcol = (uint32_t)((dtp&3)*32) + vcadd;
            #pragma unroll
            for (int g = 0; g < 4; g++) {
                const uint32_t voff = (dtp>>2)*8192 + SWZ((g*16 + vrow0)*128 + vcol);
                uint32_t vb4[4];
                ldsm4t(VB + voff, vb4);
                mma16816(o[2*dtp],   aph[g], &vb4[0]);
                mma16816(o[2*dtp+1], aph[g], &vb4[2]);
            }
        }

        if (kt + 1 < nkv) {
            CP_WAIT0();
            __syncthreads();
        }
    }

    // ---- epilogue: normalize, single fp16, write [B, L, H*128] ----
    const float inv0 = 1.f / lr0, inv1 = 1.f / lr1;
    const size_t row0 = ((size_t)(b*SEQ + rg0)) * D_MODEL + h*HDIM;
    const size_t row1 = row0 + 8 * D_MODEL;
    #pragma unroll
    for (int t = 0; t < 16; t++) {
        const int d = t*8 + 2*(lane & 3);
        *(uint32_t*)&g_ah[row0 + d] = pack2h(o[t][0]*inv0, o[t][1]*inv0);
        *(uint32_t*)&g_ah[row1 + d] = pack2h(o[t][2]*inv1, o[t][3]*inv1);
    }
}

// ---------------------------------------------------------------------------
extern "C" void kernel_launch(void* const* d_in, const int* in_sizes, int n_in,
                              void* d_out, int out_size)
{
    const float* query = (const float*)d_in[0];
    const float* W_qkv = (const float*)d_in[1];
    const float* b_qkv = (const float*)d_in[2];
    const float* W_out = (const float*)d_in[3];
    const float* b_out = (const float*)d_in[4];
    float* out = (float*)d_out;

    void *p_qh, *p_ql, *p_w, *p_o, *p_ah;
    cudaGetSymbolAddress(&p_qh, g_qh);  cudaGetSymbolAddress(&p_ql, g_ql);
    cudaGetSymbolAddress(&p_w, g_w);    cudaGetSymbolAddress(&p_o, g_o);
    cudaGetSymbolAddress(&p_ah, g_ah);

    const int GEMM_SMEM = 1024 + 3*24576;       // 3-stage K32 pipeline (2 CTAs/SM)
    cudaFuncSetAttribute(tc_gemm<0>, cudaFuncAttributeMaxDynamicSharedMemorySize, GEMM_SMEM);
    cudaFuncSetAttribute(tc_gemm<1>, cudaFuncAttributeMaxDynamicSharedMemorySize, GEMM_SMEM);
    const int ATTN_SMEM = 1024 + 32768 + 2*32768;   // Q 32KB + 2 KV bufs (2 CTAs/SM)
    cudaFuncSetAttribute(attn_kernel, cudaFuncAttributeMaxDynamicSharedMemorySize, ATTN_SMEM);

    // 0) rope tables (must precede QKV epilogue)
    rope_table_kernel<<<(SEQ*64)/256, 256>>>();

    // 1) prepare fp16 operands
    {
        int n;
        n = MROWS*D_MODEL;
        splith_kernel<<<n/1024, 256>>>(query, (__half*)p_qh, (__half*)p_ql, n);
        n = 3*D_MODEL*D_MODEL;
        cvth_kernel<<<n/1024, 256>>>(W_qkv, (__half*)p_w, n);
        n = D_MODEL*D_MODEL;
        cvth_kernel<<<n/1024, 256>>>(W_out, (__half*)p_o, n);
    }

    // 2) QKV projection (dual for q,k; single for v) with fused rope epilogue
    tc_gemm<1><<<dim3(3*D_MODEL/128, MROWS/128), 256, GEMM_SMEM>>>(
        (const __half*)p_qh, (const __half*)p_ql, (const __half*)p_w,
        b_qkv, nullptr, 3*D_MODEL, D_MODEL);

    // 3) causal flash attention (BQ=64, 2 CTAs/SM) -> g_ah
    attn_kernel<<<dim3(SEQ/64, NHEAD, BATCH), 128, ATTN_SMEM>>>();

    // 4) Output projection (single product) -> d_out
    tc_gemm<0><<<dim3(D_MODEL/128, MROWS/128), 256, GEMM_SMEM>>>(
        (const __half*)p_ah, (const __half*)p_ah, (const __half*)p_o,
        b_out, out, D_MODEL, D_MODEL);
}

// round 16
// speedup vs baseline: 2.0423x; 1.0601x over previous
#include <cuda_runtime.h>
#include <cuda_fp16.h>
#include <math.h>
#include <stdint.h>

#define D_MODEL 2048
#define NHEAD   16
#define HDIM    128
#define BATCH   2
#define SEQ     2048
#define MROWS   (BATCH*SEQ)   // 4096

// ---------------- device scratch (no runtime allocation) ----------------
__device__ __half g_qbh[(size_t)BATCH*NHEAD*SEQ*HDIM];  // roped+scaled Q hi/lo (fp16)
__device__ __half g_qbl[(size_t)BATCH*NHEAD*SEQ*HDIM];
__device__ __half g_kb [(size_t)BATCH*NHEAD*SEQ*HDIM];  // roped K (single fp16)
__device__ __half g_vb [(size_t)BATCH*NHEAD*SEQ*HDIM];  // V (single fp16)

__device__ __half g_qh[(size_t)MROWS*D_MODEL];          // query hi/lo (GEMM A)
__device__ __half g_ql[(size_t)MROWS*D_MODEL];
__device__ __half g_w [(size_t)3*D_MODEL*D_MODEL];      // W_qkv (single fp16)
__device__ __half g_o [(size_t)D_MODEL*D_MODEL];        // W_out (single fp16)
__device__ __half g_ah[(size_t)MROWS*D_MODEL];          // attn-out (single fp16)

__device__ float g_cos[(size_t)SEQ*64];                 // rope tables
__device__ float g_sin[(size_t)SEQ*64];

// ---------------- helpers ----------------
__device__ __forceinline__ uint32_t smem_u32(const void* p) {
    uint32_t a;
    asm("{ .reg .u64 t; cvta.to.shared.u64 t, %1; cvt.u32.u64 %0, t; }" : "=r"(a) : "l"(p));
    return a;
}
#define SWZ(o) ((o) ^ (((o) >> 3) & 0x70))

__device__ __forceinline__ void ldsm4(uint32_t addr, uint32_t* r) {
    asm volatile("ldmatrix.sync.aligned.m8n8.x4.shared.b16 {%0,%1,%2,%3}, [%4];"
                 : "=r"(r[0]), "=r"(r[1]), "=r"(r[2]), "=r"(r[3]) : "r"(addr));
}
__device__ __forceinline__ void ldsm4t(uint32_t addr, uint32_t* r) {
    asm volatile("ldmatrix.sync.aligned.m8n8.x4.trans.shared.b16 {%0,%1,%2,%3}, [%4];"
                 : "=r"(r[0]), "=r"(r[1]), "=r"(r[2]), "=r"(r[3]) : "r"(addr));
}
__device__ __forceinline__ void mma16816(float* c, const uint32_t* a, const uint32_t* b) {
    asm volatile(
        "mma.sync.aligned.m16n8k16.row.col.f32.f16.f16.f32 "
        "{%0,%1,%2,%3}, {%4,%5,%6,%7}, {%8,%9}, {%0,%1,%2,%3};"
        : "+f"(c[0]), "+f"(c[1]), "+f"(c[2]), "+f"(c[3])
        : "r"(a[0]), "r"(a[1]), "r"(a[2]), "r"(a[3]), "r"(b[0]), "r"(b[1]));
}
#define CP16(dst, src) \
    asm volatile("cp.async.cg.shared.global [%0], [%1], 16;" :: "r"(dst), "l"(src))
#define CP_COMMIT() asm volatile("cp.async.commit_group;" ::: "memory")
#define CP_WAIT0()  asm volatile("cp.async.wait_group 0;" ::: "memory")
#define CP_WAIT1()  asm volatile("cp.async.wait_group 1;" ::: "memory")

// split pair of fp32 into packed fp16x2 hi and lo (residual)
__device__ __forceinline__ void split2h(float x, float y, uint32_t& hi, uint32_t& lo) {
    __half hx = __float2half_rn(x), hy = __float2half_rn(y);
    float rx = x - __half2float(hx), ry = y - __half2float(hy);
    __half lx = __float2half_rn(rx), ly = __float2half_rn(ry);
    hi = ((uint32_t)__half_as_ushort(hy) << 16) | __half_as_ushort(hx);
    lo = ((uint32_t)__half_as_ushort(ly) << 16) | __half_as_ushort(lx);
}
__device__ __forceinline__ uint32_t pack2h(float x, float y) {
    __half hx = __float2half_rn(x), hy = __float2half_rn(y);
    return ((uint32_t)__half_as_ushort(hy) << 16) | __half_as_ushort(hx);
}

// ---------------------------------------------------------------------------
// fp32 -> fp16 hi/lo split, and fp32 -> fp16 single convert
// ---------------------------------------------------------------------------
__global__ void splith_kernel(const float* __restrict__ x,
                              __half* __restrict__ hi,
                              __half* __restrict__ lo, int n)
{
    int i = (blockIdx.x * 256 + threadIdx.x) * 4;
    if (i >= n) return;
    float4 v = *(const float4*)(x + i);
    uint32_t h0, l0, h1, l1;
    split2h(v.x, v.y, h0, l0);
    split2h(v.z, v.w, h1, l1);
    *(uint2*)(hi + i) = make_uint2(h0, h1);
    *(uint2*)(lo + i) = make_uint2(l0, l1);
}
__global__ void cvth_kernel(const float* __restrict__ x,
                            __half* __restrict__ y, int n)
{
    int i = (blockIdx.x * 256 + threadIdx.x) * 4;
    if (i >= n) return;
    float4 v = *(const float4*)(x + i);
    *(uint2*)(y + i) = make_uint2(pack2h(v.x, v.y), pack2h(v.z, v.w));
}

// ---------------------------------------------------------------------------
// RoPE cos/sin table (double-precision range reduction, robust to fast-math)
// ---------------------------------------------------------------------------
__global__ void rope_table_kernel()
{
    int idx = blockIdx.x * 256 + threadIdx.x;       // SEQ*64 threads
    int l = idx >> 6, d = idx & 63;
    double invf = exp2(-(double)d * (13.287712379549449 / 64.0)); // 10000^(-d/64)
    double t    = fmod((double)l * invf, 6.283185307179586476925286766559);
    g_cos[idx] = cosf((float)t);
    g_sin[idx] = sinf((float)t);
}

// ---------------------------------------------------------------------------
// HMMA GEMM (fp16): C = (Ah [+ Al]) * B^T + bias, fp32 accum.
// `dual` (block-uniform):
//   MODE 0 (out-proj): single (attn output enters linearly).
//   MODE 1 (QKV): dual ONLY for q columns (q stays hi/lo into exp path);
//     k,v columns single — k/v are rounded to single fp16 at storage anyway,
//     so their dual-product precision would be immediately destroyed.
// CTA 128x128, 8 warps, K-chunks of 32, 3-stage cp.async, 2 CTAs/SM.
// ---------------------------------------------------------------------------
__device__ __forceinline__ void load_chunk_async(
    const __half* __restrict__ a0, const __half* __restrict__ a1,
    const __half* __restrict__ b, int K, int k0, uint32_t dst, bool dual)
{
    const __half* p = a0 + k0;
    #pragma unroll
    for (int it = 0; it < 2; it++) {
        int i = threadIdx.x + it * 256;         // 0..511
        int r = i >> 2, c = i & 3;
        CP16(dst + SWZ(r * 128 + c * 16), p + (size_t)r * K + c * 8);
    }
    if (dual) {
        p = a1 + k0;
        #pragma unroll
        for (int it = 0; it < 2; it++) {
            int i = threadIdx.x + it * 256;
            int r = i >> 2, c = i & 3;
            CP16(dst + SWZ(r * 128 + 64 + c * 16), p + (size_t)r * K + c * 8);
        }
    }
    const __half* pb = b + k0;
    #pragma unroll
    for (int it = 0; it < 2; it++) {
        int i = threadIdx.x + it * 256;         // 0..511
        int r = i >> 2, c = i & 3;              // r = N row 0..127
        CP16(dst + 16384 + SWZ((r & 63) * 128 + ((r >> 6) << 6) + c * 16),
             pb + (size_t)r * K + c * 8);
    }
}

template<int MODE>
__global__ __launch_bounds__(256, 2)
void tc_gemm(const __half* __restrict__ Ah, const __half* __restrict__ Al,
             const __half* __restrict__ B,
             const float* __restrict__ bias, float* __restrict__ C, int N, int K)
{
    extern __shared__ char smem[];
    char* smp = (char*)(((uintptr_t)smem + 1023) & ~(uintptr_t)1023);
    const uint32_t bufs = smem_u32(smp);

    const int tid  = threadIdx.x;
    const int lane = tid & 31;
    const int wid  = tid >> 5;
    const int wr   = wid >> 2;
    const int wc   = wid & 3;
    const int m0   = blockIdx.y << 7;
    const int n0   = blockIdx.x << 7;
    const int KCHUNKS = K >> 5;
    const bool dual = (MODE == 1) ? ((n0 >> 11) == 0) : false;

    const __half* Ahp = Ah + (size_t)m0 * K;
    const __half* Alp = Al + (size_t)m0 * K;
    const __half* Bp  = B  + (size_t)n0 * K;

    float acc[4][4][4];
    #pragma unroll
    for (int i = 0; i < 4; i++)
        #pragma unroll
        for (int j = 0; j < 4; j++)
            #pragma unroll
            for (int r = 0; r < 4; r++) acc[i][j][r] = 0.f;

    const int      arow = lane & 15;
    const uint32_t adk  = (lane >> 4) << 4;
    const int      brow = (lane & 7) + ((lane >> 4) << 3);
    const uint32_t bdk  = ((lane >> 3) & 1) << 4;

    load_chunk_async(Ahp, Alp, Bp, K, 0,  bufs, dual);
    CP_COMMIT();
    load_chunk_async(Ahp, Alp, Bp, K, 32, bufs + 24576, dual);
    CP_COMMIT();
    CP_WAIT1();
    __syncthreads();

    for (int c = 0; c < KCHUNKS; c++) {
        if (c + 2 < KCHUNKS) {
            load_chunk_async(Ahp, Alp, Bp, K, (c + 2) << 5,
                             bufs + ((c + 2) % 3) * 24576, dual);
            CP_COMMIT();
        }

        const uint32_t bA = bufs + (c % 3) * 24576;
        const uint32_t bB = bA + 16384;

        #pragma unroll
        for (int ks = 0; ks < 2; ks++) {
            const uint32_t kbA = (uint32_t)ks * 32 + adk;
            const uint32_t kbB = (uint32_t)ks * 32 + bdk;

            uint32_t ah[4][4], bx[2][4];
            #pragma unroll
            for (int mt = 0; mt < 4; mt++)
                ldsm4(bA + SWZ((uint32_t)(wr*64 + mt*16 + arow) * 128 + kbA), ah[mt]);
            #pragma unroll
            for (int np = 0; np < 2; np++) {
                const int rw = wc*32 + np*16 + brow;
                ldsm4(bB + SWZ((uint32_t)(rw & 63) * 128 + (uint32_t)((rw >> 6) << 6) + kbB),
                      bx[np]);
            }
            #pragma unroll
            for (int mt = 0; mt < 4; mt++)
                #pragma unroll
                for (int nt = 0; nt < 4; nt++)
                    mma16816(acc[mt][nt], ah[mt], &bx[nt >> 1][(nt & 1) * 2]);

            if (dual) {
                uint32_t al[4][4];
                #pragma unroll
                for (int mt = 0; mt < 4; mt++)
                    ldsm4(bA + SWZ((uint32_t)(wr*64 + mt*16 + arow) * 128 + 64 + kbA),
                          al[mt]);
                #pragma unroll
                for (int mt = 0; mt < 4; mt++)
                    #pragma unroll
                    for (int nt = 0; nt < 4; nt++)
                        mma16816(acc[mt][nt], al[mt], &bx[nt >> 1][(nt & 1) * 2]);
            }
        }

        if (c + 1 < KCHUNKS) {
            if (c + 2 < KCHUNKS) CP_WAIT1(); else CP_WAIT0();
            __syncthreads();
        }
    }

    if (MODE == 0) {
        #pragma unroll
        for (int mt = 0; mt < 4; mt++) {
            const int mrow = m0 + wr*64 + mt*16 + (lane >> 2);
            #pragma unroll
            for (int nt = 0; nt < 4; nt++) {
                const int cg = n0 + wc*32 + nt*8 + (lane & 3)*2;
                const float bx2 = bias[cg], by = bias[cg + 1];
                *(float2*)&C[(size_t)mrow * N + cg] =
                    make_float2(acc[mt][nt][0] + bx2, acc[mt][nt][1] + by);
                *(float2*)&C[(size_t)(mrow + 8) * N + cg] =
                    make_float2(acc[mt][nt][2] + bx2, acc[mt][nt][3] + by);
            }
        }
        return;
    }

    // ---------------- MODE 1 epilogue: stage -> rope/convert -> scatter -----
    float* st = (float*)smp;                 // 128 x 132 fp32
    const int PITCH = 132;
    __syncthreads();
    #pragma unroll
    for (int mt = 0; mt < 4; mt++) {
        const int r0 = wr*64 + mt*16 + (lane >> 2);
        #pragma unroll
        for (int nt = 0; nt < 4; nt++) {
            const int cl = wc*32 + nt*8 + (lane & 3)*2;
            const float bx2 = bias[n0 + cl], by = bias[n0 + cl + 1];
            *(float2*)&st[r0*PITCH + cl] =
                make_float2(acc[mt][nt][0] + bx2, acc[mt][nt][1] + by);
            *(float2*)&st[(r0 + 8)*PITCH + cl] =
                make_float2(acc[mt][nt][2] + bx2, acc[mt][nt][3] + by);
        }
    }
    __syncthreads();

    const int which = n0 >> 11;              // 0=q 1=k 2=v
    const int h     = (n0 >> 7) & 15;
    const int row   = tid >> 1;
    const int half  = tid & 1;
    const int m     = m0 + row;
    const int bb    = m >> 11;
    const int l     = m & (SEQ - 1);
    const size_t obase = (((size_t)(bb*NHEAD + h))*SEQ + l)*HDIM;
    const float* srow = st + row * PITCH;
    const int d0 = half * 32;

    if (which == 2) {
        uint32_t h1[16], h2[16];
        #pragma unroll
        for (int j = 0; j < 16; j++) {
            h1[j] = pack2h(srow[d0 + 2*j],      srow[d0 + 2*j + 1]);
            h2[j] = pack2h(srow[d0 + 64 + 2*j], srow[d0 + 64 + 2*j + 1]);
        }
        #pragma unroll
        for (int j = 0; j < 4; j++) {
            *(uint4*)&g_vb[obase + d0 + j*8]      = ((uint4*)h1)[j];
            *(uint4*)&g_vb[obase + d0 + 64 + j*8] = ((uint4*)h2)[j];
        }
    } else {
        const float qs = (which == 0) ? 0.08838834764831845f : 1.0f;
        const float* ct  = g_cos + (size_t)l * 64;
        const float* stb = g_sin + (size_t)l * 64;
        if (which == 0) {
            uint32_t h1[16], l1[16], h2[16], l2[16];
            #pragma unroll
            for (int j = 0; j < 16; j++) {
                const int d = d0 + 2*j;
                float2 cc = *(const float2*)&ct[d];
                float2 ss = *(const float2*)&stb[d];
                float x1a = srow[d],      x1b = srow[d + 1];
                float x2a = srow[d + 64], x2b = srow[d + 65];
                split2h((x1a*cc.x - x2a*ss.x)*qs, (x1b*cc.y - x2b*ss.y)*qs, h1[j], l1[j]);
                split2h((x2a*cc.x + x1a*ss.x)*qs, (x2b*cc.y + x1b*ss.y)*qs, h2[j], l2[j]);
            }
            #pragma unroll
            for (int j = 0; j < 4; j++) {
                *(uint4*)&g_qbh[obase + d0 + j*8]      = ((uint4*)h1)[j];
                *(uint4*)&g_qbl[obase + d0 + j*8]      = ((uint4*)l1)[j];
                *(uint4*)&g_qbh[obase + d0 + 64 + j*8] = ((uint4*)h2)[j];
                *(uint4*)&g_qbl[obase + d0 + 64 + j*8] = ((uint4*)l2)[j];
            }
        } else {
            uint32_t h1[16], h2[16];
            #pragma unroll
            for (int j = 0; j < 16; j++) {
                const int d = d0 + 2*j;
                float2 cc = *(const float2*)&ct[d];
                float2 ss = *(const float2*)&stb[d];
                float x1a = srow[d],      x1b = srow[d + 1];
                float x2a = srow[d + 64], x2b = srow[d + 65];
                h1[j] = pack2h(x1a*cc.x - x2a*ss.x, x1b*cc.y - x2b*ss.y);
                h2[j] = pack2h(x2a*cc.x + x1a*ss.x, x2b*cc.y + x1b*ss.y);
            }
            #pragma unroll
            for (int j = 0; j < 4; j++) {
                *(uint4*)&g_kb[obase + d0 + j*8]      = ((uint4*)h1)[j];
                *(uint4*)&g_kb[obase + d0 + 64 + j*8] = ((uint4*)h2)[j];
            }
        }
    }
}

// ---------------------------------------------------------------------------
// HMMA causal flash attention (fp16).
// S = (Qh+Ql) K^T (dual: logits feed exp). PV = P V (single fp16 P).
// Output O stored single fp16 (enters out-proj linearly).
// BQ=64, 4 warps, 2 CTAs/SM. Q hi/lo 32KB + double-buffered KV 2x32KB.
// ---------------------------------------------------------------------------
__global__ __launch_bounds__(128, 2)
void attn_kernel()
{
    extern __shared__ char sm[];
    const uint32_t base = (smem_u32(sm) + 1023) & ~1023u;
    const uint32_t QH = base;                 // 2 panels x 8KB (dims 0-63, 64-127)
    const uint32_t QL = base + 16384;
    const uint32_t KV = base + 32768;         // buf b at +b*32768 (K 16KB, V 16KB)

    const int tid  = threadIdx.x;
    const int lane = tid & 31;
    const int wid  = tid >> 5;                // 0..3
    const int qt   = (int)gridDim.x - 1 - (int)blockIdx.x;  // heavy tiles first
    const int h    = blockIdx.y;
    const int b    = blockIdx.z;
    const int bh   = b*NHEAD + h;
    const int q0   = qt << 6;
    const int nkv  = qt + 1;

    const size_t hoff = (size_t)bh * SEQ * HDIM;
    const __half* qbh = g_qbh + hoff + (size_t)q0 * HDIM;
    const __half* qbl = g_qbl + hoff + (size_t)q0 * HDIM;
    const __half* kb  = g_kb + hoff;
    const __half* vb  = g_vb + hoff;

    // ---- Q load (64 rows x 16 units per array) ----
    #pragma unroll
    for (int it = 0; it < 8; it++) {
        int i = tid + it * 128;               // 0..1023
        int row = i >> 4, u = i & 15;
        uint32_t off = (u >> 3) * 8192 + SWZ(row * 128 + (u & 7) * 16);
        CP16(QH + off, qbh + (size_t)row * HDIM + u * 8);
        CP16(QL + off, qbl + (size_t)row * HDIM + u * 8);
    }
    // ---- KV block 0 ----
    {
        const __half* arr[2] = {kb, vb};
        #pragma unroll
        for (int t = 0; t < 2; t++)
            #pragma unroll
            for (int it = 0; it < 8; it++) {
                int i = tid + it * 128;       // 0..1023
                int row = i >> 4, u = i & 15;
                uint32_t d = KV + t*16384 + (u>>3)*8192 + SWZ(row*128 + (u&7)*16);
                CP16(d, arr[t] + (size_t)row * HDIM + u * 8);
            }
    }
    CP_COMMIT();
    CP_WAIT0();
    __syncthreads();

    float mr0 = -1e30f, mr1 = -1e30f, lr0 = 0.f, lr1 = 0.f;
    float o[16][4];
    #pragma unroll
    for (int t = 0; t < 16; t++)
        #pragma unroll
        for (int j = 0; j < 4; j++) o[t][j] = 0.f;

    const int rloc0 = wid*16 + (lane >> 2);   // 0..63
    const int rg0   = q0 + rloc0;

    for (int kt = 0; kt < nkv; kt++) {
        const uint32_t KB = KV + (kt & 1) * 32768;
        const uint32_t VB = KB + 16384;

        if (kt + 1 < nkv) {
            const __half* arr[2] = {kb, vb};
            const size_t s0 = (size_t)(kt + 1) * 64 * HDIM;
            const uint32_t nb = KV + ((kt + 1) & 1) * 32768;
            #pragma unroll
            for (int t = 0; t < 2; t++)
                #pragma unroll
                for (int it = 0; it < 8; it++) {
                    int i = tid + it * 128;
                    int row = i >> 4, u = i & 15;
                    uint32_t d = nb + t*16384 + (u>>3)*8192 + SWZ(row*128 + (u&7)*16);
                    CP16(d, arr[t] + s0 + (size_t)row * HDIM + u * 8);
                }
            CP_COMMIT();
        }

        // ---- S = (Qh+Ql) K^T ----
        float s[8][4];
        #pragma unroll
        for (int t = 0; t < 8; t++)
            #pragma unroll
            for (int j = 0; j < 4; j++) s[t][j] = 0.f;

        #pragma unroll
        for (int ks = 0; ks < 8; ks++) {
            const int arow = wid*16 + (lane & 15);
            const uint32_t aoff = (ks>>2)*8192
                + SWZ(arow*128 + (ks&3)*32 + ((lane>>4)<<4));
            uint32_t qa[4], qla[4];
            ldsm4(QH + aoff, qa);
            ldsm4(QL + aoff, qla);

            const int krow0 = (lane & 7) + ((lane >> 4) << 3);
            const uint32_t kcol = (uint32_t)((ks&3)*32 + (((lane>>3)&1)<<4));
            #pragma unroll
            for (int ntp = 0; ntp < 4; ntp++) {
                const uint32_t koff = (ks>>2)*8192 + SWZ((ntp*16 + krow0)*128 + kcol);
                uint32_t kb4[4];
                ldsm4(KB + koff, kb4);
                mma16816(s[2*ntp],   qa,  &kb4[0]);
                mma16816(s[2*ntp],   qla, &kb4[0]);
                mma16816(s[2*ntp+1], qa,  &kb4[2]);
                mma16816(s[2*ntp+1], qla, &kb4[2]);
            }
        }

        // ---- causal mask (diagonal block only) ----
        if (kt >= qt) {
            #pragma unroll
            for (int t = 0; t < 8; t++) {
                #pragma unroll
                for (int j = 0; j < 2; j++) {
                    const int n = kt*64 + t*8 + 2*(lane & 3) + j;
                    if (n > rg0)     s[t][j]   = -1e30f;
                    if (n > rg0 + 8) s[t][2+j] = -1e30f;
                }
            }
        }

        float rm0 = -1e30f, rm1 = -1e30f;
        #pragma unroll
        for (int t = 0; t < 8; t++) {
            rm0 = fmaxf(rm0, fmaxf(s[t][0], s[t][1]));
            rm1 = fmaxf(rm1, fmaxf(s[t][2], s[t][3]));
        }
        rm0 = fmaxf(rm0, __shfl_xor_sync(0xffffffffu, rm0, 1));
        rm0 = fmaxf(rm0, __shfl_xor_sync(0xffffffffu, rm0, 2));
        rm1 = fmaxf(rm1, __shfl_xor_sync(0xffffffffu, rm1, 1));
        rm1 = fmaxf(rm1, __shfl_xor_sync(0xffffffffu, rm1, 2));

        const float mn0 = fmaxf(mr0, rm0), mn1 = fmaxf(mr1, rm1);
        const float sf0 = __expf(mr0 - mn0), sf1 = __expf(mr1 - mn1);
        mr0 = mn0; mr1 = mn1;

        float rs0 = 0.f, rs1 = 0.f;
        #pragma unroll
        for (int t = 0; t < 8; t++) {
            s[t][0] = __expf(s[t][0] - mn0);
            s[t][1] = __expf(s[t][1] - mn0);
            s[t][2] = __expf(s[t][2] - mn1);
            s[t][3] = __expf(s[t][3] - mn1);
            rs0 += s[t][0] + s[t][1];
            rs1 += s[t][2] + s[t][3];
        }
        rs0 += __shfl_xor_sync(0xffffffffu, rs0, 1);
        rs0 += __shfl_xor_sync(0xffffffffu, rs0, 2);
        rs1 += __shfl_xor_sync(0xffffffffu, rs1, 1);
        rs1 += __shfl_xor_sync(0xffffffffu, rs1, 2);
        lr0 = lr0 * sf0 + rs0;
        lr1 = lr1 * sf1 + rs1;

        #pragma unroll
        for (int t = 0; t < 16; t++) {
            o[t][0] *= sf0; o[t][1] *= sf0;
            o[t][2] *= sf1; o[t][3] *= sf1;
        }

        // ---- P packed single fp16 into A-fragments ----
        uint32_t aph[4][4];
        #pragma unroll
        for (int g = 0; g < 4; g++) {
            aph[g][0] = pack2h(s[2*g][0],   s[2*g][1]);
            aph[g][1] = pack2h(s[2*g][2],   s[2*g][3]);
            aph[g][2] = pack2h(s[2*g+1][0], s[2*g+1][1]);
            aph[g][3] = pack2h(s[2*g+1][2], s[2*g+1][3]);
        }

        // ---- O += P V (single product) ----
        const int vrow0 = (lane & 15);
        const uint32_t vcadd = (uint32_t)((lane >> 4) << 4);
        #pragma unroll
        for (int dtp = 0; dtp < 8; dtp++) {
            const uint32_t vcol = (uint32_t)((dtp&3)*32) + vcadd;
            #pragma unroll
            for (int g = 0; g < 4; g++) {
                const uint32_t voff = (dtp>>2)*8192 + SWZ((g*16 + vrow0)*128 + vcol);
                uint32_t vb4[4];
                ldsm4t(VB + voff, vb4);
                mma16816(o[2*dtp],   aph[g], &vb4[0]);
                mma16816(o[2*dtp+1], aph[g], &vb4[2]);
            }
        }

        if (kt + 1 < nkv) {
            CP_WAIT0();
            __syncthreads();
        }
    }

    // ---- epilogue: normalize, single fp16, write [B, L, H*128] ----
    const float inv0 = 1.f / lr0, inv1 = 1.f / lr1;
    const size_t row0 = ((size_t)(b*SEQ + rg0)) * D_MODEL + h*HDIM;
    const size_t row1 = row0 + 8 * D_MODEL;
    #pragma unroll
    for (int t = 0; t < 16; t++) {
        const int d = t*8 + 2*(lane & 3);
        *(uint32_t*)&g_ah[row0 + d] = pack2h(o[t][0]*inv0, o[t][1]*inv0);
        *(uint32_t*)&g_ah[row1 + d] = pack2h(o[t][2]*inv1, o[t][3]*inv1);
    }
}

// ---------------------------------------------------------------------------
extern "C" void kernel_launch(void* const* d_in, const int* in_sizes, int n_in,
                              void* d_out, int out_size)
{
    const float* query = (const float*)d_in[0];
    const float* W_qkv = (const float*)d_in[1];
    const float* b_qkv = (const float*)d_in[2];
    const float* W_out = (const float*)d_in[3];
    const float* b_out = (const float*)d_in[4];
    float* out = (float*)d_out;

    void *p_qh, *p_ql, *p_w, *p_o, *p_ah;
    cudaGetSymbolAddress(&p_qh, g_qh);  cudaGetSymbolAddress(&p_ql, g_ql);
    cudaGetSymbolAddress(&p_w, g_w);    cudaGetSymbolAddress(&p_o, g_o);
    cudaGetSymbolAddress(&p_ah, g_ah);

    const int GEMM_SMEM = 1024 + 3*24576;       // 3-stage K32 pipeline (2 CTAs/SM)
    cudaFuncSetAttribute(tc_gemm<0>, cudaFuncAttributeMaxDynamicSharedMemorySize, GEMM_SMEM);
    cudaFuncSetAttribute(tc_gemm<1>, cudaFuncAttributeMaxDynamicSharedMemorySize, GEMM_SMEM);
    const int ATTN_SMEM = 1024 + 32768 + 2*32768;   // Q 32KB + 2 KV bufs (2 CTAs/SM)
    cudaFuncSetAttribute(attn_kernel, cudaFuncAttributeMaxDynamicSharedMemorySize, ATTN_SMEM);

    // 0) rope tables (must precede QKV epilogue)
    rope_table_kernel<<<(SEQ*64)/256, 256>>>();

    // 1) prepare fp16 operands
    {
        int n;
        n = MROWS*D_MODEL;
        splith_kernel<<<n/1024, 256>>>(query, (__half*)p_qh, (__half*)p_ql, n);
        n = 3*D_MODEL*D_MODEL;
        cvth_kernel<<<n/1024, 256>>>(W_qkv, (__half*)p_w, n);
        n = D_MODEL*D_MODEL;
        cvth_kernel<<<n/1024, 256>>>(W_out, (__half*)p_o, n);
    }

    // 2) QKV projection (dual for q; single for k,v) with fused rope epilogue
    tc_gemm<1><<<dim3(3*D_MODEL/128, MROWS/128), 256, GEMM_SMEM>>>(
        (const __half*)p_qh, (const __half*)p_ql, (const __half*)p_w,
        b_qkv, nullptr, 3*D_MODEL, D_MODEL);

    // 3) causal flash attention (BQ=64, 2 CTAs/SM) -> g_ah
    attn_kernel<<<dim3(SEQ/64, NHEAD, BATCH), 128, ATTN_SMEM>>>();

    // 4) Output projection (single product) -> d_out
    tc_gemm<0><<<dim3(D_MODEL/128, MROWS/128), 256, GEMM_SMEM>>>(
        (const __half*)p_ah, (const __half*)p_ah, (const __half*)p_o,
        b_out, out, D_MODEL, D_MODEL);
}